// round 1
// baseline (speedup 1.0000x reference)
#include <cuda_runtime.h>
#include <cuda_bf16.h>

// Problem constants
#define BB 16
#define LL 512
#define DD 1024
#define HH 16
#define DK 64
#define FF 4096
#define CC 10
#define NLAYER 6

// ---------------- scratch (static __device__, no allocations) ----------------
__device__ float g_x[BB * LL * DD];       // activations [8192,1024]
__device__ float g_tmp[BB * LL * DD];     // FFN output
__device__ float g_q[LL * DD];
__device__ float g_k[LL * DD];
__device__ float g_v[LL * DD];
__device__ float g_o[LL * DD];
__device__ float g_src2[LL * DD];
__device__ float g_scores[HH * LL * LL];  // [16,512,512]
__device__ float g_Wff[DD * DD];          // w1@w2
__device__ float g_bff[DD];               // b1@w2 + b2
__device__ float g_bffpart[32 * DD];
__device__ float g_pooled[BB * DD];
__device__ int   g_ids64;

// ---------------- reductions ----------------
__device__ __forceinline__ float warpSum(float v) {
    #pragma unroll
    for (int o = 16; o > 0; o >>= 1) v += __shfl_xor_sync(0xffffffffu, v, o);
    return v;
}
__device__ __forceinline__ float warpMax(float v) {
    #pragma unroll
    for (int o = 16; o > 0; o >>= 1) v = fmaxf(v, __shfl_xor_sync(0xffffffffu, v, o));
    return v;
}
__device__ __forceinline__ float blockSum(float v) {
    __shared__ float sm[32];
    int lane = threadIdx.x & 31, w = threadIdx.x >> 5;
    v = warpSum(v);
    if (lane == 0) sm[w] = v;
    __syncthreads();
    if (w == 0) {
        float x = (lane < (int)(blockDim.x >> 5)) ? sm[lane] : 0.f;
        x = warpSum(x);
        if (lane == 0) sm[0] = x;
    }
    __syncthreads();
    float r = sm[0];
    __syncthreads();
    return r;
}
__device__ __forceinline__ float blockMax(float v) {
    __shared__ float sm[32];
    int lane = threadIdx.x & 31, w = threadIdx.x >> 5;
    v = warpMax(v);
    if (lane == 0) sm[w] = v;
    __syncthreads();
    if (w == 0) {
        float x = (lane < (int)(blockDim.x >> 5)) ? sm[lane] : -3.4e38f;
        x = warpMax(x);
        if (lane == 0) sm[0] = x;
    }
    __syncthreads();
    float r = sm[0];
    __syncthreads();
    return r;
}

// ---------------- dtype detect + embed ----------------
__global__ void detect_kernel(const void* ids) {
    // int64 tokens (< 2^31) have zero high words; 128 random int32 tokens can't all be 0.
    const int* p = (const int*)ids;
    int nz = 0;
    for (int i = 0; i < 256; i += 2)
        if (p[i + 1] != 0) nz++;
    g_ids64 = (nz == 0) ? 1 : 0;
}

__global__ void embed_kernel(const void* ids, const float* __restrict__ emb,
                             const float* __restrict__ pe) {
    int row = blockIdx.x;              // 0..8191  (b*512 + l)
    int d = threadIdx.x * 4;
    long long id;
    if (g_ids64) id = ((const long long*)ids)[row];
    else         id = (long long)((const int*)ids)[row];
    int l = row & (LL - 1);
    float4 e = *(const float4*)(emb + (size_t)id * DD + d);
    float4 p = *(const float4*)(pe + (size_t)l * DD + d);
    float4 o;
    o.x = e.x * 32.f + p.x; o.y = e.y * 32.f + p.y;
    o.z = e.z * 32.f + p.z; o.w = e.w * 32.f + p.w;
    *(float4*)(g_x + (size_t)row * DD + d) = o;
}

// ---------------- generic fp32 GEMM: C = A@B (+bias), tiles 128x64x16 ----------------
__device__ __forceinline__ void gemm_body(const float* __restrict__ A,
                                          const float* __restrict__ Bm,
                                          const float* __restrict__ bias,
                                          float* __restrict__ C,
                                          int M, int N, int K) {
    __shared__ __align__(16) float As[16][132];
    __shared__ __align__(16) float Bs[16][68];
    int t = threadIdx.x;
    int tx = t & 15, ty = t >> 4;
    int m0 = blockIdx.y * 128;
    int n0 = blockIdx.x * 64;
    float acc[8][4];
    #pragma unroll
    for (int i = 0; i < 8; i++)
        #pragma unroll
        for (int j = 0; j < 4; j++) acc[i][j] = 0.f;

    for (int k0 = 0; k0 < K; k0 += 16) {
        #pragma unroll
        for (int it = 0; it < 2; it++) {
            int idx = t * 2 + it;          // 0..511 float4s of A tile
            int row = idx >> 2;
            int c4 = (idx & 3) * 4;
            float4 va = *(const float4*)(A + (size_t)(m0 + row) * K + k0 + c4);
            As[c4 + 0][row] = va.x; As[c4 + 1][row] = va.y;
            As[c4 + 2][row] = va.z; As[c4 + 3][row] = va.w;
        }
        {
            int row = t >> 4;              // 0..15
            int c4 = (t & 15) * 4;
            *(float4*)(&Bs[row][c4]) =
                *(const float4*)(Bm + (size_t)(k0 + row) * N + n0 + c4);
        }
        __syncthreads();
        #pragma unroll
        for (int kk = 0; kk < 16; kk++) {
            float a[8], b[4];
            #pragma unroll
            for (int i = 0; i < 8; i++) a[i] = As[kk][ty + i * 16];
            #pragma unroll
            for (int j = 0; j < 4; j++) b[j] = Bs[kk][tx + j * 16];
            #pragma unroll
            for (int i = 0; i < 8; i++)
                #pragma unroll
                for (int j = 0; j < 4; j++)
                    acc[i][j] = fmaf(a[i], b[j], acc[i][j]);
        }
        __syncthreads();
    }
    #pragma unroll
    for (int j = 0; j < 4; j++) {
        int n = n0 + tx + j * 16;
        float bv = bias ? bias[n] : 0.f;
        #pragma unroll
        for (int i = 0; i < 8; i++) {
            int m = m0 + ty + i * 16;
            C[(size_t)m * N + n] = acc[i][j] + bv;
        }
    }
}

__global__ __launch_bounds__(256) void gemm_bias(const float* __restrict__ A,
                                                 const float* __restrict__ Bm,
                                                 const float* __restrict__ bias,
                                                 float* __restrict__ C,
                                                 int M, int N, int K) {
    gemm_body(A, Bm, bias, C, M, N, K);
}

__global__ __launch_bounds__(256) void gemm_qkv(const float* __restrict__ A,
                                                const float* __restrict__ Bq,
                                                const float* __restrict__ Bk,
                                                const float* __restrict__ Bv,
                                                const float* __restrict__ bq,
                                                const float* __restrict__ bk,
                                                const float* __restrict__ bv,
                                                float* __restrict__ Cq,
                                                float* __restrict__ Ck,
                                                float* __restrict__ Cv,
                                                int M, int N, int K) {
    const float* Bm = (blockIdx.z == 0) ? Bq : (blockIdx.z == 1) ? Bk : Bv;
    const float* bi = (blockIdx.z == 0) ? bq : (blockIdx.z == 1) ? bk : bv;
    float* C        = (blockIdx.z == 0) ? Cq : (blockIdx.z == 1) ? Ck : Cv;
    gemm_body(A, Bm, bi, C, M, N, K);
}

// ---------------- attention (batch 0 only) ----------------
// scores[h, m, n] = (q_h[m,:] . k_h[n,:]) / 8     grid:(ntile=8, mtile=8, head=16)
__global__ __launch_bounds__(256) void attn_scores(const float* __restrict__ q,
                                                   const float* __restrict__ k,
                                                   float* __restrict__ s) {
    __shared__ __align__(16) float Qs[64][68];   // [kk][m]
    __shared__ __align__(16) float Ks[64][68];   // [kk][n]
    int h = blockIdx.z, m0 = blockIdx.y * 64, n0 = blockIdx.x * 64;
    int t = threadIdx.x, tx = t & 15, ty = t >> 4;
    #pragma unroll
    for (int it = 0; it < 4; it++) {
        int idx = it * 256 + t;          // 0..1023 float4s
        int row = idx >> 4;
        int c4 = (idx & 15) * 4;
        float4 vq = *(const float4*)(q + (size_t)(m0 + row) * DD + h * 64 + c4);
        Qs[c4 + 0][row] = vq.x; Qs[c4 + 1][row] = vq.y;
        Qs[c4 + 2][row] = vq.z; Qs[c4 + 3][row] = vq.w;
        float4 vk = *(const float4*)(k + (size_t)(n0 + row) * DD + h * 64 + c4);
        Ks[c4 + 0][row] = vk.x; Ks[c4 + 1][row] = vk.y;
        Ks[c4 + 2][row] = vk.z; Ks[c4 + 3][row] = vk.w;
    }
    __syncthreads();
    float acc[4][4];
    #pragma unroll
    for (int i = 0; i < 4; i++)
        #pragma unroll
        for (int j = 0; j < 4; j++) acc[i][j] = 0.f;
    #pragma unroll 8
    for (int kk = 0; kk < 64; kk++) {
        float a[4], b[4];
        #pragma unroll
        for (int i = 0; i < 4; i++) a[i] = Qs[kk][ty + i * 16];
        #pragma unroll
        for (int j = 0; j < 4; j++) b[j] = Ks[kk][tx + j * 16];
        #pragma unroll
        for (int i = 0; i < 4; i++)
            #pragma unroll
            for (int j = 0; j < 4; j++)
                acc[i][j] = fmaf(a[i], b[j], acc[i][j]);
    }
    #pragma unroll
    for (int i = 0; i < 4; i++) {
        int m = m0 + ty + i * 16;
        #pragma unroll
        for (int j = 0; j < 4; j++) {
            int n = n0 + tx + j * 16;
            s[((size_t)h * LL + m) * LL + n] = acc[i][j] * 0.125f;
        }
    }
}

__global__ __launch_bounds__(256) void softmax512(float* __restrict__ s) {
    float* r = s + (size_t)blockIdx.x * LL;
    int t = threadIdx.x;
    float v0 = r[t], v1 = r[t + 256];
    float m = blockMax(fmaxf(v0, v1));
    float e0 = expf(v0 - m), e1 = expf(v1 - m);
    float inv = 1.f / blockSum(e0 + e1);
    r[t] = e0 * inv;
    r[t + 256] = e1 * inv;
}

// o_h = p_h @ v_h   grid:(mtile=8, head=16)
__global__ __launch_bounds__(256) void attn_pv(const float* __restrict__ p,
                                               const float* __restrict__ v,
                                               float* __restrict__ o) {
    __shared__ __align__(16) float Ps[64][68];   // [kk][m]
    __shared__ __align__(16) float Vs[64][68];   // [kk][n]
    int h = blockIdx.y, m0 = blockIdx.x * 64;
    int t = threadIdx.x, tx = t & 15, ty = t >> 4;
    float acc[4][4];
    #pragma unroll
    for (int i = 0; i < 4; i++)
        #pragma unroll
        for (int j = 0; j < 4; j++) acc[i][j] = 0.f;

    for (int k0 = 0; k0 < LL; k0 += 64) {
        #pragma unroll
        for (int it = 0; it < 4; it++) {
            int idx = it * 256 + t;
            int row = idx >> 4;
            int c4 = (idx & 15) * 4;
            float4 vp = *(const float4*)(p + ((size_t)h * LL + m0 + row) * LL + k0 + c4);
            Ps[c4 + 0][row] = vp.x; Ps[c4 + 1][row] = vp.y;
            Ps[c4 + 2][row] = vp.z; Ps[c4 + 3][row] = vp.w;
            float4 vv = *(const float4*)(v + (size_t)(k0 + row) * DD + h * 64 + c4);
            *(float4*)(&Vs[row][c4]) = vv;
        }
        __syncthreads();
        #pragma unroll 8
        for (int kk = 0; kk < 64; kk++) {
            float a[4], b[4];
            #pragma unroll
            for (int i = 0; i < 4; i++) a[i] = Ps[kk][ty + i * 16];
            #pragma unroll
            for (int j = 0; j < 4; j++) b[j] = Vs[kk][tx + j * 16];
            #pragma unroll
            for (int i = 0; i < 4; i++)
                #pragma unroll
                for (int j = 0; j < 4; j++)
                    acc[i][j] = fmaf(a[i], b[j], acc[i][j]);
        }
        __syncthreads();
    }
    #pragma unroll
    for (int i = 0; i < 4; i++) {
        int m = m0 + ty + i * 16;
        #pragma unroll
        for (int j = 0; j < 4; j++)
            o[(size_t)m * DD + h * 64 + tx + j * 16] = acc[i][j];
    }
}

// ---------------- residual add + LayerNorm (in place on x) ----------------
__global__ __launch_bounds__(256) void add_ln(float* __restrict__ x,
                                              const float* __restrict__ add,
                                              int addMask,
                                              const float* __restrict__ g,
                                              const float* __restrict__ b) {
    int row = blockIdx.x;
    int t = threadIdx.x;
    float* xr = x + (size_t)row * DD;
    const float* ar = add + (size_t)(row & addMask) * DD;
    float4 xv = *(const float4*)(xr + t * 4);
    float4 av = *(const float4*)(ar + t * 4);
    float v0 = xv.x + av.x, v1 = xv.y + av.y, v2 = xv.z + av.z, v3 = xv.w + av.w;
    float mean = blockSum(v0 + v1 + v2 + v3) * (1.f / DD);
    float d0 = v0 - mean, d1 = v1 - mean, d2 = v2 - mean, d3 = v3 - mean;
    float var = blockSum(d0 * d0 + d1 * d1 + d2 * d2 + d3 * d3) * (1.f / DD);
    float rs = rsqrtf(var + 1e-5f);
    float4 gv = *(const float4*)(g + t * 4);
    float4 bv = *(const float4*)(b + t * 4);
    float4 o;
    o.x = d0 * rs * gv.x + bv.x;
    o.y = d1 * rs * gv.y + bv.y;
    o.z = d2 * rs * gv.z + bv.z;
    o.w = d3 * rs * gv.w + bv.w;
    *(float4*)(xr + t * 4) = o;
}

// ---------------- folded FFN bias: bff = b1@w2 + b2 ----------------
__global__ __launch_bounds__(256) void bff_part(const float* __restrict__ b1,
                                                const float* __restrict__ w2) {
    int y = blockIdx.x;            // 0..31, f range [y*128,(y+1)*128)
    int t = threadIdx.x;
    float s[4] = {0.f, 0.f, 0.f, 0.f};
    int f0 = y * 128;
    for (int f = f0; f < f0 + 128; f++) {
        float bv = b1[f];
        const float* wr = w2 + (size_t)f * DD;
        #pragma unroll
        for (int j = 0; j < 4; j++) s[j] = fmaf(bv, wr[t + j * 256], s[j]);
    }
    #pragma unroll
    for (int j = 0; j < 4; j++) g_bffpart[y * DD + t + j * 256] = s[j];
}
__global__ __launch_bounds__(256) void bff_reduce(const float* __restrict__ b2) {
    int d = blockIdx.x * 256 + threadIdx.x;
    float s = b2[d];
    for (int y = 0; y < 32; y++) s += g_bffpart[y * DD + d];
    g_bff[d] = s;
}

// ---------------- pooling + classifier ----------------
__global__ __launch_bounds__(256) void pool_mean(const float* __restrict__ x) {
    int b = blockIdx.y;
    int d = blockIdx.x * 256 + threadIdx.x;
    const float* p = x + ((size_t)b * LL) * DD + d;
    float s = 0.f;
    for (int l = 0; l < LL; l++) s += p[(size_t)l * DD];
    g_pooled[b * DD + d] = s * (1.f / LL);
}
__global__ __launch_bounds__(256) void logits_kernel(const float* __restrict__ wf,
                                                     const float* __restrict__ bf,
                                                     float* __restrict__ out) {
    int b = blockIdx.x / CC, c = blockIdx.x % CC;
    float s = 0.f;
    for (int d = threadIdx.x; d < DD; d += 256)
        s += g_pooled[b * DD + d] * wf[(size_t)d * CC + c];
    s = blockSum(s);
    if (threadIdx.x == 0) out[b * CC + c] = s + bf[c];
}

// ---------------- launch ----------------
extern "C" void kernel_launch(void* const* d_in, const int* in_sizes, int n_in,
                              void* d_out, int out_size) {
    const void*  ids = d_in[0];
    const float* emb = (const float*)d_in[1];
    const float* pe  = (const float*)d_in[2];
    const float* wq  = (const float*)d_in[3];
    const float* bq  = (const float*)d_in[4];
    const float* wk  = (const float*)d_in[5];
    const float* bk  = (const float*)d_in[6];
    const float* wv  = (const float*)d_in[7];
    const float* bv  = (const float*)d_in[8];
    const float* wo  = (const float*)d_in[9];
    const float* bo  = (const float*)d_in[10];
    const float* w1  = (const float*)d_in[11];
    const float* b1  = (const float*)d_in[12];
    const float* w2  = (const float*)d_in[13];
    const float* b2  = (const float*)d_in[14];
    const float* g1  = (const float*)d_in[15];
    const float* be1 = (const float*)d_in[16];
    const float* g2  = (const float*)d_in[17];
    const float* be2 = (const float*)d_in[18];
    const float* wf  = (const float*)d_in[19];
    const float* bf  = (const float*)d_in[20];
    float* out = (float*)d_out;

    float *x, *tmp, *q, *k, *v, *o, *src2, *scores, *Wff, *bff;
    cudaGetSymbolAddress((void**)&x, g_x);
    cudaGetSymbolAddress((void**)&tmp, g_tmp);
    cudaGetSymbolAddress((void**)&q, g_q);
    cudaGetSymbolAddress((void**)&k, g_k);
    cudaGetSymbolAddress((void**)&v, g_v);
    cudaGetSymbolAddress((void**)&o, g_o);
    cudaGetSymbolAddress((void**)&src2, g_src2);
    cudaGetSymbolAddress((void**)&scores, g_scores);
    cudaGetSymbolAddress((void**)&Wff, g_Wff);
    cudaGetSymbolAddress((void**)&bff, g_bff);

    detect_kernel<<<1, 1>>>(ids);
    embed_kernel<<<BB * LL, 256>>>(ids, emb, pe);

    // Folded FFN: Wff = w1@w2, bff = b1@w2 + b2
    bff_part<<<32, 256>>>(b1, w2);
    bff_reduce<<<4, 256>>>(b2);
    gemm_bias<<<dim3(DD / 64, DD / 128), 256>>>(w1, w2, nullptr, Wff, DD, DD, FF);

    for (int layer = 0; layer < NLAYER; layer++) {
        // Attention path on batch 0 (rows 0..511 of x)
        gemm_qkv<<<dim3(DD / 64, LL / 128, 3), 256>>>(x, wq, wk, wv, bq, bk, bv,
                                                      q, k, v, LL, DD, DD);
        attn_scores<<<dim3(8, 8, HH), 256>>>(q, k, scores);
        softmax512<<<HH * LL, 256>>>(scores);
        attn_pv<<<dim3(8, HH), 256>>>(scores, v, o);
        gemm_bias<<<dim3(DD / 64, LL / 128), 256>>>(o, wo, bo, src2, LL, DD, DD);

        // x = LN(x + broadcast(src2))
        add_ln<<<BB * LL, 256>>>(x, src2, LL - 1, g1, be1);
        // FFN (folded): tmp = x@Wff + bff ; x = LN(x + tmp)
        gemm_bias<<<dim3(DD / 64, (BB * LL) / 128), 256>>>(x, Wff, bff, tmp,
                                                           BB * LL, DD, DD);
        add_ln<<<BB * LL, 256>>>(x, tmp, BB * LL - 1, g2, be2);
    }

    pool_mean<<<dim3(DD / 256, BB), 256>>>(x);
    logits_kernel<<<BB * CC, 256>>>(wf, bf, out);
}

// round 2
// speedup vs baseline: 1.0004x; 1.0004x over previous
#include <cuda_runtime.h>
#include <cuda_bf16.h>

// Problem constants
#define BB 16
#define LL 512
#define DD 1024
#define HH 16
#define DK 64
#define FF 4096
#define CC 10
#define NLAYER 6

// ---------------- scratch (static __device__, no allocations) ----------------
__device__ float g_x[BB * LL * DD];       // activations [8192,1024]
__device__ float g_tmp[BB * LL * DD];     // FFN output
__device__ float g_q[LL * DD];
__device__ float g_k[LL * DD];
__device__ float g_v[LL * DD];
__device__ float g_o[LL * DD];
__device__ float g_src2[LL * DD];
__device__ float g_scores[HH * LL * LL];  // [16,512,512]
__device__ float g_Wff[DD * DD];          // w1@w2
__device__ float g_bff[DD];               // b1@w2 + b2
__device__ float g_bffpart[32 * DD];
__device__ float g_pooled[BB * DD];
__device__ int   g_ids64;

// ---------------- reductions ----------------
__device__ __forceinline__ float warpSum(float v) {
    #pragma unroll
    for (int o = 16; o > 0; o >>= 1) v += __shfl_xor_sync(0xffffffffu, v, o);
    return v;
}
__device__ __forceinline__ float warpMax(float v) {
    #pragma unroll
    for (int o = 16; o > 0; o >>= 1) v = fmaxf(v, __shfl_xor_sync(0xffffffffu, v, o));
    return v;
}
__device__ __forceinline__ float blockSum(float v) {
    __shared__ float sm[32];
    int lane = threadIdx.x & 31, w = threadIdx.x >> 5;
    v = warpSum(v);
    if (lane == 0) sm[w] = v;
    __syncthreads();
    if (w == 0) {
        float x = (lane < (int)(blockDim.x >> 5)) ? sm[lane] : 0.f;
        x = warpSum(x);
        if (lane == 0) sm[0] = x;
    }
    __syncthreads();
    float r = sm[0];
    __syncthreads();
    return r;
}
__device__ __forceinline__ float blockMax(float v) {
    __shared__ float sm[32];
    int lane = threadIdx.x & 31, w = threadIdx.x >> 5;
    v = warpMax(v);
    if (lane == 0) sm[w] = v;
    __syncthreads();
    if (w == 0) {
        float x = (lane < (int)(blockDim.x >> 5)) ? sm[lane] : -3.4e38f;
        x = warpMax(x);
        if (lane == 0) sm[0] = x;
    }
    __syncthreads();
    float r = sm[0];
    __syncthreads();
    return r;
}

// ---------------- dtype detect + embed ----------------
__global__ void detect_kernel(const void* ids) {
    // int64 tokens (< 2^31) have zero high words; 128 random int32 tokens can't all be 0.
    const int* p = (const int*)ids;
    int nz = 0;
    for (int i = 0; i < 256; i += 2)
        if (p[i + 1] != 0) nz++;
    g_ids64 = (nz == 0) ? 1 : 0;
}

__global__ void embed_kernel(const void* ids, const float* __restrict__ emb,
                             const float* __restrict__ pe) {
    int row = blockIdx.x;              // 0..8191  (b*512 + l)
    int d = threadIdx.x * 4;
    long long id;
    if (g_ids64) id = ((const long long*)ids)[row];
    else         id = (long long)((const int*)ids)[row];
    int l = row & (LL - 1);
    float4 e = *(const float4*)(emb + (size_t)id * DD + d);
    float4 p = *(const float4*)(pe + (size_t)l * DD + d);
    float4 o;
    o.x = e.x * 32.f + p.x; o.y = e.y * 32.f + p.y;
    o.z = e.z * 32.f + p.z; o.w = e.w * 32.f + p.w;
    *(float4*)(g_x + (size_t)row * DD + d) = o;
}

// ---------------- generic fp32 GEMM: C = A@B (+bias), tiles 128x64x16 ----------------
__device__ __forceinline__ void gemm_body(const float* __restrict__ A,
                                          const float* __restrict__ Bm,
                                          const float* __restrict__ bias,
                                          float* __restrict__ C,
                                          int M, int N, int K) {
    __shared__ __align__(16) float As[16][132];
    __shared__ __align__(16) float Bs[16][68];
    int t = threadIdx.x;
    int tx = t & 15, ty = t >> 4;
    int m0 = blockIdx.y * 128;
    int n0 = blockIdx.x * 64;
    float acc[8][4];
    #pragma unroll
    for (int i = 0; i < 8; i++)
        #pragma unroll
        for (int j = 0; j < 4; j++) acc[i][j] = 0.f;

    for (int k0 = 0; k0 < K; k0 += 16) {
        #pragma unroll
        for (int it = 0; it < 2; it++) {
            int idx = t * 2 + it;          // 0..511 float4s of A tile
            int row = idx >> 2;
            int c4 = (idx & 3) * 4;
            float4 va = *(const float4*)(A + (size_t)(m0 + row) * K + k0 + c4);
            As[c4 + 0][row] = va.x; As[c4 + 1][row] = va.y;
            As[c4 + 2][row] = va.z; As[c4 + 3][row] = va.w;
        }
        {
            int row = t >> 4;              // 0..15
            int c4 = (t & 15) * 4;
            *(float4*)(&Bs[row][c4]) =
                *(const float4*)(Bm + (size_t)(k0 + row) * N + n0 + c4);
        }
        __syncthreads();
        #pragma unroll
        for (int kk = 0; kk < 16; kk++) {
            float a[8], b[4];
            #pragma unroll
            for (int i = 0; i < 8; i++) a[i] = As[kk][ty + i * 16];
            #pragma unroll
            for (int j = 0; j < 4; j++) b[j] = Bs[kk][tx + j * 16];
            #pragma unroll
            for (int i = 0; i < 8; i++)
                #pragma unroll
                for (int j = 0; j < 4; j++)
                    acc[i][j] = fmaf(a[i], b[j], acc[i][j]);
        }
        __syncthreads();
    }
    #pragma unroll
    for (int j = 0; j < 4; j++) {
        int n = n0 + tx + j * 16;
        float bv = bias ? bias[n] : 0.f;
        #pragma unroll
        for (int i = 0; i < 8; i++) {
            int m = m0 + ty + i * 16;
            C[(size_t)m * N + n] = acc[i][j] + bv;
        }
    }
}

__global__ __launch_bounds__(256) void gemm_bias(const float* __restrict__ A,
                                                 const float* __restrict__ Bm,
                                                 const float* __restrict__ bias,
                                                 float* __restrict__ C,
                                                 int M, int N, int K) {
    gemm_body(A, Bm, bias, C, M, N, K);
}

__global__ __launch_bounds__(256) void gemm_qkv(const float* __restrict__ A,
                                                const float* __restrict__ Bq,
                                                const float* __restrict__ Bk,
                                                const float* __restrict__ Bv,
                                                const float* __restrict__ bq,
                                                const float* __restrict__ bk,
                                                const float* __restrict__ bv,
                                                float* __restrict__ Cq,
                                                float* __restrict__ Ck,
                                                float* __restrict__ Cv,
                                                int M, int N, int K) {
    const float* Bm = (blockIdx.z == 0) ? Bq : (blockIdx.z == 1) ? Bk : Bv;
    const float* bi = (blockIdx.z == 0) ? bq : (blockIdx.z == 1) ? bk : bv;
    float* C        = (blockIdx.z == 0) ? Cq : (blockIdx.z == 1) ? Ck : Cv;
    gemm_body(A, Bm, bi, C, M, N, K);
}

// ---------------- attention (batch 0 only) ----------------
// scores[h, m, n] = (q_h[m,:] . k_h[n,:]) / 8     grid:(ntile=8, mtile=8, head=16)
__global__ __launch_bounds__(256) void attn_scores(const float* __restrict__ q,
                                                   const float* __restrict__ k,
                                                   float* __restrict__ s) {
    __shared__ __align__(16) float Qs[64][68];   // [kk][m]
    __shared__ __align__(16) float Ks[64][68];   // [kk][n]
    int h = blockIdx.z, m0 = blockIdx.y * 64, n0 = blockIdx.x * 64;
    int t = threadIdx.x, tx = t & 15, ty = t >> 4;
    #pragma unroll
    for (int it = 0; it < 4; it++) {
        int idx = it * 256 + t;          // 0..1023 float4s
        int row = idx >> 4;
        int c4 = (idx & 15) * 4;
        float4 vq = *(const float4*)(q + (size_t)(m0 + row) * DD + h * 64 + c4);
        Qs[c4 + 0][row] = vq.x; Qs[c4 + 1][row] = vq.y;
        Qs[c4 + 2][row] = vq.z; Qs[c4 + 3][row] = vq.w;
        float4 vk = *(const float4*)(k + (size_t)(n0 + row) * DD + h * 64 + c4);
        Ks[c4 + 0][row] = vk.x; Ks[c4 + 1][row] = vk.y;
        Ks[c4 + 2][row] = vk.z; Ks[c4 + 3][row] = vk.w;
    }
    __syncthreads();
    float acc[4][4];
    #pragma unroll
    for (int i = 0; i < 4; i++)
        #pragma unroll
        for (int j = 0; j < 4; j++) acc[i][j] = 0.f;
    #pragma unroll 8
    for (int kk = 0; kk < 64; kk++) {
        float a[4], b[4];
        #pragma unroll
        for (int i = 0; i < 4; i++) a[i] = Qs[kk][ty + i * 16];
        #pragma unroll
        for (int j = 0; j < 4; j++) b[j] = Ks[kk][tx + j * 16];
        #pragma unroll
        for (int i = 0; i < 4; i++)
            #pragma unroll
            for (int j = 0; j < 4; j++)
                acc[i][j] = fmaf(a[i], b[j], acc[i][j]);
    }
    #pragma unroll
    for (int i = 0; i < 4; i++) {
        int m = m0 + ty + i * 16;
        #pragma unroll
        for (int j = 0; j < 4; j++) {
            int n = n0 + tx + j * 16;
            s[((size_t)h * LL + m) * LL + n] = acc[i][j] * 0.125f;
        }
    }
}

__global__ __launch_bounds__(256) void softmax512(float* __restrict__ s) {
    float* r = s + (size_t)blockIdx.x * LL;
    int t = threadIdx.x;
    float v0 = r[t], v1 = r[t + 256];
    float m = blockMax(fmaxf(v0, v1));
    float e0 = expf(v0 - m), e1 = expf(v1 - m);
    float inv = 1.f / blockSum(e0 + e1);
    r[t] = e0 * inv;
    r[t + 256] = e1 * inv;
}

// o_h = p_h @ v_h   grid:(mtile=8, head=16)
__global__ __launch_bounds__(256) void attn_pv(const float* __restrict__ p,
                                               const float* __restrict__ v,
                                               float* __restrict__ o) {
    __shared__ __align__(16) float Ps[64][68];   // [kk][m]
    __shared__ __align__(16) float Vs[64][68];   // [kk][n]
    int h = blockIdx.y, m0 = blockIdx.x * 64;
    int t = threadIdx.x, tx = t & 15, ty = t >> 4;
    float acc[4][4];
    #pragma unroll
    for (int i = 0; i < 4; i++)
        #pragma unroll
        for (int j = 0; j < 4; j++) acc[i][j] = 0.f;

    for (int k0 = 0; k0 < LL; k0 += 64) {
        #pragma unroll
        for (int it = 0; it < 4; it++) {
            int idx = it * 256 + t;
            int row = idx >> 4;
            int c4 = (idx & 15) * 4;
            float4 vp = *(const float4*)(p + ((size_t)h * LL + m0 + row) * LL + k0 + c4);
            Ps[c4 + 0][row] = vp.x; Ps[c4 + 1][row] = vp.y;
            Ps[c4 + 2][row] = vp.z; Ps[c4 + 3][row] = vp.w;
            float4 vv = *(const float4*)(v + (size_t)(k0 + row) * DD + h * 64 + c4);
            *(float4*)(&Vs[row][c4]) = vv;
        }
        __syncthreads();
        #pragma unroll 8
        for (int kk = 0; kk < 64; kk++) {
            float a[4], b[4];
            #pragma unroll
            for (int i = 0; i < 4; i++) a[i] = Ps[kk][ty + i * 16];
            #pragma unroll
            for (int j = 0; j < 4; j++) b[j] = Vs[kk][tx + j * 16];
            #pragma unroll
            for (int i = 0; i < 4; i++)
                #pragma unroll
                for (int j = 0; j < 4; j++)
                    acc[i][j] = fmaf(a[i], b[j], acc[i][j]);
        }
        __syncthreads();
    }
    #pragma unroll
    for (int i = 0; i < 4; i++) {
        int m = m0 + ty + i * 16;
        #pragma unroll
        for (int j = 0; j < 4; j++)
            o[(size_t)m * DD + h * 64 + tx + j * 16] = acc[i][j];
    }
}

// ---------------- residual add + LayerNorm (in place on x) ----------------
__global__ __launch_bounds__(256) void add_ln(float* __restrict__ x,
                                              const float* __restrict__ add,
                                              int addMask,
                                              const float* __restrict__ g,
                                              const float* __restrict__ b) {
    int row = blockIdx.x;
    int t = threadIdx.x;
    float* xr = x + (size_t)row * DD;
    const float* ar = add + (size_t)(row & addMask) * DD;
    float4 xv = *(const float4*)(xr + t * 4);
    float4 av = *(const float4*)(ar + t * 4);
    float v0 = xv.x + av.x, v1 = xv.y + av.y, v2 = xv.z + av.z, v3 = xv.w + av.w;
    float mean = blockSum(v0 + v1 + v2 + v3) * (1.f / DD);
    float d0 = v0 - mean, d1 = v1 - mean, d2 = v2 - mean, d3 = v3 - mean;
    float var = blockSum(d0 * d0 + d1 * d1 + d2 * d2 + d3 * d3) * (1.f / DD);
    float rs = rsqrtf(var + 1e-5f);
    float4 gv = *(const float4*)(g + t * 4);
    float4 bv = *(const float4*)(b + t * 4);
    float4 o;
    o.x = d0 * rs * gv.x + bv.x;
    o.y = d1 * rs * gv.y + bv.y;
    o.z = d2 * rs * gv.z + bv.z;
    o.w = d3 * rs * gv.w + bv.w;
    *(float4*)(xr + t * 4) = o;
}

// ---------------- folded FFN bias: bff = b1@w2 + b2 ----------------
__global__ __launch_bounds__(256) void bff_part(const float* __restrict__ b1,
                                                const float* __restrict__ w2) {
    int y = blockIdx.x;            // 0..31, f range [y*128,(y+1)*128)
    int t = threadIdx.x;
    float s[4] = {0.f, 0.f, 0.f, 0.f};
    int f0 = y * 128;
    for (int f = f0; f < f0 + 128; f++) {
        float bv = b1[f];
        const float* wr = w2 + (size_t)f * DD;
        #pragma unroll
        for (int j = 0; j < 4; j++) s[j] = fmaf(bv, wr[t + j * 256], s[j]);
    }
    #pragma unroll
    for (int j = 0; j < 4; j++) g_bffpart[y * DD + t + j * 256] = s[j];
}
__global__ __launch_bounds__(256) void bff_reduce(const float* __restrict__ b2) {
    int d = blockIdx.x * 256 + threadIdx.x;
    float s = b2[d];
    for (int y = 0; y < 32; y++) s += g_bffpart[y * DD + d];
    g_bff[d] = s;
}

// ---------------- pooling + classifier ----------------
__global__ __launch_bounds__(256) void pool_mean(const float* __restrict__ x) {
    int b = blockIdx.y;
    int d = blockIdx.x * 256 + threadIdx.x;
    const float* p = x + ((size_t)b * LL) * DD + d;
    float s = 0.f;
    for (int l = 0; l < LL; l++) s += p[(size_t)l * DD];
    g_pooled[b * DD + d] = s * (1.f / LL);
}
__global__ __launch_bounds__(256) void logits_kernel(const float* __restrict__ wf,
                                                     const float* __restrict__ bf,
                                                     float* __restrict__ out) {
    int b = blockIdx.x / CC, c = blockIdx.x % CC;
    float s = 0.f;
    for (int d = threadIdx.x; d < DD; d += 256)
        s += g_pooled[b * DD + d] * wf[(size_t)d * CC + c];
    s = blockSum(s);
    if (threadIdx.x == 0) out[b * CC + c] = s + bf[c];
}

// ---------------- launch ----------------
extern "C" void kernel_launch(void* const* d_in, const int* in_sizes, int n_in,
                              void* d_out, int out_size) {
    const void*  ids = d_in[0];
    const float* emb = (const float*)d_in[1];
    const float* pe  = (const float*)d_in[2];
    const float* wq  = (const float*)d_in[3];
    const float* bq  = (const float*)d_in[4];
    const float* wk  = (const float*)d_in[5];
    const float* bk  = (const float*)d_in[6];
    const float* wv  = (const float*)d_in[7];
    const float* bv  = (const float*)d_in[8];
    const float* wo  = (const float*)d_in[9];
    const float* bo  = (const float*)d_in[10];
    const float* w1  = (const float*)d_in[11];
    const float* b1  = (const float*)d_in[12];
    const float* w2  = (const float*)d_in[13];
    const float* b2  = (const float*)d_in[14];
    const float* g1  = (const float*)d_in[15];
    const float* be1 = (const float*)d_in[16];
    const float* g2  = (const float*)d_in[17];
    const float* be2 = (const float*)d_in[18];
    const float* wf  = (const float*)d_in[19];
    const float* bf  = (const float*)d_in[20];
    float* out = (float*)d_out;

    float *x, *tmp, *q, *k, *v, *o, *src2, *scores, *Wff, *bff;
    cudaGetSymbolAddress((void**)&x, g_x);
    cudaGetSymbolAddress((void**)&tmp, g_tmp);
    cudaGetSymbolAddress((void**)&q, g_q);
    cudaGetSymbolAddress((void**)&k, g_k);
    cudaGetSymbolAddress((void**)&v, g_v);
    cudaGetSymbolAddress((void**)&o, g_o);
    cudaGetSymbolAddress((void**)&src2, g_src2);
    cudaGetSymbolAddress((void**)&scores, g_scores);
    cudaGetSymbolAddress((void**)&Wff, g_Wff);
    cudaGetSymbolAddress((void**)&bff, g_bff);

    detect_kernel<<<1, 1>>>(ids);
    embed_kernel<<<BB * LL, 256>>>(ids, emb, pe);

    // Folded FFN: Wff = w1@w2, bff = b1@w2 + b2
    bff_part<<<32, 256>>>(b1, w2);
    bff_reduce<<<4, 256>>>(b2);
    gemm_bias<<<dim3(DD / 64, DD / 128), 256>>>(w1, w2, nullptr, Wff, DD, DD, FF);

    for (int layer = 0; layer < NLAYER; layer++) {
        // Attention path on batch 0 (rows 0..511 of x)
        gemm_qkv<<<dim3(DD / 64, LL / 128, 3), 256>>>(x, wq, wk, wv, bq, bk, bv,
                                                      q, k, v, LL, DD, DD);
        attn_scores<<<dim3(8, 8, HH), 256>>>(q, k, scores);
        softmax512<<<HH * LL, 256>>>(scores);
        attn_pv<<<dim3(8, HH), 256>>>(scores, v, o);
        gemm_bias<<<dim3(DD / 64, LL / 128), 256>>>(o, wo, bo, src2, LL, DD, DD);

        // x = LN(x + broadcast(src2))
        add_ln<<<BB * LL, 256>>>(x, src2, LL - 1, g1, be1);
        // FFN (folded): tmp = x@Wff + bff ; x = LN(x + tmp)
        gemm_bias<<<dim3(DD / 64, (BB * LL) / 128), 256>>>(x, Wff, bff, tmp,
                                                           BB * LL, DD, DD);
        add_ln<<<BB * LL, 256>>>(x, tmp, BB * LL - 1, g2, be2);
    }

    pool_mean<<<dim3(DD / 256, BB), 256>>>(x);
    logits_kernel<<<BB * CC, 256>>>(wf, bf, out);
}

// round 4
// speedup vs baseline: 2.1351x; 2.1342x over previous
#include <cuda_runtime.h>
#include <cuda_bf16.h>
#include <cstdint>

#define BB 16
#define LL 512
#define DD 1024
#define HH 16
#define FF 4096
#define CC 10
#define NLAYER 6

typedef __nv_bfloat16 bf16;

// ---------------- scratch ----------------
__device__ float g_tmp[BB * LL * DD];
__device__ bf16 g_xhi[BB * LL * DD];
__device__ bf16 g_xlo[BB * LL * DD];
__device__ float g_qkv[LL * 3 * DD];
__device__ float g_scores[HH * LL * LL];
__device__ bf16 g_ohi[LL * DD];
__device__ bf16 g_olo[LL * DD];
__device__ float g_src2[LL * DD];
__device__ float g_Wff[DD * DD];
__device__ float g_bff[DD];
__device__ float g_bffpart[32 * DD];
__device__ float g_bqkv[3 * DD];
__device__ float g_pooled[BB * DD];
__device__ int g_ids64;
__device__ bf16 g_wqkvT_hi[3 * DD * DD], g_wqkvT_lo[3 * DD * DD];
__device__ bf16 g_woT_hi[DD * DD], g_woT_lo[DD * DD];
__device__ bf16 g_WffT_hi[DD * DD], g_WffT_lo[DD * DD];
__device__ bf16 g_w1_hi[DD * FF], g_w1_lo[DD * FF];
__device__ bf16 g_w2T_hi[DD * FF], g_w2T_lo[DD * FF];

__device__ __forceinline__ void f2hl(float v, bf16& h, bf16& l) {
    h = __float2bfloat16(v);
    l = __float2bfloat16(v - __bfloat162float(h));
}
__device__ __forceinline__ float warpSum(float v) {
    #pragma unroll
    for (int o = 16; o > 0; o >>= 1) v += __shfl_xor_sync(0xffffffffu, v, o);
    return v;
}
__device__ __forceinline__ float warpMax(float v) {
    #pragma unroll
    for (int o = 16; o > 0; o >>= 1) v = fmaxf(v, __shfl_xor_sync(0xffffffffu, v, o));
    return v;
}
__device__ __forceinline__ float blockSum(float v) {
    __shared__ float sm[32];
    int lane = threadIdx.x & 31, w = threadIdx.x >> 5;
    v = warpSum(v);
    if (lane == 0) sm[w] = v;
    __syncthreads();
    if (w == 0) {
        float x = (lane < (int)(blockDim.x >> 5)) ? sm[lane] : 0.f;
        x = warpSum(x);
        if (lane == 0) sm[0] = x;
    }
    __syncthreads();
    float r = sm[0];
    __syncthreads();
    return r;
}
__device__ __forceinline__ float blockMax(float v) {
    __shared__ float sm[32];
    int lane = threadIdx.x & 31, w = threadIdx.x >> 5;
    v = warpMax(v);
    if (lane == 0) sm[w] = v;
    __syncthreads();
    if (w == 0) {
        float x = (lane < (int)(blockDim.x >> 5)) ? sm[lane] : -3.4e38f;
        x = warpMax(x);
        if (lane == 0) sm[0] = x;
    }
    __syncthreads();
    float r = sm[0];
    __syncthreads();
    return r;
}

// ---------------- PTX helpers (baseline PTX only: sm_80-class) ----------------
__device__ __forceinline__ uint32_t s2u(const void* p) {
    uint32_t a;
    asm("{ .reg .u64 t; cvta.to.shared.u64 t, %1; cvt.u32.u64 %0, t; }" : "=r"(a) : "l"(p));
    return a;
}
__device__ __forceinline__ void cpa(uint32_t dst, const void* src) {
    asm volatile("cp.async.cg.shared.global [%0], [%1], 16;" :: "r"(dst), "l"(src));
}
__device__ __forceinline__ void cpcommit() { asm volatile("cp.async.commit_group;"); }
template <int N> __device__ __forceinline__ void cpwait() {
    asm volatile("cp.async.wait_group %0;" :: "n"(N));
}
__device__ __forceinline__ void ldmx4(uint32_t* r, uint32_t a) {
    asm volatile("ldmatrix.sync.aligned.m8n8.x4.shared.b16 {%0,%1,%2,%3}, [%4];"
                 : "=r"(r[0]), "=r"(r[1]), "=r"(r[2]), "=r"(r[3]) : "r"(a));
}
__device__ __forceinline__ void mmabf(float* d, const uint32_t* a, const uint32_t* b) {
    asm volatile(
        "mma.sync.aligned.m16n8k16.row.col.f32.bf16.bf16.f32 "
        "{%0,%1,%2,%3}, {%4,%5,%6,%7}, {%8,%9}, {%0,%1,%2,%3};"
        : "+f"(d[0]), "+f"(d[1]), "+f"(d[2]), "+f"(d[3])
        : "r"(a[0]), "r"(a[1]), "r"(a[2]), "r"(a[3]), "r"(b[0]), "r"(b[1]));
}

// ---------------- bf16x3 mma.sync GEMM: C[M,N] = (Ahi+Alo)@(Bhi+Blo)^T + bias ----------------
// CTA tile 128x128, K-block 32, 2-stage cp.async pipeline, 8 warps (2x4), warp tile 64x32.
#define KBLK 32
#define PITCH 80               // bytes per smem row: 32 bf16 = 64B + 16B pad (ldmatrix conflict-free)
#define OFS_AHI 0
#define OFS_ALO 10240
#define OFS_BHI 20480
#define OFS_BLO 30720
#define STB 40960
#define GSMEM (2 * STB)

__device__ __forceinline__ void gemm_load_stage(
    const bf16* __restrict__ Ahi, const bf16* __restrict__ Alo,
    const bf16* __restrict__ Bhi, const bf16* __restrict__ Blo,
    int K, int m0, int n0, int kb0, uint32_t base, int t) {
    #pragma unroll
    for (int i = 0; i < 2; i++) {
        int idx = t + i * 256;         // 512 chunks: 128 rows x 4 x 16B
        int row = idx >> 2, c = idx & 3;
        uint32_t so = (uint32_t)(row * PITCH + c * 16);
        size_t ga = (size_t)(m0 + row) * K + kb0 + c * 8;
        size_t gb = (size_t)(n0 + row) * K + kb0 + c * 8;
        cpa(base + OFS_AHI + so, Ahi + ga);
        cpa(base + OFS_ALO + so, Alo + ga);
        cpa(base + OFS_BHI + so, Bhi + gb);
        cpa(base + OFS_BLO + so, Blo + gb);
    }
    cpcommit();
}

__global__ __launch_bounds__(256, 1) void gemm_tc(
    const bf16* __restrict__ Ahi, const bf16* __restrict__ Alo,
    const bf16* __restrict__ Bhi, const bf16* __restrict__ Blo,
    const float* __restrict__ bias, float* __restrict__ C, int K, int N) {
    extern __shared__ char smem[];
    uint32_t sb = s2u(smem);
    const int t = threadIdx.x, lane = t & 31, wid = t >> 5;
    const int m0 = blockIdx.y * 128, n0 = blockIdx.x * 128;
    const int wr = wid >> 2, wc = wid & 3;    // warp offsets: m += wr*64, n += wc*32
    const int NKB = K / KBLK;

    float acc[4][4][4];
    #pragma unroll
    for (int i = 0; i < 4; i++)
        #pragma unroll
        for (int j = 0; j < 4; j++)
            #pragma unroll
            for (int r = 0; r < 4; r++) acc[i][j][r] = 0.f;

    // precomputed fragment address offsets (within a stage buffer)
    const uint32_t aoff = (uint32_t)((wr * 64 + (lane & 15)) * PITCH + ((lane >> 4) << 4));
    const int brow = wc * 32 + (lane & 7) + ((lane & 16) ? 8 : 0);
    const uint32_t boff = (uint32_t)(brow * PITCH + ((lane & 8) ? 16 : 0));

    gemm_load_stage(Ahi, Alo, Bhi, Blo, K, m0, n0, 0, sb, t);

    for (int kb = 0; kb < NKB; kb++) {
        int cur = kb & 1;
        if (kb + 1 < NKB) {
            gemm_load_stage(Ahi, Alo, Bhi, Blo, K, m0, n0, (kb + 1) * KBLK,
                            sb + (uint32_t)(cur ^ 1) * STB, t);
            cpwait<1>();
        } else {
            cpwait<0>();
        }
        __syncthreads();
        uint32_t base = sb + (uint32_t)cur * STB;
        #pragma unroll
        for (int ks = 0; ks < 2; ks++) {
            uint32_t kbyte = (uint32_t)(ks * 32);
            uint32_t ah[4][4], bh[2][4], bl[2][4];
            #pragma unroll
            for (int mt = 0; mt < 4; mt++)
                ldmx4(ah[mt], base + OFS_AHI + aoff + (uint32_t)(mt * 16 * PITCH) + kbyte);
            #pragma unroll
            for (int ng = 0; ng < 2; ng++) {
                ldmx4(bh[ng], base + OFS_BHI + boff + (uint32_t)(ng * 16 * PITCH) + kbyte);
                ldmx4(bl[ng], base + OFS_BLO + boff + (uint32_t)(ng * 16 * PITCH) + kbyte);
            }
            #pragma unroll
            for (int mt = 0; mt < 4; mt++)
                #pragma unroll
                for (int nt = 0; nt < 4; nt++) {
                    mmabf(acc[mt][nt], ah[mt], &bh[nt >> 1][(nt & 1) * 2]);
                    mmabf(acc[mt][nt], ah[mt], &bl[nt >> 1][(nt & 1) * 2]);
                }
            #pragma unroll
            for (int mt = 0; mt < 4; mt++) {
                uint32_t al[4];
                ldmx4(al, base + OFS_ALO + aoff + (uint32_t)(mt * 16 * PITCH) + kbyte);
                #pragma unroll
                for (int nt = 0; nt < 4; nt++)
                    mmabf(acc[mt][nt], al, &bh[nt >> 1][(nt & 1) * 2]);
            }
        }
        __syncthreads();
    }

    // epilogue
    #pragma unroll
    for (int mt = 0; mt < 4; mt++) {
        int m = m0 + wr * 64 + mt * 16 + (lane >> 2);
        #pragma unroll
        for (int nt = 0; nt < 4; nt++) {
            int n = n0 + wc * 32 + nt * 8 + (lane & 3) * 2;
            float b0 = 0.f, b1 = 0.f;
            if (bias) { b0 = bias[n]; b1 = bias[n + 1]; }
            float2 v0 = make_float2(acc[mt][nt][0] + b0, acc[mt][nt][1] + b1);
            float2 v1 = make_float2(acc[mt][nt][2] + b0, acc[mt][nt][3] + b1);
            *(float2*)(C + (size_t)m * N + n) = v0;
            *(float2*)(C + (size_t)(m + 8) * N + n) = v1;
        }
    }
}

// ---------------- prep ----------------
__global__ void detect_kernel(const void* ids) {
    const int* p = (const int*)ids;
    int nz = 0;
    for (int i = 0; i < 256; i += 2)
        if (p[i + 1] != 0) nz++;
    g_ids64 = (nz == 0) ? 1 : 0;
}
__global__ void embed_kernel(const void* ids, const float* __restrict__ emb,
                             const float* __restrict__ pe) {
    int row = blockIdx.x;
    int d = threadIdx.x * 4;
    long long id;
    if (g_ids64) id = ((const long long*)ids)[row];
    else         id = (long long)((const int*)ids)[row];
    int l = row & (LL - 1);
    float4 e = *(const float4*)(emb + (size_t)id * DD + d);
    float4 p = *(const float4*)(pe + (size_t)l * DD + d);
    float v[4] = {e.x * 32.f + p.x, e.y * 32.f + p.y, e.z * 32.f + p.z, e.w * 32.f + p.w};
    size_t base = (size_t)row * DD + d;
    #pragma unroll
    for (int j = 0; j < 4; j++) {
        bf16 h, lo;
        f2hl(v[j], h, lo);
        g_xhi[base + j] = h;
        g_xlo[base + j] = lo;
    }
}
// transpose+convert: in[R,C] fp32 -> out[(nOff+c)*R + r] hi/lo
__global__ void tconv(const float* __restrict__ in, bf16* __restrict__ ohi,
                      bf16* __restrict__ olo, int R, int C, int nOff) {
    __shared__ float tl[32][33];
    int n0 = blockIdx.x * 32, k0 = blockIdx.y * 32;
    int tx = threadIdx.x, ty = threadIdx.y;
    #pragma unroll
    for (int i = 0; i < 4; i++)
        tl[ty + i * 8][tx] = in[(size_t)(k0 + ty + i * 8) * C + n0 + tx];
    __syncthreads();
    #pragma unroll
    for (int i = 0; i < 4; i++) {
        int nn = ty + i * 8;
        bf16 h, lo;
        f2hl(tl[tx][nn], h, lo);
        size_t o = (size_t)(nOff + n0 + nn) * R + k0 + tx;
        ohi[o] = h;
        olo[o] = lo;
    }
}
__global__ void conv_hl(const float* __restrict__ in, bf16* __restrict__ ohi,
                        bf16* __restrict__ olo) {
    size_t i = ((size_t)blockIdx.x * 256 + threadIdx.x) * 4;
    float4 v = *(const float4*)(in + i);
    float a[4] = {v.x, v.y, v.z, v.w};
    #pragma unroll
    for (int j = 0; j < 4; j++) {
        bf16 h, lo;
        f2hl(a[j], h, lo);
        ohi[i + j] = h;
        olo[i + j] = lo;
    }
}
__global__ void concat_bias(const float* __restrict__ bq, const float* __restrict__ bk,
                            const float* __restrict__ bv) {
    int t = threadIdx.x, s = blockIdx.x;
    const float* src = (s == 0) ? bq : (s == 1) ? bk : bv;
    g_bqkv[s * DD + t] = src[t];
}
__global__ __launch_bounds__(256) void bff_part(const float* __restrict__ b1,
                                                const float* __restrict__ w2) {
    int y = blockIdx.x, t = threadIdx.x;
    float s[4] = {0.f, 0.f, 0.f, 0.f};
    for (int f = y * 128; f < y * 128 + 128; f++) {
        float bv = b1[f];
        const float* wr = w2 + (size_t)f * DD;
        #pragma unroll
        for (int j = 0; j < 4; j++) s[j] = fmaf(bv, wr[t + j * 256], s[j]);
    }
    #pragma unroll
    for (int j = 0; j < 4; j++) g_bffpart[y * DD + t + j * 256] = s[j];
}
__global__ __launch_bounds__(256) void bff_reduce(const float* __restrict__ b2) {
    int d = blockIdx.x * 256 + threadIdx.x;
    float s = b2[d];
    for (int y = 0; y < 32; y++) s += g_bffpart[y * DD + d];
    g_bff[d] = s;
}

// ---------------- attention (batch 0), 128-wide tiles, 8x8 / 8x4 microtiles ----------------
__global__ __launch_bounds__(256) void attn_scores(const float* __restrict__ qkv,
                                                   float* __restrict__ s) {
    __shared__ __align__(16) float Qs[16][132];
    __shared__ __align__(16) float Ks[16][132];
    int h = blockIdx.z, m0 = blockIdx.y * 128, n0 = blockIdx.x * 128;
    int t = threadIdx.x, tx = t & 15, ty = t >> 4;
    float acc[8][8];
    #pragma unroll
    for (int i = 0; i < 8; i++)
        #pragma unroll
        for (int j = 0; j < 8; j++) acc[i][j] = 0.f;

    for (int k0 = 0; k0 < 64; k0 += 16) {
        #pragma unroll
        for (int i = 0; i < 2; i++) {
            int idx = t + i * 256;          // 512 chunks: 128 rows x 4 float4
            int m = idx >> 2, kg = idx & 3;
            float4 q4 = *(const float4*)(qkv + (size_t)(m0 + m) * (3 * DD) + h * 64 + k0 + kg * 4);
            Qs[kg * 4 + 0][m] = q4.x; Qs[kg * 4 + 1][m] = q4.y;
            Qs[kg * 4 + 2][m] = q4.z; Qs[kg * 4 + 3][m] = q4.w;
            float4 k4 = *(const float4*)(qkv + (size_t)(n0 + m) * (3 * DD) + DD + h * 64 + k0 + kg * 4);
            Ks[kg * 4 + 0][m] = k4.x; Ks[kg * 4 + 1][m] = k4.y;
            Ks[kg * 4 + 2][m] = k4.z; Ks[kg * 4 + 3][m] = k4.w;
        }
        __syncthreads();
        #pragma unroll
        for (int kk = 0; kk < 16; kk++) {
            float a_[8], b_[8];
            *(float4*)&a_[0] = *(const float4*)&Qs[kk][ty * 8];
            *(float4*)&a_[4] = *(const float4*)&Qs[kk][ty * 8 + 4];
            *(float4*)&b_[0] = *(const float4*)&Ks[kk][tx * 8];
            *(float4*)&b_[4] = *(const float4*)&Ks[kk][tx * 8 + 4];
            #pragma unroll
            for (int i = 0; i < 8; i++)
                #pragma unroll
                for (int j = 0; j < 8; j++)
                    acc[i][j] = fmaf(a_[i], b_[j], acc[i][j]);
        }
        __syncthreads();
    }
    #pragma unroll
    for (int i = 0; i < 8; i++) {
        int m = m0 + ty * 8 + i;
        float* row = s + ((size_t)h * LL + m) * LL + n0 + tx * 8;
        #pragma unroll
        for (int j4 = 0; j4 < 2; j4++) {
            float4 o;
            o.x = acc[i][j4 * 4 + 0] * 0.125f;
            o.y = acc[i][j4 * 4 + 1] * 0.125f;
            o.z = acc[i][j4 * 4 + 2] * 0.125f;
            o.w = acc[i][j4 * 4 + 3] * 0.125f;
            *(float4*)(row + j4 * 4) = o;
        }
    }
}

__global__ __launch_bounds__(256) void softmax512(float* __restrict__ s) {
    float* r = s + (size_t)blockIdx.x * LL;
    int t = threadIdx.x;
    float v0 = r[t], v1 = r[t + 256];
    float m = blockMax(fmaxf(v0, v1));
    float e0 = expf(v0 - m), e1 = expf(v1 - m);
    float inv = 1.f / blockSum(e0 + e1);
    r[t] = e0 * inv;
    r[t + 256] = e1 * inv;
}

__global__ __launch_bounds__(256) void attn_pv(const float* __restrict__ p,
                                               const float* __restrict__ qkv) {
    __shared__ __align__(16) float Ps[32][132];
    __shared__ __align__(16) float Vs[32][68];
    int h = blockIdx.y, m0 = blockIdx.x * 128;
    int t = threadIdx.x, tx = t & 15, ty = t >> 4;
    float acc[8][4];
    #pragma unroll
    for (int i = 0; i < 8; i++)
        #pragma unroll
        for (int j = 0; j < 4; j++) acc[i][j] = 0.f;

    for (int k0 = 0; k0 < LL; k0 += 32) {
        #pragma unroll
        for (int i = 0; i < 4; i++) {
            int idx = t + i * 256;          // 1024 chunks: 128 rows x 8 float4
            int m = idx >> 3, kg = idx & 7;
            float4 v4 = *(const float4*)(p + ((size_t)h * LL + m0 + m) * LL + k0 + kg * 4);
            Ps[kg * 4 + 0][m] = v4.x; Ps[kg * 4 + 1][m] = v4.y;
            Ps[kg * 4 + 2][m] = v4.z; Ps[kg * 4 + 3][m] = v4.w;
        }
        #pragma unroll
        for (int i = 0; i < 2; i++) {
            int idx = t + i * 256;          // 512 chunks: 32 rows x 16 float4
            int kk = idx >> 4, c = (idx & 15) * 4;
            *(float4*)&Vs[kk][c] =
                *(const float4*)(qkv + (size_t)(k0 + kk) * (3 * DD) + 2 * DD + h * 64 + c);
        }
        __syncthreads();
        #pragma unroll
        for (int kk = 0; kk < 32; kk++) {
            float4 b = *(const float4*)&Vs[kk][tx * 4];
            float a_[8];
            *(float4*)&a_[0] = *(const float4*)&Ps[kk][ty * 8];
            *(float4*)&a_[4] = *(const float4*)&Ps[kk][ty * 8 + 4];
            #pragma unroll
            for (int i = 0; i < 8; i++) {
                acc[i][0] = fmaf(a_[i], b.x, acc[i][0]);
                acc[i][1] = fmaf(a_[i], b.y, acc[i][1]);
                acc[i][2] = fmaf(a_[i], b.z, acc[i][2]);
                acc[i][3] = fmaf(a_[i], b.w, acc[i][3]);
            }
        }
        __syncthreads();
    }
    #pragma unroll
    for (int i = 0; i < 8; i++) {
        int m = m0 + ty * 8 + i;
        size_t base = (size_t)m * DD + h * 64 + tx * 4;
        #pragma unroll
        for (int j = 0; j < 4; j++) {
            bf16 hh, lo;
            f2hl(acc[i][j], hh, lo);
            g_ohi[base + j] = hh;
            g_olo[base + j] = lo;
        }
    }
}

// ---------------- residual + LayerNorm on hi/lo x ----------------
__global__ __launch_bounds__(256) void add_ln(bf16* __restrict__ xhi, bf16* __restrict__ xlo,
                                              const float* __restrict__ add, int addMask,
                                              const float* __restrict__ g,
                                              const float* __restrict__ b) {
    int row = blockIdx.x, t = threadIdx.x;
    size_t base = (size_t)row * DD + t * 4;
    __nv_bfloat162 h0 = *(const __nv_bfloat162*)(xhi + base);
    __nv_bfloat162 h1 = *(const __nv_bfloat162*)(xhi + base + 2);
    __nv_bfloat162 l0 = *(const __nv_bfloat162*)(xlo + base);
    __nv_bfloat162 l1 = *(const __nv_bfloat162*)(xlo + base + 2);
    float4 av = *(const float4*)(add + (size_t)(row & addMask) * DD + t * 4);
    float v0 = __low2float(h0) + __low2float(l0) + av.x;
    float v1 = __high2float(h0) + __high2float(l0) + av.y;
    float v2 = __low2float(h1) + __low2float(l1) + av.z;
    float v3 = __high2float(h1) + __high2float(l1) + av.w;
    float mean = blockSum(v0 + v1 + v2 + v3) * (1.f / DD);
    float d0 = v0 - mean, d1 = v1 - mean, d2 = v2 - mean, d3 = v3 - mean;
    float var = blockSum(d0 * d0 + d1 * d1 + d2 * d2 + d3 * d3) * (1.f / DD);
    float rs = rsqrtf(var + 1e-5f);
    float4 gv = *(const float4*)(g + t * 4);
    float4 bv = *(const float4*)(b + t * 4);
    float o0 = d0 * rs * gv.x + bv.x, o1 = d1 * rs * gv.y + bv.y;
    float o2 = d2 * rs * gv.z + bv.z, o3 = d3 * rs * gv.w + bv.w;
    bf16 hh, ll;
    f2hl(o0, hh, ll); xhi[base + 0] = hh; xlo[base + 0] = ll;
    f2hl(o1, hh, ll); xhi[base + 1] = hh; xlo[base + 1] = ll;
    f2hl(o2, hh, ll); xhi[base + 2] = hh; xlo[base + 2] = ll;
    f2hl(o3, hh, ll); xhi[base + 3] = hh; xlo[base + 3] = ll;
}

// ---------------- pooling + classifier ----------------
__global__ __launch_bounds__(256) void pool_mean() {
    int b = blockIdx.y;
    int d = blockIdx.x * 256 + threadIdx.x;
    size_t base = (size_t)b * LL * DD + d;
    float s = 0.f;
    for (int l = 0; l < LL; l++)
        s += __bfloat162float(g_xhi[base + (size_t)l * DD]) +
             __bfloat162float(g_xlo[base + (size_t)l * DD]);
    g_pooled[b * DD + d] = s * (1.f / LL);
}
__global__ __launch_bounds__(256) void logits_kernel(const float* __restrict__ wf,
                                                     const float* __restrict__ bf,
                                                     float* __restrict__ out) {
    int b = blockIdx.x / CC, c = blockIdx.x % CC;
    float s = 0.f;
    for (int d = threadIdx.x; d < DD; d += 256)
        s += g_pooled[b * DD + d] * wf[(size_t)d * CC + c];
    s = blockSum(s);
    if (threadIdx.x == 0) out[b * CC + c] = s + bf[c];
}

// ---------------- launch ----------------
extern "C" void kernel_launch(void* const* d_in, const int* in_sizes, int n_in,
                              void* d_out, int out_size) {
    const void*  ids = d_in[0];
    const float* emb = (const float*)d_in[1];
    const float* pe  = (const float*)d_in[2];
    const float* wq  = (const float*)d_in[3];
    const float* bq  = (const float*)d_in[4];
    const float* wk  = (const float*)d_in[5];
    const float* bk  = (const float*)d_in[6];
    const float* wv  = (const float*)d_in[7];
    const float* bv  = (const float*)d_in[8];
    const float* wo  = (const float*)d_in[9];
    const float* bo  = (const float*)d_in[10];
    const float* w1  = (const float*)d_in[11];
    const float* b1  = (const float*)d_in[12];
    const float* w2  = (const float*)d_in[13];
    const float* b2  = (const float*)d_in[14];
    const float* g1  = (const float*)d_in[15];
    const float* be1 = (const float*)d_in[16];
    const float* g2  = (const float*)d_in[17];
    const float* be2 = (const float*)d_in[18];
    const float* wf  = (const float*)d_in[19];
    const float* bf  = (const float*)d_in[20];
    float* out = (float*)d_out;

    cudaFuncSetAttribute(gemm_tc, cudaFuncAttributeMaxDynamicSharedMemorySize, GSMEM);

    float *tmp, *qkv, *scores, *src2, *Wff, *bff, *bqkv;
    bf16 *xhi, *xlo, *ohi, *olo, *wqkvTh, *wqkvTl, *woTh, *woTl, *WffTh, *WffTl, *w1h, *w1l, *w2Th, *w2Tl;
    cudaGetSymbolAddress((void**)&tmp, g_tmp);
    cudaGetSymbolAddress((void**)&qkv, g_qkv);
    cudaGetSymbolAddress((void**)&scores, g_scores);
    cudaGetSymbolAddress((void**)&src2, g_src2);
    cudaGetSymbolAddress((void**)&Wff, g_Wff);
    cudaGetSymbolAddress((void**)&bff, g_bff);
    cudaGetSymbolAddress((void**)&bqkv, g_bqkv);
    cudaGetSymbolAddress((void**)&xhi, g_xhi);
    cudaGetSymbolAddress((void**)&xlo, g_xlo);
    cudaGetSymbolAddress((void**)&ohi, g_ohi);
    cudaGetSymbolAddress((void**)&olo, g_olo);
    cudaGetSymbolAddress((void**)&wqkvTh, g_wqkvT_hi);
    cudaGetSymbolAddress((void**)&wqkvTl, g_wqkvT_lo);
    cudaGetSymbolAddress((void**)&woTh, g_woT_hi);
    cudaGetSymbolAddress((void**)&woTl, g_woT_lo);
    cudaGetSymbolAddress((void**)&WffTh, g_WffT_hi);
    cudaGetSymbolAddress((void**)&WffTl, g_WffT_lo);
    cudaGetSymbolAddress((void**)&w1h, g_w1_hi);
    cudaGetSymbolAddress((void**)&w1l, g_w1_lo);
    cudaGetSymbolAddress((void**)&w2Th, g_w2T_hi);
    cudaGetSymbolAddress((void**)&w2Tl, g_w2T_lo);

    detect_kernel<<<1, 1>>>(ids);
    embed_kernel<<<BB * LL, 256>>>(ids, emb, pe);

    dim3 tb(32, 8);
    tconv<<<dim3(32, 32), tb>>>(wq, wqkvTh, wqkvTl, DD, DD, 0);
    tconv<<<dim3(32, 32), tb>>>(wk, wqkvTh, wqkvTl, DD, DD, DD);
    tconv<<<dim3(32, 32), tb>>>(wv, wqkvTh, wqkvTl, DD, DD, 2 * DD);
    tconv<<<dim3(32, 32), tb>>>(wo, woTh, woTl, DD, DD, 0);
    tconv<<<dim3(32, 128), tb>>>(w2, w2Th, w2Tl, FF, DD, 0);
    conv_hl<<<(DD * FF) / 1024, 256>>>(w1, w1h, w1l);
    concat_bias<<<3, 1024>>>(bq, bk, bv);
    bff_part<<<32, 256>>>(b1, w2);
    bff_reduce<<<4, 256>>>(b2);
    // Wff = w1 @ w2
    gemm_tc<<<dim3(DD / 128, DD / 128), 256, GSMEM>>>(w1h, w1l, w2Th, w2Tl, nullptr, Wff, FF, DD);
    tconv<<<dim3(32, 32), tb>>>(Wff, WffTh, WffTl, DD, DD, 0);

    for (int layer = 0; layer < NLAYER; layer++) {
        gemm_tc<<<dim3(3 * DD / 128, LL / 128), 256, GSMEM>>>(xhi, xlo, wqkvTh, wqkvTl,
                                                              bqkv, qkv, DD, 3 * DD);
        attn_scores<<<dim3(4, 4, HH), 256>>>(qkv, scores);
        softmax512<<<HH * LL, 256>>>(scores);
        attn_pv<<<dim3(4, HH), 256>>>(scores, qkv);
        gemm_tc<<<dim3(DD / 128, LL / 128), 256, GSMEM>>>(ohi, olo, woTh, woTl, bo, src2, DD, DD);
        add_ln<<<BB * LL, 256>>>(xhi, xlo, src2, LL - 1, g1, be1);
        gemm_tc<<<dim3(DD / 128, (BB * LL) / 128), 256, GSMEM>>>(xhi, xlo, WffTh, WffTl,
                                                                 bff, tmp, DD, DD);
        add_ln<<<BB * LL, 256>>>(xhi, xlo, tmp, BB * LL - 1, g2, be2);
    }

    pool_mean<<<dim3(DD / 256, BB), 256>>>();
    logits_kernel<<<BB * CC, 256>>>(wf, bf, out);
}

// round 5
// speedup vs baseline: 2.6422x; 1.2375x over previous
#include <cuda_runtime.h>
#include <cuda_bf16.h>
#include <cstdint>

#define BB 16
#define LL 512
#define DD 1024
#define HH 16
#define FF 4096
#define CC 10
#define NLAYER 6

typedef __nv_bfloat16 bf16;

__device__ float g_tmp[BB * LL * DD];
__device__ bf16 g_xhi[BB * LL * DD];
__device__ bf16 g_xlo[BB * LL * DD];
__device__ float g_qkv[LL * 3 * DD];
__device__ float g_scores[HH * LL * LL];
__device__ float g_opart[2 * LL * DD];
__device__ bf16 g_ohi[LL * DD];
__device__ bf16 g_olo[LL * DD];
__device__ float g_src2[2 * LL * DD];
__device__ float g_Wff[2 * DD * DD];
__device__ float g_bff[DD];
__device__ float g_bffpart[32 * DD];
__device__ float g_bqkv[3 * DD];
__device__ float g_pooled[BB * DD];
__device__ int g_ids64;
__device__ bf16 g_wqkvT_hi[3 * DD * DD], g_wqkvT_lo[3 * DD * DD];
__device__ bf16 g_woT_hi[DD * DD], g_woT_lo[DD * DD];
__device__ bf16 g_WffT_hi[DD * DD], g_WffT_lo[DD * DD];
__device__ bf16 g_w1_hi[DD * FF], g_w1_lo[DD * FF];
__device__ bf16 g_w2T_hi[DD * FF], g_w2T_lo[DD * FF];

__device__ __forceinline__ void f2hl(float v, bf16& h, bf16& l) {
    h = __float2bfloat16(v);
    l = __float2bfloat16(v - __bfloat162float(h));
}
__device__ __forceinline__ float warpSum(float v) {
    #pragma unroll
    for (int o = 16; o > 0; o >>= 1) v += __shfl_xor_sync(0xffffffffu, v, o);
    return v;
}
__device__ __forceinline__ float warpMax(float v) {
    #pragma unroll
    for (int o = 16; o > 0; o >>= 1) v = fmaxf(v, __shfl_xor_sync(0xffffffffu, v, o));
    return v;
}
__device__ __forceinline__ float blockSum(float v) {
    __shared__ float sm[32];
    int lane = threadIdx.x & 31, w = threadIdx.x >> 5;
    v = warpSum(v);
    if (lane == 0) sm[w] = v;
    __syncthreads();
    if (w == 0) {
        float x = (lane < (int)(blockDim.x >> 5)) ? sm[lane] : 0.f;
        x = warpSum(x);
        if (lane == 0) sm[0] = x;
    }
    __syncthreads();
    float r = sm[0];
    __syncthreads();
    return r;
}
__device__ __forceinline__ float blockMax(float v) {
    __shared__ float sm[32];
    int lane = threadIdx.x & 31, w = threadIdx.x >> 5;
    v = warpMax(v);
    if (lane == 0) sm[w] = v;
    __syncthreads();
    if (w == 0) {
        float x = (lane < (int)(blockDim.x >> 5)) ? sm[lane] : -3.4e38f;
        x = warpMax(x);
        if (lane == 0) sm[0] = x;
    }
    __syncthreads();
    float r = sm[0];
    __syncthreads();
    return r;
}

__device__ __forceinline__ uint32_t s2u(const void* p) {
    uint32_t a;
    asm("{ .reg .u64 t; cvta.to.shared.u64 t, %1; cvt.u32.u64 %0, t; }" : "=r"(a) : "l"(p));
    return a;
}
__device__ __forceinline__ void cpa(uint32_t dst, const void* src) {
    asm volatile("cp.async.cg.shared.global [%0], [%1], 16;" :: "r"(dst), "l"(src));
}
__device__ __forceinline__ void cpcommit() { asm volatile("cp.async.commit_group;"); }
template <int N> __device__ __forceinline__ void cpwait() {
    asm volatile("cp.async.wait_group %0;" :: "n"(N));
}
__device__ __forceinline__ void ldmx4(uint32_t* r, uint32_t a) {
    asm volatile("ldmatrix.sync.aligned.m8n8.x4.shared.b16 {%0,%1,%2,%3}, [%4];"
                 : "=r"(r[0]), "=r"(r[1]), "=r"(r[2]), "=r"(r[3]) : "r"(a));
}
__device__ __forceinline__ void mmabf(float* d, const uint32_t* a, const uint32_t* b) {
    asm volatile(
        "mma.sync.aligned.m16n8k16.row.col.f32.bf16.bf16.f32 "
        "{%0,%1,%2,%3}, {%4,%5,%6,%7}, {%8,%9}, {%0,%1,%2,%3};"
        : "+f"(d[0]), "+f"(d[1]), "+f"(d[2]), "+f"(d[3])
        : "r"(a[0]), "r"(a[1]), "r"(a[2]), "r"(a[3]), "r"(b[0]), "r"(b[1]));
}

#define PITCH 80

template <int MT>
__global__ __launch_bounds__(MT * 2, (MT == 64) ? 3 : 2) void gemm_tc(
    const bf16* __restrict__ Ahi, const bf16* __restrict__ Alo,
    const bf16* __restrict__ Bhi, const bf16* __restrict__ Blo,
    const float* __restrict__ bias, float* __restrict__ C,
    int Kiter, int Kstride, int N, int Czoff) {
    constexpr int THREADS = MT * 2;
    constexpr int OFS_ALO = MT * PITCH;
    constexpr int OFS_BHI = 2 * MT * PITCH;
    constexpr int OFS_BLO = 2 * MT * PITCH + 128 * PITCH;
    constexpr int STB = (2 * MT + 256) * PITCH;
    extern __shared__ char smem[];
    uint32_t sb = s2u(smem);
    const int t = threadIdx.x, lane = t & 31, wid = t >> 5;
    const int m0 = blockIdx.y * MT, n0 = blockIdx.x * 128;
    const int wr = wid >> 2, wc = wid & 3;
    const size_t kz = (size_t)blockIdx.z * Kiter;
    C += (size_t)blockIdx.z * Czoff;
    const int NKB = Kiter / 32;

    float acc[4][4][4];
    #pragma unroll
    for (int i = 0; i < 4; i++)
        #pragma unroll
        for (int j = 0; j < 4; j++)
            #pragma unroll
            for (int r = 0; r < 4; r++) acc[i][j][r] = 0.f;

    const uint32_t aoff = (uint32_t)((wr * 64 + (lane & 15)) * PITCH + ((lane >> 4) << 4));
    const int brow = wc * 32 + (lane & 7) + ((lane & 16) ? 8 : 0);
    const uint32_t boff = (uint32_t)(brow * PITCH + ((lane & 8) ? 16 : 0));

    auto load_stage = [&](int kb0, uint32_t base) {
        #pragma unroll
        for (int idx = t; idx < MT * 4; idx += THREADS) {
            int row = idx >> 2, c = idx & 3;
            uint32_t so = (uint32_t)(row * PITCH + c * 16);
            size_t ga = (size_t)(m0 + row) * Kstride + kz + kb0 + c * 8;
            cpa(base + so, Ahi + ga);
            cpa(base + OFS_ALO + so, Alo + ga);
        }
        #pragma unroll
        for (int idx = t; idx < 512; idx += THREADS) {
            int row = idx >> 2, c = idx & 3;
            uint32_t so = (uint32_t)(row * PITCH + c * 16);
            size_t gb = (size_t)(n0 + row) * Kstride + kz + kb0 + c * 8;
            cpa(base + OFS_BHI + so, Bhi + gb);
            cpa(base + OFS_BLO + so, Blo + gb);
        }
        cpcommit();
    };

    load_stage(0, sb);

    for (int kb = 0; kb < NKB; kb++) {
        int cur = kb & 1;
        if (kb + 1 < NKB) {
            load_stage((kb + 1) * 32, sb + (uint32_t)(cur ^ 1) * STB);
            cpwait<1>();
        } else {
            cpwait<0>();
        }
        __syncthreads();
        uint32_t base = sb + (uint32_t)cur * STB;
        #pragma unroll
        for (int ks = 0; ks < 2; ks++) {
            uint32_t kbyte = (uint32_t)(ks * 32);
            uint32_t ah[4][4], bh[2][4], bl[2][4];
            #pragma unroll
            for (int mt = 0; mt < 4; mt++)
                ldmx4(ah[mt], base + aoff + (uint32_t)(mt * 16 * PITCH) + kbyte);
            #pragma unroll
            for (int ng = 0; ng < 2; ng++) {
                ldmx4(bh[ng], base + OFS_BHI + boff + (uint32_t)(ng * 16 * PITCH) + kbyte);
                ldmx4(bl[ng], base + OFS_BLO + boff + (uint32_t)(ng * 16 * PITCH) + kbyte);
            }
            #pragma unroll
            for (int mt = 0; mt < 4; mt++)
                #pragma unroll
                for (int nt = 0; nt < 4; nt++) {
                    mmabf(acc[mt][nt], ah[mt], &bh[nt >> 1][(nt & 1) * 2]);
                    mmabf(acc[mt][nt], ah[mt], &bl[nt >> 1][(nt & 1) * 2]);
                }
            #pragma unroll
            for (int mt = 0; mt < 4; mt++) {
                uint32_t al[4];
                ldmx4(al, base + OFS_ALO + aoff + (uint32_t)(mt * 16 * PITCH) + kbyte);
                #pragma unroll
                for (int nt = 0; nt < 4; nt++)
                    mmabf(acc[mt][nt], al, &bh[nt >> 1][(nt & 1) * 2]);
            }
        }
        __syncthreads();
    }

    #pragma unroll
    for (int mt = 0; mt < 4; mt++) {
        int m = m0 + wr * 64 + mt * 16 + (lane >> 2);
        #pragma unroll
        for (int nt = 0; nt < 4; nt++) {
            int n = n0 + wc * 32 + nt * 8 + (lane & 3) * 2;
            float b0 = 0.f, b1 = 0.f;
            if (bias) { b0 = bias[n]; b1 = bias[n + 1]; }
            *(float2*)(C + (size_t)m * N + n) = make_float2(acc[mt][nt][0] + b0, acc[mt][nt][1] + b1);
            *(float2*)(C + (size_t)(m + 8) * N + n) = make_float2(acc[mt][nt][2] + b0, acc[mt][nt][3] + b1);
        }
    }
}

__global__ void detect_kernel(const void* ids) {
    const int* p = (const int*)ids;
    int nz = 0;
    for (int i = 0; i < 256; i += 2)
        if (p[i + 1] != 0) nz++;
    g_ids64 = (nz == 0) ? 1 : 0;
}
__global__ void embed_kernel(const void* ids, const float* __restrict__ emb,
                             const float* __restrict__ pe) {
    int row = blockIdx.x;
    int d = threadIdx.x * 4;
    long long id;
    if (g_ids64) id = ((const long long*)ids)[row];
    else         id = (long long)((const int*)ids)[row];
    int l = row & (LL - 1);
    float4 e = *(const float4*)(emb + (size_t)id * DD + d);
    float4 p = *(const float4*)(pe + (size_t)l * DD + d);
    float v[4] = {e.x * 32.f + p.x, e.y * 32.f + p.y, e.z * 32.f + p.z, e.w * 32.f + p.w};
    size_t base = (size_t)row * DD + d;
    #pragma unroll
    for (int j = 0; j < 4; j++) {
        bf16 h, lo;
        f2hl(v[j], h, lo);
        g_xhi[base + j] = h;
        g_xlo[base + j] = lo;
    }
}
__global__ void tconv(const float* __restrict__ in, const float* __restrict__ in2,
                      bf16* __restrict__ ohi, bf16* __restrict__ olo, int R, int C, int nOff) {
    __shared__ float tl[32][33];
    int n0 = blockIdx.x * 32, k0 = blockIdx.y * 32;
    int tx = threadIdx.x, ty = threadIdx.y;
    #pragma unroll
    for (int i = 0; i < 4; i++) {
        size_t idx = (size_t)(k0 + ty + i * 8) * C + n0 + tx;
        float v = in[idx];
        if (in2) v += in2[idx];
        tl[ty + i * 8][tx] = v;
    }
    __syncthreads();
    #pragma unroll
    for (int i = 0; i < 4; i++) {
        int nn = ty + i * 8;
        bf16 h, lo;
        f2hl(tl[tx][nn], h, lo);
        size_t o = (size_t)(nOff + n0 + nn) * R + k0 + tx;
        ohi[o] = h;
        olo[o] = lo;
    }
}
__global__ void conv_hl(const float* __restrict__ in, bf16* __restrict__ ohi,
                        bf16* __restrict__ olo) {
    size_t i = ((size_t)blockIdx.x * 256 + threadIdx.x) * 4;
    float4 v = *(const float4*)(in + i);
    float a[4] = {v.x, v.y, v.z, v.w};
    #pragma unroll
    for (int j = 0; j < 4; j++) {
        bf16 h, lo;
        f2hl(a[j], h, lo);
        ohi[i + j] = h;
        olo[i + j] = lo;
    }
}
__global__ void concat_bias(const float* __restrict__ bq, const float* __restrict__ bk,
                            const float* __restrict__ bv) {
    int t = threadIdx.x, s = blockIdx.x;
    const float* src = (s == 0) ? bq : (s == 1) ? bk : bv;
    g_bqkv[s * DD + t] = src[t];
}
__global__ __launch_bounds__(256) void bff_part(const float* __restrict__ b1,
                                                const float* __restrict__ w2) {
    int y = blockIdx.x, t = threadIdx.x;
    float s[4] = {0.f, 0.f, 0.f, 0.f};
    for (int f = y * 128; f < y * 128 + 128; f++) {
        float bv = b1[f];
        const float* wr = w2 + (size_t)f * DD;
        #pragma unroll
        for (int j = 0; j < 4; j++) s[j] = fmaf(bv, wr[t + j * 256], s[j]);
    }
    #pragma unroll
    for (int j = 0; j < 4; j++) g_bffpart[y * DD + t + j * 256] = s[j];
}
__global__ __launch_bounds__(256) void bff_reduce(const float* __restrict__ b2) {
    int d = blockIdx.x * 256 + threadIdx.x;
    float s = b2[d];
    for (int y = 0; y < 32; y++) s += g_bffpart[y * DD + d];
    g_bff[d] = s;
}

__global__ __launch_bounds__(256, 2) void attn_scores(const float* __restrict__ qkv,
                                                      float* __restrict__ s) {
    __shared__ __align__(16) float Qs[16][132];
    __shared__ __align__(16) float Ks[16][132];
    int h = blockIdx.z, m0 = blockIdx.y * 128, n0 = blockIdx.x * 128;
    int t = threadIdx.x, tx = t & 15, ty = t >> 4;
    float acc[8][8];
    #pragma unroll
    for (int i = 0; i < 8; i++)
        #pragma unroll
        for (int j = 0; j < 8; j++) acc[i][j] = 0.f;

    for (int k0 = 0; k0 < 64; k0 += 16) {
        #pragma unroll
        for (int i = 0; i < 2; i++) {
            int idx = t + i * 256;
            int m = idx >> 2, kg = idx & 3;
            float4 q4 = *(const float4*)(qkv + (size_t)(m0 + m) * (3 * DD) + h * 64 + k0 + kg * 4);
            Qs[kg * 4 + 0][m] = q4.x; Qs[kg * 4 + 1][m] = q4.y;
            Qs[kg * 4 + 2][m] = q4.z; Qs[kg * 4 + 3][m] = q4.w;
            float4 k4 = *(const float4*)(qkv + (size_t)(n0 + m) * (3 * DD) + DD + h * 64 + k0 + kg * 4);
            Ks[kg * 4 + 0][m] = k4.x; Ks[kg * 4 + 1][m] = k4.y;
            Ks[kg * 4 + 2][m] = k4.z; Ks[kg * 4 + 3][m] = k4.w;
        }
        __syncthreads();
        #pragma unroll
        for (int kk = 0; kk < 16; kk++) {
            float a_[8], b_[8];
            *(float4*)&a_[0] = *(const float4*)&Qs[kk][ty * 8];
            *(float4*)&a_[4] = *(const float4*)&Qs[kk][ty * 8 + 4];
            *(float4*)&b_[0] = *(const float4*)&Ks[kk][tx * 8];
            *(float4*)&b_[4] = *(const float4*)&Ks[kk][tx * 8 + 4];
            #pragma unroll
            for (int i = 0; i < 8; i++)
                #pragma unroll
                for (int j = 0; j < 8; j++)
                    acc[i][j] = fmaf(a_[i], b_[j], acc[i][j]);
        }
        __syncthreads();
    }
    #pragma unroll
    for (int i = 0; i < 8; i++) {
        int m = m0 + ty * 8 + i;
        float* row = s + ((size_t)h * LL + m) * LL + n0 + tx * 8;
        #pragma unroll
        for (int j4 = 0; j4 < 2; j4++) {
            float4 o;
            o.x = acc[i][j4 * 4 + 0] * 0.125f;
            o.y = acc[i][j4 * 4 + 1] * 0.125f;
            o.z = acc[i][j4 * 4 + 2] * 0.125f;
            o.w = acc[i][j4 * 4 + 3] * 0.125f;
            *(float4*)(row + j4 * 4) = o;
        }
    }
}

__global__ __launch_bounds__(256) void softmax512(float* __restrict__ s) {
    float* r = s + (size_t)blockIdx.x * LL;
    int t = threadIdx.x;
    float v0 = r[t], v1 = r[t + 256];
    float m = blockMax(fmaxf(v0, v1));
    float e0 = expf(v0 - m), e1 = expf(v1 - m);
    float inv = 1.f / blockSum(e0 + e1);
    r[t] = e0 * inv;
    r[t + 256] = e1 * inv;
}

__global__ __launch_bounds__(256, 2) void attn_pv(const float* __restrict__ p,
                                                  const float* __restrict__ qkv,
                                                  float* __restrict__ opart) {
    __shared__ __align__(16) float Ps[32][132];
    __shared__ __align__(16) float Vs[32][68];
    int h = blockIdx.y, m0 = blockIdx.x * 128, z = blockIdx.z;
    float* outp = opart + (size_t)z * LL * DD;
    int t = threadIdx.x, tx = t & 15, ty = t >> 4;
    float acc[8][4];
    #pragma unroll
    for (int i = 0; i < 8; i++)
        #pragma unroll
        for (int j = 0; j < 4; j++) acc[i][j] = 0.f;

    for (int k0 = z * 256; k0 < z * 256 + 256; k0 += 32) {
        #pragma unroll
        for (int i = 0; i < 4; i++) {
            int idx = t + i * 256;
            int m = idx >> 3, kg = idx & 7;
            float4 v4 = *(const float4*)(p + ((size_t)h * LL + m0 + m) * LL + k0 + kg * 4);
            Ps[kg * 4 + 0][m] = v4.x; Ps[kg * 4 + 1][m] = v4.y;
            Ps[kg * 4 + 2][m] = v4.z; Ps[kg * 4 + 3][m] = v4.w;
        }
        #pragma unroll
        for (int i = 0; i < 2; i++) {
            int idx = t + i * 256;
            int kk = idx >> 4, c = (idx & 15) * 4;
            *(float4*)&Vs[kk][c] =
                *(const float4*)(qkv + (size_t)(k0 + kk) * (3 * DD) + 2 * DD + h * 64 + c);
        }
        __syncthreads();
        #pragma unroll
        for (int kk = 0; kk < 32; kk++) {
            float4 b = *(const float4*)&Vs[kk][tx * 4];
            float a_[8];
            *(float4*)&a_[0] = *(const float4*)&Ps[kk][ty * 8];
            *(float4*)&a_[4] = *(const float4*)&Ps[kk][ty * 8 + 4];
            #pragma unroll
            for (int i = 0; i < 8; i++) {
                acc[i][0] = fmaf(a_[i], b.x, acc[i][0]);
                acc[i][1] = fmaf(a_[i], b.y, acc[i][1]);
                acc[i][2] = fmaf(a_[i], b.z, acc[i][2]);
                acc[i][3] = fmaf(a_[i], b.w, acc[i][3]);
            }
        }
        __syncthreads();
    }
    #pragma unroll
    for (int i = 0; i < 8; i++) {
        int m = m0 + ty * 8 + i;
        *(float4*)(outp + (size_t)m * DD + h * 64 + tx * 4) =
            make_float4(acc[i][0], acc[i][1], acc[i][2], acc[i][3]);
    }
}

__global__ __launch_bounds__(256) void o_combine() {
    int m = blockIdx.x, t = threadIdx.x;
    size_t base = (size_t)m * DD + t * 4;
    float4 a = *(const float4*)(g_opart + base);
    float4 b = *(const float4*)(g_opart + (size_t)LL * DD + base);
    float v[4] = {a.x + b.x, a.y + b.y, a.z + b.z, a.w + b.w};
    #pragma unroll
    for (int j = 0; j < 4; j++) {
        bf16 h, lo;
        f2hl(v[j], h, lo);
        g_ohi[base + j] = h;
        g_olo[base + j] = lo;
    }
}

__global__ __launch_bounds__(256) void add_ln(bf16* __restrict__ xhi, bf16* __restrict__ xlo,
                                              const float* __restrict__ add,
                                              const float* __restrict__ add2,
                                              const float* __restrict__ cbias, int addMask,
                                              const float* __restrict__ g,
                                              const float* __restrict__ b) {
    int row = blockIdx.x, t = threadIdx.x;
    size_t base = (size_t)row * DD + t * 4;
    __nv_bfloat162 h0 = *(const __nv_bfloat162*)(xhi + base);
    __nv_bfloat162 h1 = *(const __nv_bfloat162*)(xhi + base + 2);
    __nv_bfloat162 l0 = *(const __nv_bfloat162*)(xlo + base);
    __nv_bfloat162 l1 = *(const __nv_bfloat162*)(xlo + base + 2);
    size_t aoff = (size_t)(row & addMask) * DD + t * 4;
    float4 av = *(const float4*)(add + aoff);
    if (add2) {
        float4 a2 = *(const float4*)(add2 + aoff);
        av.x += a2.x; av.y += a2.y; av.z += a2.z; av.w += a2.w;
    }
    if (cbias) {
        float4 cb = *(const float4*)(cbias + t * 4);
        av.x += cb.x; av.y += cb.y; av.z += cb.z; av.w += cb.w;
    }
    float v0 = __low2float(h0) + __low2float(l0) + av.x;
    float v1 = __high2float(h0) + __high2float(l0) + av.y;
    float v2 = __low2float(h1) + __low2float(l1) + av.z;
    float v3 = __high2float(h1) + __high2float(l1) + av.w;
    float mean = blockSum(v0 + v1 + v2 + v3) * (1.f / DD);
    float d0 = v0 - mean, d1 = v1 - mean, d2 = v2 - mean, d3 = v3 - mean;
    float var = blockSum(d0 * d0 + d1 * d1 + d2 * d2 + d3 * d3) * (1.f / DD);
    float rs = rsqrtf(var + 1e-5f);
    float4 gv = *(const float4*)(g + t * 4);
    float4 bv = *(const float4*)(b + t * 4);
    float o0 = d0 * rs * gv.x + bv.x, o1 = d1 * rs * gv.y + bv.y;
    float o2 = d2 * rs * gv.z + bv.z, o3 = d3 * rs * gv.w + bv.w;
    bf16 hh, ll;
    f2hl(o0, hh, ll); xhi[base + 0] = hh; xlo[base + 0] = ll;
    f2hl(o1, hh, ll); xhi[base + 1] = hh; xlo[base + 1] = ll;
    f2hl(o2, hh, ll); xhi[base + 2] = hh; xlo[base + 2] = ll;
    f2hl(o3, hh, ll); xhi[base + 3] = hh; xlo[base + 3] = ll;
}

__global__ __launch_bounds__(256) void pool_mean() {
    int b = blockIdx.y;
    int d = blockIdx.x * 256 + threadIdx.x;
    size_t base = (size_t)b * LL * DD + d;
    float s = 0.f;
    for (int l = 0; l < LL; l++)
        s += __bfloat162float(g_xhi[base + (size_t)l * DD]) +
             __bfloat162float(g_xlo[base + (size_t)l * DD]);
    g_pooled[b * DD + d] = s * (1.f / LL);
}
__global__ __launch_bounds__(256) void logits_kernel(const float* __restrict__ wf,
                                                     const float* __restrict__ bf,
                                                     float* __restrict__ out) {
    int b = blockIdx.x / CC, c = blockIdx.x % CC;
    float s = 0.f;
    for (int d = threadIdx.x; d < DD; d += 256)
        s += g_pooled[b * DD + d] * wf[(size_t)d * CC + c];
    s = blockSum(s);
    if (threadIdx.x == 0) out[b * CC + c] = s + bf[c];
}

extern "C" void kernel_launch(void* const* d_in, const int* in_sizes, int n_in,
                              void* d_out, int out_size) {
    const void*  ids = d_in[0];
    const float* emb = (const float*)d_in[1];
    const float* pe  = (const float*)d_in[2];
    const float* wq  = (const float*)d_in[3];
    const float* bq  = (const float*)d_in[4];
    const float* wk  = (const float*)d_in[5];
    const float* bk  = (const float*)d_in[6];
    const float* wv  = (const float*)d_in[7];
    const float* bv  = (const float*)d_in[8];
    const float* wo  = (const float*)d_in[9];
    const float* bo  = (const float*)d_in[10];
    const float* w1  = (const float*)d_in[11];
    const float* b1  = (const float*)d_in[12];
    const float* w2  = (const float*)d_in[13];
    const float* b2  = (const float*)d_in[14];
    const float* g1  = (const float*)d_in[15];
    const float* be1 = (const float*)d_in[16];
    const float* g2  = (const float*)d_in[17];
    const float* be2 = (const float*)d_in[18];
    const float* wf  = (const float*)d_in[19];
    const float* bf  = (const float*)d_in[20];
    float* out = (float*)d_out;

    const int SM128 = (2 * 128 + 256) * PITCH * 2;
    const int SM64  = (2 * 64 + 256) * PITCH * 2;
    cudaFuncSetAttribute(gemm_tc<128>, cudaFuncAttributeMaxDynamicSharedMemorySize, SM128);
    cudaFuncSetAttribute(gemm_tc<64>, cudaFuncAttributeMaxDynamicSharedMemorySize, SM64);

    float *tmp, *qkv, *scores, *src2, *Wff, *bff, *bqkv, *opart;
    bf16 *xhi, *xlo, *ohi, *olo, *wqkvTh, *wqkvTl, *woTh, *woTl, *WffTh, *WffTl, *w1h, *w1l, *w2Th, *w2Tl;
    cudaGetSymbolAddress((void**)&tmp, g_tmp);
    cudaGetSymbolAddress((void**)&qkv, g_qkv);
    cudaGetSymbolAddress((void**)&scores, g_scores);
    cudaGetSymbolAddress((void**)&src2, g_src2);
    cudaGetSymbolAddress((void**)&Wff, g_Wff);
    cudaGetSymbolAddress((void**)&bff, g_bff);
    cudaGetSymbolAddress((void**)&bqkv, g_bqkv);
    cudaGetSymbolAddress((void**)&opart, g_opart);
    cudaGetSymbolAddress((void**)&xhi, g_xhi);
    cudaGetSymbolAddress((void**)&xlo, g_xlo);
    cudaGetSymbolAddress((void**)&ohi, g_ohi);
    cudaGetSymbolAddress((void**)&olo, g_olo);
    cudaGetSymbolAddress((void**)&wqkvTh, g_wqkvT_hi);
    cudaGetSymbolAddress((void**)&wqkvTl, g_wqkvT_lo);
    cudaGetSymbolAddress((void**)&woTh, g_woT_hi);
    cudaGetSymbolAddress((void**)&woTl, g_woT_lo);
    cudaGetSymbolAddress((void**)&WffTh, g_WffT_hi);
    cudaGetSymbolAddress((void**)&WffTl, g_WffT_lo);
    cudaGetSymbolAddress((void**)&w1h, g_w1_hi);
    cudaGetSymbolAddress((void**)&w1l, g_w1_lo);
    cudaGetSymbolAddress((void**)&w2Th, g_w2T_hi);
    cudaGetSymbolAddress((void**)&w2Tl, g_w2T_lo);

    detect_kernel<<<1, 1>>>(ids);
    embed_kernel<<<BB * LL, 256>>>(ids, emb, pe);

    dim3 tb(32, 8);
    tconv<<<dim3(32, 32), tb>>>(wq, nullptr, wqkvTh, wqkvTl, DD, DD, 0);
    tconv<<<dim3(32, 32), tb>>>(wk, nullptr, wqkvTh, wqkvTl, DD, DD, DD);
    tconv<<<dim3(32, 32), tb>>>(wv, nullptr, wqkvTh, wqkvTl, DD, DD, 2 * DD);
    tconv<<<dim3(32, 32), tb>>>(wo, nullptr, woTh, woTl, DD, DD, 0);
    tconv<<<dim3(32, 128), tb>>>(w2, nullptr, w2Th, w2Tl, FF, DD, 0);
    conv_hl<<<(DD * FF) / 1024, 256>>>(w1, w1h, w1l);
    concat_bias<<<3, 1024>>>(bq, bk, bv);
    bff_part<<<32, 256>>>(b1, w2);
    bff_reduce<<<4, 256>>>(b2);
    gemm_tc<64><<<dim3(DD / 128, DD / 64, 2), 128, SM64>>>(w1h, w1l, w2Th, w2Tl, nullptr,
                                                           Wff, FF / 2, FF, DD, DD * DD);
    tconv<<<dim3(32, 32), tb>>>(Wff, Wff + (size_t)DD * DD, WffTh, WffTl, DD, DD, 0);

    for (int layer = 0; layer < NLAYER; layer++) {
        gemm_tc<64><<<dim3(3 * DD / 128, LL / 64, 1), 128, SM64>>>(xhi, xlo, wqkvTh, wqkvTl,
                                                                   bqkv, qkv, DD, DD, 3 * DD, 0);
        attn_scores<<<dim3(4, 4, HH), 256>>>(qkv, scores);
        softmax512<<<HH * LL, 256>>>(scores);
        attn_pv<<<dim3(4, HH, 2), 256>>>(scores, qkv, opart);
        o_combine<<<LL, 256>>>();
        gemm_tc<64><<<dim3(DD / 128, LL / 64, 2), 128, SM64>>>(ohi, olo, woTh, woTl, nullptr,
                                                               src2, DD / 2, DD, DD, LL * DD);
        add_ln<<<BB * LL, 256>>>(xhi, xlo, src2, src2 + (size_t)LL * DD, bo, LL - 1, g1, be1);
        gemm_tc<128><<<dim3(DD / 128, (BB * LL) / 128, 1), 256, SM128>>>(xhi, xlo, WffTh, WffTl,
                                                                         bff, tmp, DD, DD, DD, 0);
        add_ln<<<BB * LL, 256>>>(xhi, xlo, tmp, nullptr, nullptr, BB * LL - 1, g2, be2);
    }

    pool_mean<<<dim3(DD / 256, BB), 256>>>();
    logits_kernel<<<BB * CC, 256>>>(wf, bf, out);
}

// round 6
// speedup vs baseline: 2.6924x; 1.0190x over previous
#include <cuda_runtime.h>
#include <cuda_bf16.h>
#include <cstdint>

#define BB 16
#define LL 512
#define DD 1024
#define HH 16
#define FF 4096
#define CC 10
#define NLAYER 6

typedef __nv_bfloat16 bf16;

__device__ float g_tmp[BB * LL * DD];
__device__ bf16 g_xhi[BB * LL * DD];
__device__ bf16 g_xlo[BB * LL * DD];
__device__ float g_qkv[LL * 3 * DD];
__device__ bf16 g_ohi[LL * DD];
__device__ bf16 g_olo[LL * DD];
__device__ float g_src2[2 * LL * DD];
__device__ float g_Wff[2 * DD * DD];
__device__ float g_bff[DD];
__device__ float g_bffpart[32 * DD];
__device__ float g_bqkv[3 * DD];
__device__ float g_pooled[BB * DD];
__device__ int g_ids64;
__device__ bf16 g_wqkvT_hi[3 * DD * DD], g_wqkvT_lo[3 * DD * DD];
__device__ bf16 g_woT_hi[DD * DD], g_woT_lo[DD * DD];
__device__ bf16 g_WffT_hi[DD * DD], g_WffT_lo[DD * DD];
__device__ bf16 g_w1_hi[DD * FF], g_w1_lo[DD * FF];
__device__ bf16 g_w2T_hi[DD * FF], g_w2T_lo[DD * FF];

__device__ __forceinline__ void f2hl(float v, bf16& h, bf16& l) {
    h = __float2bfloat16(v);
    l = __float2bfloat16(v - __bfloat162float(h));
}
__device__ __forceinline__ float warpSum(float v) {
    #pragma unroll
    for (int o = 16; o > 0; o >>= 1) v += __shfl_xor_sync(0xffffffffu, v, o);
    return v;
}
__device__ __forceinline__ float warpMax(float v) {
    #pragma unroll
    for (int o = 16; o > 0; o >>= 1) v = fmaxf(v, __shfl_xor_sync(0xffffffffu, v, o));
    return v;
}
__device__ __forceinline__ float blockSum(float v) {
    __shared__ float sm[32];
    int lane = threadIdx.x & 31, w = threadIdx.x >> 5;
    v = warpSum(v);
    if (lane == 0) sm[w] = v;
    __syncthreads();
    if (w == 0) {
        float x = (lane < (int)(blockDim.x >> 5)) ? sm[lane] : 0.f;
        x = warpSum(x);
        if (lane == 0) sm[0] = x;
    }
    __syncthreads();
    float r = sm[0];
    __syncthreads();
    return r;
}

__device__ __forceinline__ uint32_t s2u(const void* p) {
    uint32_t a;
    asm("{ .reg .u64 t; cvta.to.shared.u64 t, %1; cvt.u32.u64 %0, t; }" : "=r"(a) : "l"(p));
    return a;
}
__device__ __forceinline__ void cpa(uint32_t dst, const void* src) {
    asm volatile("cp.async.cg.shared.global [%0], [%1], 16;" :: "r"(dst), "l"(src));
}
__device__ __forceinline__ void cpcommit() { asm volatile("cp.async.commit_group;"); }
template <int N> __device__ __forceinline__ void cpwait() {
    asm volatile("cp.async.wait_group %0;" :: "n"(N));
}
__device__ __forceinline__ void ldmx4(uint32_t* r, uint32_t a) {
    asm volatile("ldmatrix.sync.aligned.m8n8.x4.shared.b16 {%0,%1,%2,%3}, [%4];"
                 : "=r"(r[0]), "=r"(r[1]), "=r"(r[2]), "=r"(r[3]) : "r"(a));
}
__device__ __forceinline__ void mmabf(float* d, const uint32_t* a, const uint32_t* b) {
    asm volatile(
        "mma.sync.aligned.m16n8k16.row.col.f32.bf16.bf16.f32 "
        "{%0,%1,%2,%3}, {%4,%5,%6,%7}, {%8,%9}, {%0,%1,%2,%3};"
        : "+f"(d[0]), "+f"(d[1]), "+f"(d[2]), "+f"(d[3])
        : "r"(a[0]), "r"(a[1]), "r"(a[2]), "r"(a[3]), "r"(b[0]), "r"(b[1]));
}

#define PITCH 80

template <int MT>
__global__ __launch_bounds__(MT * 2, (MT == 64) ? 3 : 2) void gemm_tc(
    const bf16* __restrict__ Ahi, const bf16* __restrict__ Alo,
    const bf16* __restrict__ Bhi, const bf16* __restrict__ Blo,
    const float* __restrict__ bias, float* __restrict__ C,
    int Kiter, int Kstride, int N, int Czoff) {
    constexpr int THREADS = MT * 2;
    constexpr int OFS_ALO = MT * PITCH;
    constexpr int OFS_BHI = 2 * MT * PITCH;
    constexpr int OFS_BLO = 2 * MT * PITCH + 128 * PITCH;
    constexpr int STB = (2 * MT + 256) * PITCH;
    extern __shared__ char smem[];
    uint32_t sb = s2u(smem);
    const int t = threadIdx.x, lane = t & 31, wid = t >> 5;
    const int m0 = blockIdx.y * MT, n0 = blockIdx.x * 128;
    const int wr = wid >> 2, wc = wid & 3;
    const size_t kz = (size_t)blockIdx.z * Kiter;
    C += (size_t)blockIdx.z * Czoff;
    const int NKB = Kiter / 32;

    float acc[4][4][4];
    #pragma unroll
    for (int i = 0; i < 4; i++)
        #pragma unroll
        for (int j = 0; j < 4; j++)
            #pragma unroll
            for (int r = 0; r < 4; r++) acc[i][j][r] = 0.f;

    const uint32_t aoff = (uint32_t)((wr * 64 + (lane & 15)) * PITCH + ((lane >> 4) << 4));
    const int brow = wc * 32 + (lane & 7) + ((lane & 16) ? 8 : 0);
    const uint32_t boff = (uint32_t)(brow * PITCH + ((lane & 8) ? 16 : 0));

    auto load_stage = [&](int kb0, uint32_t base) {
        #pragma unroll
        for (int idx = t; idx < MT * 4; idx += THREADS) {
            int row = idx >> 2, c = idx & 3;
            uint32_t so = (uint32_t)(row * PITCH + c * 16);
            size_t ga = (size_t)(m0 + row) * Kstride + kz + kb0 + c * 8;
            cpa(base + so, Ahi + ga);
            cpa(base + OFS_ALO + so, Alo + ga);
        }
        #pragma unroll
        for (int idx = t; idx < 512; idx += THREADS) {
            int row = idx >> 2, c = idx & 3;
            uint32_t so = (uint32_t)(row * PITCH + c * 16);
            size_t gb = (size_t)(n0 + row) * Kstride + kz + kb0 + c * 8;
            cpa(base + OFS_BHI + so, Bhi + gb);
            cpa(base + OFS_BLO + so, Blo + gb);
        }
        cpcommit();
    };

    load_stage(0, sb);

    for (int kb = 0; kb < NKB; kb++) {
        int cur = kb & 1;
        if (kb + 1 < NKB) {
            load_stage((kb + 1) * 32, sb + (uint32_t)(cur ^ 1) * STB);
            cpwait<1>();
        } else {
            cpwait<0>();
        }
        __syncthreads();
        uint32_t base = sb + (uint32_t)cur * STB;
        #pragma unroll
        for (int ks = 0; ks < 2; ks++) {
            uint32_t kbyte = (uint32_t)(ks * 32);
            uint32_t ah[4][4], bh[2][4], bl[2][4];
            #pragma unroll
            for (int mt = 0; mt < 4; mt++)
                ldmx4(ah[mt], base + aoff + (uint32_t)(mt * 16 * PITCH) + kbyte);
            #pragma unroll
            for (int ng = 0; ng < 2; ng++) {
                ldmx4(bh[ng], base + OFS_BHI + boff + (uint32_t)(ng * 16 * PITCH) + kbyte);
                ldmx4(bl[ng], base + OFS_BLO + boff + (uint32_t)(ng * 16 * PITCH) + kbyte);
            }
            #pragma unroll
            for (int mt = 0; mt < 4; mt++)
                #pragma unroll
                for (int nt = 0; nt < 4; nt++) {
                    mmabf(acc[mt][nt], ah[mt], &bh[nt >> 1][(nt & 1) * 2]);
                    mmabf(acc[mt][nt], ah[mt], &bl[nt >> 1][(nt & 1) * 2]);
                }
            #pragma unroll
            for (int mt = 0; mt < 4; mt++) {
                uint32_t al[4];
                ldmx4(al, base + OFS_ALO + aoff + (uint32_t)(mt * 16 * PITCH) + kbyte);
                #pragma unroll
                for (int nt = 0; nt < 4; nt++)
                    mmabf(acc[mt][nt], al, &bh[nt >> 1][(nt & 1) * 2]);
            }
        }
        __syncthreads();
    }

    #pragma unroll
    for (int mt = 0; mt < 4; mt++) {
        int m = m0 + wr * 64 + mt * 16 + (lane >> 2);
        #pragma unroll
        for (int nt = 0; nt < 4; nt++) {
            int n = n0 + wc * 32 + nt * 8 + (lane & 3) * 2;
            float b0 = 0.f, b1 = 0.f;
            if (bias) { b0 = bias[n]; b1 = bias[n + 1]; }
            *(float2*)(C + (size_t)m * N + n) = make_float2(acc[mt][nt][0] + b0, acc[mt][nt][1] + b1);
            *(float2*)(C + (size_t)(m + 8) * N + n) = make_float2(acc[mt][nt][2] + b0, acc[mt][nt][3] + b1);
        }
    }
}

__global__ void detect_kernel(const void* ids) {
    const int* p = (const int*)ids;
    int nz = 0;
    for (int i = 0; i < 256; i += 2)
        if (p[i + 1] != 0) nz++;
    g_ids64 = (nz == 0) ? 1 : 0;
}
__global__ void embed_kernel(const void* ids, const float* __restrict__ emb,
                             const float* __restrict__ pe) {
    int row = blockIdx.x;
    int d = threadIdx.x * 4;
    long long id;
    if (g_ids64) id = ((const long long*)ids)[row];
    else         id = (long long)((const int*)ids)[row];
    int l = row & (LL - 1);
    float4 e = *(const float4*)(emb + (size_t)id * DD + d);
    float4 p = *(const float4*)(pe + (size_t)l * DD + d);
    float v[4] = {e.x * 32.f + p.x, e.y * 32.f + p.y, e.z * 32.f + p.z, e.w * 32.f + p.w};
    size_t base = (size_t)row * DD + d;
    #pragma unroll
    for (int j = 0; j < 4; j++) {
        bf16 h, lo;
        f2hl(v[j], h, lo);
        g_xhi[base + j] = h;
        g_xlo[base + j] = lo;
    }
}
__global__ void tconv(const float* __restrict__ in, const float* __restrict__ in2,
                      bf16* __restrict__ ohi, bf16* __restrict__ olo, int R, int C, int nOff) {
    __shared__ float tl[32][33];
    int n0 = blockIdx.x * 32, k0 = blockIdx.y * 32;
    int tx = threadIdx.x, ty = threadIdx.y;
    #pragma unroll
    for (int i = 0; i < 4; i++) {
        size_t idx = (size_t)(k0 + ty + i * 8) * C + n0 + tx;
        float v = in[idx];
        if (in2) v += in2[idx];
        tl[ty + i * 8][tx] = v;
    }
    __syncthreads();
    #pragma unroll
    for (int i = 0; i < 4; i++) {
        int nn = ty + i * 8;
        bf16 h, lo;
        f2hl(tl[tx][nn], h, lo);
        size_t o = (size_t)(nOff + n0 + nn) * R + k0 + tx;
        ohi[o] = h;
        olo[o] = lo;
    }
}
__global__ void conv_hl(const float* __restrict__ in, bf16* __restrict__ ohi,
                        bf16* __restrict__ olo) {
    size_t i = ((size_t)blockIdx.x * 256 + threadIdx.x) * 4;
    float4 v = *(const float4*)(in + i);
    float a[4] = {v.x, v.y, v.z, v.w};
    #pragma unroll
    for (int j = 0; j < 4; j++) {
        bf16 h, lo;
        f2hl(a[j], h, lo);
        ohi[i + j] = h;
        olo[i + j] = lo;
    }
}
__global__ void concat_bias(const float* __restrict__ bq, const float* __restrict__ bk,
                            const float* __restrict__ bv) {
    int t = threadIdx.x, s = blockIdx.x;
    const float* src = (s == 0) ? bq : (s == 1) ? bk : bv;
    g_bqkv[s * DD + t] = src[t];
}
__global__ __launch_bounds__(256) void bff_part(const float* __restrict__ b1,
                                                const float* __restrict__ w2) {
    int y = blockIdx.x, t = threadIdx.x;
    float s[4] = {0.f, 0.f, 0.f, 0.f};
    for (int f = y * 128; f < y * 128 + 128; f++) {
        float bv = b1[f];
        const float* wr = w2 + (size_t)f * DD;
        #pragma unroll
        for (int j = 0; j < 4; j++) s[j] = fmaf(bv, wr[t + j * 256], s[j]);
    }
    #pragma unroll
    for (int j = 0; j < 4; j++) g_bffpart[y * DD + t + j * 256] = s[j];
}
__global__ __launch_bounds__(256) void bff_reduce(const float* __restrict__ b2) {
    int d = blockIdx.x * 256 + threadIdx.x;
    float s = b2[d];
    for (int y = 0; y < 32; y++) s += g_bffpart[y * DD + d];
    g_bff[d] = s;
}

// ---------------- flash-fused attention (batch 0): S -> online softmax -> PV ----------------
// grid (8 m-tiles of 64, 16 heads), 256 threads (16x16), 4x4 microtiles.
__global__ __launch_bounds__(256, 2) void flash_attn(const float* __restrict__ qkv) {
    extern __shared__ float fs[];
    float (*Qs)[68] = (float(*)[68])fs;               // [dk][m]
    float (*Ks)[68] = (float(*)[68])(fs + 64 * 68);   // [dk][key]
    float (*Vs)[68] = (float(*)[68])(fs + 2 * 64 * 68); // [key][dk]
    float (*Ps)[68] = (float(*)[68])(fs + 3 * 64 * 68); // [key][m]
    int h = blockIdx.y, m0 = blockIdx.x * 64;
    int t = threadIdx.x, tx = t & 15, ty = t >> 4;

    #pragma unroll
    for (int i = 0; i < 4; i++) {
        int idx = t + i * 256;
        int m = idx >> 4, kg = (idx & 15) * 4;
        float4 q4 = *(const float4*)(qkv + (size_t)(m0 + m) * (3 * DD) + h * 64 + kg);
        Qs[kg + 0][m] = q4.x; Qs[kg + 1][m] = q4.y;
        Qs[kg + 2][m] = q4.z; Qs[kg + 3][m] = q4.w;
    }

    float m_run[4], l_run[4], oa[4][4];
    #pragma unroll
    for (int i = 0; i < 4; i++) {
        m_run[i] = -1e30f; l_run[i] = 0.f;
        #pragma unroll
        for (int j = 0; j < 4; j++) oa[i][j] = 0.f;
    }

    for (int kb = 0; kb < LL; kb += 64) {
        __syncthreads();
        #pragma unroll
        for (int i = 0; i < 4; i++) {
            int idx = t + i * 256;
            int n = idx >> 4, kg = (idx & 15) * 4;
            float4 k4 = *(const float4*)(qkv + (size_t)(kb + n) * (3 * DD) + DD + h * 64 + kg);
            Ks[kg + 0][n] = k4.x; Ks[kg + 1][n] = k4.y;
            Ks[kg + 2][n] = k4.z; Ks[kg + 3][n] = k4.w;
            *(float4*)&Vs[n][kg] =
                *(const float4*)(qkv + (size_t)(kb + n) * (3 * DD) + 2 * DD + h * 64 + kg);
        }
        __syncthreads();

        float s[4][4];
        #pragma unroll
        for (int i = 0; i < 4; i++)
            #pragma unroll
            for (int j = 0; j < 4; j++) s[i][j] = 0.f;
        #pragma unroll 8
        for (int k = 0; k < 64; k++) {
            float4 a = *(const float4*)&Qs[k][ty * 4];
            float4 b = *(const float4*)&Ks[k][tx * 4];
            float av[4] = {a.x, a.y, a.z, a.w}, bv[4] = {b.x, b.y, b.z, b.w};
            #pragma unroll
            for (int i = 0; i < 4; i++)
                #pragma unroll
                for (int j = 0; j < 4; j++)
                    s[i][j] = fmaf(av[i], bv[j], s[i][j]);
        }

        #pragma unroll
        for (int i = 0; i < 4; i++) {
            float rm = fmaxf(fmaxf(s[i][0], s[i][1]), fmaxf(s[i][2], s[i][3])) * 0.125f;
            #pragma unroll
            for (int o = 8; o > 0; o >>= 1)
                rm = fmaxf(rm, __shfl_xor_sync(0xffffffffu, rm, o));
            float mn = fmaxf(m_run[i], rm);
            float corr = __expf(m_run[i] - mn);
            float p[4], rs = 0.f;
            #pragma unroll
            for (int j = 0; j < 4; j++) {
                p[j] = __expf(s[i][j] * 0.125f - mn);
                rs += p[j];
            }
            #pragma unroll
            for (int o = 8; o > 0; o >>= 1)
                rs += __shfl_xor_sync(0xffffffffu, rs, o);
            l_run[i] = l_run[i] * corr + rs;
            m_run[i] = mn;
            #pragma unroll
            for (int j = 0; j < 4; j++) {
                oa[i][j] *= corr;
                Ps[tx * 4 + j][ty * 4 + i] = p[j];
            }
        }
        __syncthreads();

        #pragma unroll 8
        for (int k = 0; k < 64; k++) {
            float4 a = *(const float4*)&Ps[k][ty * 4];
            float4 b = *(const float4*)&Vs[k][tx * 4];
            float av[4] = {a.x, a.y, a.z, a.w}, bv[4] = {b.x, b.y, b.z, b.w};
            #pragma unroll
            for (int i = 0; i < 4; i++)
                #pragma unroll
                for (int j = 0; j < 4; j++)
                    oa[i][j] = fmaf(av[i], bv[j], oa[i][j]);
        }
    }

    #pragma unroll
    for (int i = 0; i < 4; i++) {
        float inv = 1.f / l_run[i];
        int m = m0 + ty * 4 + i;
        size_t base = (size_t)m * DD + h * 64 + tx * 4;
        #pragma unroll
        for (int j = 0; j < 4; j++) {
            bf16 hh, lo;
            f2hl(oa[i][j] * inv, hh, lo);
            g_ohi[base + j] = hh;
            g_olo[base + j] = lo;
        }
    }
}

__global__ __launch_bounds__(256) void add_ln(bf16* __restrict__ xhi, bf16* __restrict__ xlo,
                                              const float* __restrict__ add,
                                              const float* __restrict__ add2,
                                              const float* __restrict__ cbias, int addMask,
                                              const float* __restrict__ g,
                                              const float* __restrict__ b) {
    int row = blockIdx.x, t = threadIdx.x;
    size_t base = (size_t)row * DD + t * 4;
    __nv_bfloat162 h0 = *(const __nv_bfloat162*)(xhi + base);
    __nv_bfloat162 h1 = *(const __nv_bfloat162*)(xhi + base + 2);
    __nv_bfloat162 l0 = *(const __nv_bfloat162*)(xlo + base);
    __nv_bfloat162 l1 = *(const __nv_bfloat162*)(xlo + base + 2);
    size_t aoff = (size_t)(row & addMask) * DD + t * 4;
    float4 av = *(const float4*)(add + aoff);
    if (add2) {
        float4 a2 = *(const float4*)(add2 + aoff);
        av.x += a2.x; av.y += a2.y; av.z += a2.z; av.w += a2.w;
    }
    if (cbias) {
        float4 cb = *(const float4*)(cbias + t * 4);
        av.x += cb.x; av.y += cb.y; av.z += cb.z; av.w += cb.w;
    }
    float v0 = __low2float(h0) + __low2float(l0) + av.x;
    float v1 = __high2float(h0) + __high2float(l0) + av.y;
    float v2 = __low2float(h1) + __low2float(l1) + av.z;
    float v3 = __high2float(h1) + __high2float(l1) + av.w;
    float mean = blockSum(v0 + v1 + v2 + v3) * (1.f / DD);
    float d0 = v0 - mean, d1 = v1 - mean, d2 = v2 - mean, d3 = v3 - mean;
    float var = blockSum(d0 * d0 + d1 * d1 + d2 * d2 + d3 * d3) * (1.f / DD);
    float rs = rsqrtf(var + 1e-5f);
    float4 gv = *(const float4*)(g + t * 4);
    float4 bv = *(const float4*)(b + t * 4);
    float o0 = d0 * rs * gv.x + bv.x, o1 = d1 * rs * gv.y + bv.y;
    float o2 = d2 * rs * gv.z + bv.z, o3 = d3 * rs * gv.w + bv.w;
    bf16 hh, ll;
    f2hl(o0, hh, ll); xhi[base + 0] = hh; xlo[base + 0] = ll;
    f2hl(o1, hh, ll); xhi[base + 1] = hh; xlo[base + 1] = ll;
    f2hl(o2, hh, ll); xhi[base + 2] = hh; xlo[base + 2] = ll;
    f2hl(o3, hh, ll); xhi[base + 3] = hh; xlo[base + 3] = ll;
}

__global__ __launch_bounds__(256) void pool_mean() {
    int b = blockIdx.y;
    int d = blockIdx.x * 256 + threadIdx.x;
    size_t base = (size_t)b * LL * DD + d;
    float s = 0.f;
    for (int l = 0; l < LL; l++)
        s += __bfloat162float(g_xhi[base + (size_t)l * DD]) +
             __bfloat162float(g_xlo[base + (size_t)l * DD]);
    g_pooled[b * DD + d] = s * (1.f / LL);
}
__global__ __launch_bounds__(256) void logits_kernel(const float* __restrict__ wf,
                                                     const float* __restrict__ bf,
                                                     float* __restrict__ out) {
    int b = blockIdx.x / CC, c = blockIdx.x % CC;
    float s = 0.f;
    for (int d = threadIdx.x; d < DD; d += 256)
        s += g_pooled[b * DD + d] * wf[(size_t)d * CC + c];
    s = blockSum(s);
    if (threadIdx.x == 0) out[b * CC + c] = s + bf[c];
}

extern "C" void kernel_launch(void* const* d_in, const int* in_sizes, int n_in,
                              void* d_out, int out_size) {
    const void*  ids = d_in[0];
    const float* emb = (const float*)d_in[1];
    const float* pe  = (const float*)d_in[2];
    const float* wq  = (const float*)d_in[3];
    const float* bq  = (const float*)d_in[4];
    const float* wk  = (const float*)d_in[5];
    const float* bk  = (const float*)d_in[6];
    const float* wv  = (const float*)d_in[7];
    const float* bv  = (const float*)d_in[8];
    const float* wo  = (const float*)d_in[9];
    const float* bo  = (const float*)d_in[10];
    const float* w1  = (const float*)d_in[11];
    const float* b1  = (const float*)d_in[12];
    const float* w2  = (const float*)d_in[13];
    const float* b2  = (const float*)d_in[14];
    const float* g1  = (const float*)d_in[15];
    const float* be1 = (const float*)d_in[16];
    const float* g2  = (const float*)d_in[17];
    const float* be2 = (const float*)d_in[18];
    const float* wf  = (const float*)d_in[19];
    const float* bf  = (const float*)d_in[20];
    float* out = (float*)d_out;

    const int SM128 = (2 * 128 + 256) * PITCH * 2;
    const int SM64  = (2 * 64 + 256) * PITCH * 2;
    const int SMFA  = 4 * 64 * 68 * 4;
    cudaFuncSetAttribute(gemm_tc<128>, cudaFuncAttributeMaxDynamicSharedMemorySize, SM128);
    cudaFuncSetAttribute(gemm_tc<64>, cudaFuncAttributeMaxDynamicSharedMemorySize, SM64);
    cudaFuncSetAttribute(flash_attn, cudaFuncAttributeMaxDynamicSharedMemorySize, SMFA);

    float *tmp, *qkv, *src2, *Wff, *bff, *bqkv;
    bf16 *xhi, *xlo, *ohi, *olo, *wqkvTh, *wqkvTl, *woTh, *woTl, *WffTh, *WffTl, *w1h, *w1l, *w2Th, *w2Tl;
    cudaGetSymbolAddress((void**)&tmp, g_tmp);
    cudaGetSymbolAddress((void**)&qkv, g_qkv);
    cudaGetSymbolAddress((void**)&src2, g_src2);
    cudaGetSymbolAddress((void**)&Wff, g_Wff);
    cudaGetSymbolAddress((void**)&bff, g_bff);
    cudaGetSymbolAddress((void**)&bqkv, g_bqkv);
    cudaGetSymbolAddress((void**)&xhi, g_xhi);
    cudaGetSymbolAddress((void**)&xlo, g_xlo);
    cudaGetSymbolAddress((void**)&ohi, g_ohi);
    cudaGetSymbolAddress((void**)&olo, g_olo);
    cudaGetSymbolAddress((void**)&wqkvTh, g_wqkvT_hi);
    cudaGetSymbolAddress((void**)&wqkvTl, g_wqkvT_lo);
    cudaGetSymbolAddress((void**)&woTh, g_woT_hi);
    cudaGetSymbolAddress((void**)&woTl, g_woT_lo);
    cudaGetSymbolAddress((void**)&WffTh, g_WffT_hi);
    cudaGetSymbolAddress((void**)&WffTl, g_WffT_lo);
    cudaGetSymbolAddress((void**)&w1h, g_w1_hi);
    cudaGetSymbolAddress((void**)&w1l, g_w1_lo);
    cudaGetSymbolAddress((void**)&w2Th, g_w2T_hi);
    cudaGetSymbolAddress((void**)&w2Tl, g_w2T_lo);

    detect_kernel<<<1, 1>>>(ids);
    embed_kernel<<<BB * LL, 256>>>(ids, emb, pe);

    dim3 tb(32, 8);
    tconv<<<dim3(32, 32), tb>>>(wq, nullptr, wqkvTh, wqkvTl, DD, DD, 0);
    tconv<<<dim3(32, 32), tb>>>(wk, nullptr, wqkvTh, wqkvTl, DD, DD, DD);
    tconv<<<dim3(32, 32), tb>>>(wv, nullptr, wqkvTh, wqkvTl, DD, DD, 2 * DD);
    tconv<<<dim3(32, 32), tb>>>(wo, nullptr, woTh, woTl, DD, DD, 0);
    tconv<<<dim3(32, 128), tb>>>(w2, nullptr, w2Th, w2Tl, FF, DD, 0);
    conv_hl<<<(DD * FF) / 1024, 256>>>(w1, w1h, w1l);
    concat_bias<<<3, 1024>>>(bq, bk, bv);
    bff_part<<<32, 256>>>(b1, w2);
    bff_reduce<<<4, 256>>>(b2);
    gemm_tc<64><<<dim3(DD / 128, DD / 64, 2), 128, SM64>>>(w1h, w1l, w2Th, w2Tl, nullptr,
                                                           Wff, FF / 2, FF, DD, DD * DD);
    tconv<<<dim3(32, 32), tb>>>(Wff, Wff + (size_t)DD * DD, WffTh, WffTl, DD, DD, 0);

    for (int layer = 0; layer < NLAYER; layer++) {
        gemm_tc<64><<<dim3(3 * DD / 128, LL / 64, 1), 128, SM64>>>(xhi, xlo, wqkvTh, wqkvTl,
                                                                   bqkv, qkv, DD, DD, 3 * DD, 0);
        flash_attn<<<dim3(8, HH), 256, SMFA>>>(qkv);
        gemm_tc<64><<<dim3(DD / 128, LL / 64, 2), 128, SM64>>>(ohi, olo, woTh, woTl, nullptr,
                                                               src2, DD / 2, DD, DD, LL * DD);
        add_ln<<<BB * LL, 256>>>(xhi, xlo, src2, src2 + (size_t)LL * DD, bo, LL - 1, g1, be1);
        gemm_tc<128><<<dim3(DD / 128, (BB * LL) / 128, 1), 256, SM128>>>(xhi, xlo, WffTh, WffTl,
                                                                         bff, tmp, DD, DD, DD, 0);
        add_ln<<<BB * LL, 256>>>(xhi, xlo, tmp, nullptr, nullptr, BB * LL - 1, g2, be2);
    }

    pool_mean<<<dim3(DD / 256, BB), 256>>>();
    logits_kernel<<<BB * CC, 256>>>(wf, bf, out);
}

// round 7
// speedup vs baseline: 3.3958x; 1.2612x over previous
#include <cuda_runtime.h>
#include <cuda_bf16.h>
#include <cuda_fp16.h>
#include <cstdint>

#define BB 16
#define LL 512
#define DD 1024
#define HH 16
#define FF 4096
#define CC 10
#define NLAYER 6

typedef __half f16;

__device__ float g_tmp[BB * LL * DD];
__device__ f16 g_xhi[BB * LL * DD];
__device__ f16 g_xlo[BB * LL * DD];
__device__ float g_qkv[LL * 3 * DD];
__device__ f16 g_ohi[LL * DD];
__device__ float g_src2[2 * LL * DD];
__device__ float g_Wff[2 * DD * DD];
__device__ float g_bff[DD];
__device__ float g_bffpart[32 * DD];
__device__ float g_bqkv[3 * DD];
__device__ float g_pooled[BB * DD];
__device__ int g_ids64;
__device__ f16 g_wqkvT_hi[3 * DD * DD], g_wqkvT_lo[3 * DD * DD];
__device__ f16 g_woT_hi[DD * DD], g_woT_lo[DD * DD];
__device__ f16 g_WffT_hi[DD * DD], g_WffT_lo[DD * DD];
__device__ f16 g_w1_hi[DD * FF];
__device__ f16 g_w2T_hi[DD * FF], g_w2T_lo[DD * FF];

__device__ __forceinline__ void f2hl(float v, f16& h, f16& l) {
    h = __float2half(v);
    l = __float2half(v - __half2float(h));
}
__device__ __forceinline__ float warpSum(float v) {
    #pragma unroll
    for (int o = 16; o > 0; o >>= 1) v += __shfl_xor_sync(0xffffffffu, v, o);
    return v;
}
__device__ __forceinline__ float blockSum(float v) {
    __shared__ float sm[32];
    int lane = threadIdx.x & 31, w = threadIdx.x >> 5;
    v = warpSum(v);
    if (lane == 0) sm[w] = v;
    __syncthreads();
    if (w == 0) {
        float x = (lane < (int)(blockDim.x >> 5)) ? sm[lane] : 0.f;
        x = warpSum(x);
        if (lane == 0) sm[0] = x;
    }
    __syncthreads();
    float r = sm[0];
    __syncthreads();
    return r;
}

__device__ __forceinline__ uint32_t s2u(const void* p) {
    uint32_t a;
    asm("{ .reg .u64 t; cvta.to.shared.u64 t, %1; cvt.u32.u64 %0, t; }" : "=r"(a) : "l"(p));
    return a;
}
__device__ __forceinline__ void cpa(uint32_t dst, const void* src) {
    asm volatile("cp.async.cg.shared.global [%0], [%1], 16;" :: "r"(dst), "l"(src));
}
__device__ __forceinline__ void cpcommit() { asm volatile("cp.async.commit_group;"); }
template <int N> __device__ __forceinline__ void cpwait() {
    asm volatile("cp.async.wait_group %0;" :: "n"(N));
}
__device__ __forceinline__ void ldmx4(uint32_t* r, uint32_t a) {
    asm volatile("ldmatrix.sync.aligned.m8n8.x4.shared.b16 {%0,%1,%2,%3}, [%4];"
                 : "=r"(r[0]), "=r"(r[1]), "=r"(r[2]), "=r"(r[3]) : "r"(a));
}
__device__ __forceinline__ void mmah(float* d, const uint32_t* a, const uint32_t* b) {
    asm volatile(
        "mma.sync.aligned.m16n8k16.row.col.f32.f16.f16.f32 "
        "{%0,%1,%2,%3}, {%4,%5,%6,%7}, {%8,%9}, {%0,%1,%2,%3};"
        : "+f"(d[0]), "+f"(d[1]), "+f"(d[2]), "+f"(d[3])
        : "r"(a[0]), "r"(a[1]), "r"(a[2]), "r"(a[3]), "r"(b[0]), "r"(b[1]));
}

#define PITCH 80

// C[M,N] = A @ (Bhi+Blo)^T + bias ; A single fp16, B split fp16 (2 MMAs per step).
template <int MT>
__global__ __launch_bounds__(MT * 2, (MT == 64) ? 3 : 2) void gemm_tc(
    const f16* __restrict__ A,
    const f16* __restrict__ Bhi, const f16* __restrict__ Blo,
    const float* __restrict__ bias, float* __restrict__ C,
    int Kiter, int Kstride, int N, int Czoff) {
    constexpr int THREADS = MT * 2;
    constexpr int OFS_BHI = MT * PITCH;
    constexpr int OFS_BLO = MT * PITCH + 128 * PITCH;
    constexpr int STB = (MT + 256) * PITCH;
    extern __shared__ char smem[];
    uint32_t sb = s2u(smem);
    const int t = threadIdx.x, lane = t & 31, wid = t >> 5;
    const int m0 = blockIdx.y * MT, n0 = blockIdx.x * 128;
    const int wr = wid >> 2, wc = wid & 3;
    const size_t kz = (size_t)blockIdx.z * Kiter;
    C += (size_t)blockIdx.z * Czoff;
    const int NKB = Kiter / 32;

    float acc[4][4][4];
    #pragma unroll
    for (int i = 0; i < 4; i++)
        #pragma unroll
        for (int j = 0; j < 4; j++)
            #pragma unroll
            for (int r = 0; r < 4; r++) acc[i][j][r] = 0.f;

    const uint32_t aoff = (uint32_t)((wr * 64 + (lane & 15)) * PITCH + ((lane >> 4) << 4));
    const int brow = wc * 32 + (lane & 7) + ((lane & 16) ? 8 : 0);
    const uint32_t boff = (uint32_t)(brow * PITCH + ((lane & 8) ? 16 : 0));

    auto load_stage = [&](int kb0, uint32_t base) {
        #pragma unroll
        for (int idx = t; idx < MT * 4; idx += THREADS) {
            int row = idx >> 2, c = idx & 3;
            uint32_t so = (uint32_t)(row * PITCH + c * 16);
            cpa(base + so, A + (size_t)(m0 + row) * Kstride + kz + kb0 + c * 8);
        }
        #pragma unroll
        for (int idx = t; idx < 512; idx += THREADS) {
            int row = idx >> 2, c = idx & 3;
            uint32_t so = (uint32_t)(row * PITCH + c * 16);
            size_t gb = (size_t)(n0 + row) * Kstride + kz + kb0 + c * 8;
            cpa(base + OFS_BHI + so, Bhi + gb);
            cpa(base + OFS_BLO + so, Blo + gb);
        }
        cpcommit();
    };

    load_stage(0, sb);

    for (int kb = 0; kb < NKB; kb++) {
        int cur = kb & 1;
        if (kb + 1 < NKB) {
            load_stage((kb + 1) * 32, sb + (uint32_t)(cur ^ 1) * STB);
            cpwait<1>();
        } else {
            cpwait<0>();
        }
        __syncthreads();
        uint32_t base = sb + (uint32_t)cur * STB;
        #pragma unroll
        for (int ks = 0; ks < 2; ks++) {
            uint32_t kbyte = (uint32_t)(ks * 32);
            uint32_t ah[4][4], bh[2][4], bl[2][4];
            #pragma unroll
            for (int mt = 0; mt < 4; mt++)
                ldmx4(ah[mt], base + aoff + (uint32_t)(mt * 16 * PITCH) + kbyte);
            #pragma unroll
            for (int ng = 0; ng < 2; ng++) {
                ldmx4(bh[ng], base + OFS_BHI + boff + (uint32_t)(ng * 16 * PITCH) + kbyte);
                ldmx4(bl[ng], base + OFS_BLO + boff + (uint32_t)(ng * 16 * PITCH) + kbyte);
            }
            #pragma unroll
            for (int mt = 0; mt < 4; mt++)
                #pragma unroll
                for (int nt = 0; nt < 4; nt++) {
                    mmah(acc[mt][nt], ah[mt], &bh[nt >> 1][(nt & 1) * 2]);
                    mmah(acc[mt][nt], ah[mt], &bl[nt >> 1][(nt & 1) * 2]);
                }
        }
        __syncthreads();
    }

    #pragma unroll
    for (int mt = 0; mt < 4; mt++) {
        int m = m0 + wr * 64 + mt * 16 + (lane >> 2);
        #pragma unroll
        for (int nt = 0; nt < 4; nt++) {
            int n = n0 + wc * 32 + nt * 8 + (lane & 3) * 2;
            float b0 = 0.f, b1 = 0.f;
            if (bias) { b0 = bias[n]; b1 = bias[n + 1]; }
            *(float2*)(C + (size_t)m * N + n) = make_float2(acc[mt][nt][0] + b0, acc[mt][nt][1] + b1);
            *(float2*)(C + (size_t)(m + 8) * N + n) = make_float2(acc[mt][nt][2] + b0, acc[mt][nt][3] + b1);
        }
    }
}

__global__ void detect_kernel(const void* ids) {
    const int* p = (const int*)ids;
    int nz = 0;
    for (int i = 0; i < 256; i += 2)
        if (p[i + 1] != 0) nz++;
    g_ids64 = (nz == 0) ? 1 : 0;
}
__global__ void embed_kernel(const void* ids, const float* __restrict__ emb,
                             const float* __restrict__ pe) {
    int row = blockIdx.x;
    int d = threadIdx.x * 4;
    long long id;
    if (g_ids64) id = ((const long long*)ids)[row];
    else         id = (long long)((const int*)ids)[row];
    int l = row & (LL - 1);
    float4 e = *(const float4*)(emb + (size_t)id * DD + d);
    float4 p = *(const float4*)(pe + (size_t)l * DD + d);
    float v[4] = {e.x * 32.f + p.x, e.y * 32.f + p.y, e.z * 32.f + p.z, e.w * 32.f + p.w};
    size_t base = (size_t)row * DD + d;
    #pragma unroll
    for (int j = 0; j < 4; j++) {
        f16 h, lo;
        f2hl(v[j], h, lo);
        g_xhi[base + j] = h;
        g_xlo[base + j] = lo;
    }
}
// transpose+convert (optional sum of two inputs): out[(nOff+c)*R + r] hi/lo fp16
__global__ void tconv(const float* __restrict__ in, const float* __restrict__ in2,
                      f16* __restrict__ ohi, f16* __restrict__ olo, int R, int C, int nOff) {
    __shared__ float tl[32][33];
    int n0 = blockIdx.x * 32, k0 = blockIdx.y * 32;
    int tx = threadIdx.x, ty = threadIdx.y;
    #pragma unroll
    for (int i = 0; i < 4; i++) {
        size_t idx = (size_t)(k0 + ty + i * 8) * C + n0 + tx;
        float v = in[idx];
        if (in2) v += in2[idx];
        tl[ty + i * 8][tx] = v;
    }
    __syncthreads();
    #pragma unroll
    for (int i = 0; i < 4; i++) {
        int nn = ty + i * 8;
        f16 h, lo;
        f2hl(tl[tx][nn], h, lo);
        size_t o = (size_t)(nOff + n0 + nn) * R + k0 + tx;
        ohi[o] = h;
        if (olo) olo[o] = lo;
    }
}
__global__ void conv_h(const float* __restrict__ in, f16* __restrict__ ohi) {
    size_t i = ((size_t)blockIdx.x * 256 + threadIdx.x) * 4;
    float4 v = *(const float4*)(in + i);
    ohi[i + 0] = __float2half(v.x);
    ohi[i + 1] = __float2half(v.y);
    ohi[i + 2] = __float2half(v.z);
    ohi[i + 3] = __float2half(v.w);
}
__global__ void concat_bias(const float* __restrict__ bq, const float* __restrict__ bk,
                            const float* __restrict__ bv) {
    int t = threadIdx.x, s = blockIdx.x;
    const float* src = (s == 0) ? bq : (s == 1) ? bk : bv;
    g_bqkv[s * DD + t] = src[t];
}
__global__ __launch_bounds__(256) void bff_part(const float* __restrict__ b1,
                                                const float* __restrict__ w2) {
    int y = blockIdx.x, t = threadIdx.x;
    float s[4] = {0.f, 0.f, 0.f, 0.f};
    for (int f = y * 128; f < y * 128 + 128; f++) {
        float bv = b1[f];
        const float* wr = w2 + (size_t)f * DD;
        #pragma unroll
        for (int j = 0; j < 4; j++) s[j] = fmaf(bv, wr[t + j * 256], s[j]);
    }
    #pragma unroll
    for (int j = 0; j < 4; j++) g_bffpart[y * DD + t + j * 256] = s[j];
}
__global__ __launch_bounds__(256) void bff_reduce(const float* __restrict__ b2) {
    int d = blockIdx.x * 256 + threadIdx.x;
    float s = b2[d];
    for (int y = 0; y < 32; y++) s += g_bffpart[y * DD + d];
    g_bff[d] = s;
}

// flash-fused attention (batch 0): grid (8 m-tiles, 16 heads), 256 thr, 4x4 microtiles
__global__ __launch_bounds__(256, 2) void flash_attn(const float* __restrict__ qkv) {
    extern __shared__ float fs[];
    float (*Qs)[68] = (float(*)[68])fs;
    float (*Ks)[68] = (float(*)[68])(fs + 64 * 68);
    float (*Vs)[68] = (float(*)[68])(fs + 2 * 64 * 68);
    float (*Ps)[68] = (float(*)[68])(fs + 3 * 64 * 68);
    int h = blockIdx.y, m0 = blockIdx.x * 64;
    int t = threadIdx.x, tx = t & 15, ty = t >> 4;

    #pragma unroll
    for (int i = 0; i < 4; i++) {
        int idx = t + i * 256;
        int m = idx >> 4, kg = (idx & 15) * 4;
        float4 q4 = *(const float4*)(qkv + (size_t)(m0 + m) * (3 * DD) + h * 64 + kg);
        Qs[kg + 0][m] = q4.x; Qs[kg + 1][m] = q4.y;
        Qs[kg + 2][m] = q4.z; Qs[kg + 3][m] = q4.w;
    }

    float m_run[4], l_run[4], oa[4][4];
    #pragma unroll
    for (int i = 0; i < 4; i++) {
        m_run[i] = -1e30f; l_run[i] = 0.f;
        #pragma unroll
        for (int j = 0; j < 4; j++) oa[i][j] = 0.f;
    }

    for (int kb = 0; kb < LL; kb += 64) {
        __syncthreads();
        #pragma unroll
        for (int i = 0; i < 4; i++) {
            int idx = t + i * 256;
            int n = idx >> 4, kg = (idx & 15) * 4;
            float4 k4 = *(const float4*)(qkv + (size_t)(kb + n) * (3 * DD) + DD + h * 64 + kg);
            Ks[kg + 0][n] = k4.x; Ks[kg + 1][n] = k4.y;
            Ks[kg + 2][n] = k4.z; Ks[kg + 3][n] = k4.w;
            *(float4*)&Vs[n][kg] =
                *(const float4*)(qkv + (size_t)(kb + n) * (3 * DD) + 2 * DD + h * 64 + kg);
        }
        __syncthreads();

        float s[4][4];
        #pragma unroll
        for (int i = 0; i < 4; i++)
            #pragma unroll
            for (int j = 0; j < 4; j++) s[i][j] = 0.f;
        #pragma unroll 8
        for (int k = 0; k < 64; k++) {
            float4 a = *(const float4*)&Qs[k][ty * 4];
            float4 b = *(const float4*)&Ks[k][tx * 4];
            float av[4] = {a.x, a.y, a.z, a.w}, bv[4] = {b.x, b.y, b.z, b.w};
            #pragma unroll
            for (int i = 0; i < 4; i++)
                #pragma unroll
                for (int j = 0; j < 4; j++)
                    s[i][j] = fmaf(av[i], bv[j], s[i][j]);
        }

        #pragma unroll
        for (int i = 0; i < 4; i++) {
            float rm = fmaxf(fmaxf(s[i][0], s[i][1]), fmaxf(s[i][2], s[i][3])) * 0.125f;
            #pragma unroll
            for (int o = 8; o > 0; o >>= 1)
                rm = fmaxf(rm, __shfl_xor_sync(0xffffffffu, rm, o));
            float mn = fmaxf(m_run[i], rm);
            float corr = __expf(m_run[i] - mn);
            float p[4], rs = 0.f;
            #pragma unroll
            for (int j = 0; j < 4; j++) {
                p[j] = __expf(s[i][j] * 0.125f - mn);
                rs += p[j];
            }
            #pragma unroll
            for (int o = 8; o > 0; o >>= 1)
                rs += __shfl_xor_sync(0xffffffffu, rs, o);
            l_run[i] = l_run[i] * corr + rs;
            m_run[i] = mn;
            #pragma unroll
            for (int j = 0; j < 4; j++) {
                oa[i][j] *= corr;
                Ps[tx * 4 + j][ty * 4 + i] = p[j];
            }
        }
        __syncthreads();

        #pragma unroll 8
        for (int k = 0; k < 64; k++) {
            float4 a = *(const float4*)&Ps[k][ty * 4];
            float4 b = *(const float4*)&Vs[k][tx * 4];
            float av[4] = {a.x, a.y, a.z, a.w}, bv[4] = {b.x, b.y, b.z, b.w};
            #pragma unroll
            for (int i = 0; i < 4; i++)
                #pragma unroll
                for (int j = 0; j < 4; j++)
                    oa[i][j] = fmaf(av[i], bv[j], oa[i][j]);
        }
    }

    #pragma unroll
    for (int i = 0; i < 4; i++) {
        float inv = 1.f / l_run[i];
        int m = m0 + ty * 4 + i;
        size_t base = (size_t)m * DD + h * 64 + tx * 4;
        #pragma unroll
        for (int j = 0; j < 4; j++)
            g_ohi[base + j] = __float2half(oa[i][j] * inv);
    }
}

__global__ __launch_bounds__(256) void add_ln(f16* __restrict__ xhi, f16* __restrict__ xlo,
                                              const float* __restrict__ add,
                                              const float* __restrict__ add2,
                                              const float* __restrict__ cbias, int addMask,
                                              const float* __restrict__ g,
                                              const float* __restrict__ b) {
    int row = blockIdx.x, t = threadIdx.x;
    size_t base = (size_t)row * DD + t * 4;
    __half2 h0 = *(const __half2*)(xhi + base);
    __half2 h1 = *(const __half2*)(xhi + base + 2);
    __half2 l0 = *(const __half2*)(xlo + base);
    __half2 l1 = *(const __half2*)(xlo + base + 2);
    size_t aoff = (size_t)(row & addMask) * DD + t * 4;
    float4 av = *(const float4*)(add + aoff);
    if (add2) {
        float4 a2 = *(const float4*)(add2 + aoff);
        av.x += a2.x; av.y += a2.y; av.z += a2.z; av.w += a2.w;
    }
    if (cbias) {
        float4 cb = *(const float4*)(cbias + t * 4);
        av.x += cb.x; av.y += cb.y; av.z += cb.z; av.w += cb.w;
    }
    float v0 = __half2float(h0.x) + __half2float(l0.x) + av.x;
    float v1 = __half2float(h0.y) + __half2float(l0.y) + av.y;
    float v2 = __half2float(h1.x) + __half2float(l1.x) + av.z;
    float v3 = __half2float(h1.y) + __half2float(l1.y) + av.w;
    float mean = blockSum(v0 + v1 + v2 + v3) * (1.f / DD);
    float d0 = v0 - mean, d1 = v1 - mean, d2 = v2 - mean, d3 = v3 - mean;
    float var = blockSum(d0 * d0 + d1 * d1 + d2 * d2 + d3 * d3) * (1.f / DD);
    float rs = rsqrtf(var + 1e-5f);
    float4 gv = *(const float4*)(g + t * 4);
    float4 bv = *(const float4*)(b + t * 4);
    float o0 = d0 * rs * gv.x + bv.x, o1 = d1 * rs * gv.y + bv.y;
    float o2 = d2 * rs * gv.z + bv.z, o3 = d3 * rs * gv.w + bv.w;
    f16 hh, ll;
    f2hl(o0, hh, ll); xhi[base + 0] = hh; xlo[base + 0] = ll;
    f2hl(o1, hh, ll); xhi[base + 1] = hh; xlo[base + 1] = ll;
    f2hl(o2, hh, ll); xhi[base + 2] = hh; xlo[base + 2] = ll;
    f2hl(o3, hh, ll); xhi[base + 3] = hh; xlo[base + 3] = ll;
}

__global__ __launch_bounds__(256) void pool_mean() {
    int b = blockIdx.y;
    int d = blockIdx.x * 256 + threadIdx.x;
    size_t base = (size_t)b * LL * DD + d;
    float s = 0.f;
    for (int l = 0; l < LL; l++)
        s += __half2float(g_xhi[base + (size_t)l * DD]) +
             __half2float(g_xlo[base + (size_t)l * DD]);
    g_pooled[b * DD + d] = s * (1.f / LL);
}
__global__ __launch_bounds__(256) void logits_kernel(const float* __restrict__ wf,
                                                     const float* __restrict__ bf,
                                                     float* __restrict__ out) {
    int b = blockIdx.x / CC, c = blockIdx.x % CC;
    float s = 0.f;
    for (int d = threadIdx.x; d < DD; d += 256)
        s += g_pooled[b * DD + d] * wf[(size_t)d * CC + c];
    s = blockSum(s);
    if (threadIdx.x == 0) out[b * CC + c] = s + bf[c];
}

extern "C" void kernel_launch(void* const* d_in, const int* in_sizes, int n_in,
                              void* d_out, int out_size) {
    const void*  ids = d_in[0];
    const float* emb = (const float*)d_in[1];
    const float* pe  = (const float*)d_in[2];
    const float* wq  = (const float*)d_in[3];
    const float* bq  = (const float*)d_in[4];
    const float* wk  = (const float*)d_in[5];
    const float* bk  = (const float*)d_in[6];
    const float* wv  = (const float*)d_in[7];
    const float* bv  = (const float*)d_in[8];
    const float* wo  = (const float*)d_in[9];
    const float* bo  = (const float*)d_in[10];
    const float* w1  = (const float*)d_in[11];
    const float* b1  = (const float*)d_in[12];
    const float* w2  = (const float*)d_in[13];
    const float* b2  = (const float*)d_in[14];
    const float* g1  = (const float*)d_in[15];
    const float* be1 = (const float*)d_in[16];
    const float* g2  = (const float*)d_in[17];
    const float* be2 = (const float*)d_in[18];
    const float* wf  = (const float*)d_in[19];
    const float* bf  = (const float*)d_in[20];
    float* out = (float*)d_out;

    const int SM128 = (128 + 256) * PITCH * 2;
    const int SM64  = (64 + 256) * PITCH * 2;
    const int SMFA  = 4 * 64 * 68 * 4;
    cudaFuncSetAttribute(gemm_tc<128>, cudaFuncAttributeMaxDynamicSharedMemorySize, SM128);
    cudaFuncSetAttribute(gemm_tc<64>, cudaFuncAttributeMaxDynamicSharedMemorySize, SM64);
    cudaFuncSetAttribute(flash_attn, cudaFuncAttributeMaxDynamicSharedMemorySize, SMFA);

    float *tmp, *qkv, *src2, *Wff, *bff, *bqkv;
    f16 *xhi, *xlo, *ohi, *wqkvTh, *wqkvTl, *woTh, *woTl, *WffTh, *WffTl, *w1h, *w2Th, *w2Tl;
    cudaGetSymbolAddress((void**)&tmp, g_tmp);
    cudaGetSymbolAddress((void**)&qkv, g_qkv);
    cudaGetSymbolAddress((void**)&src2, g_src2);
    cudaGetSymbolAddress((void**)&Wff, g_Wff);
    cudaGetSymbolAddress((void**)&bff, g_bff);
    cudaGetSymbolAddress((void**)&bqkv, g_bqkv);
    cudaGetSymbolAddress((void**)&xhi, g_xhi);
    cudaGetSymbolAddress((void**)&xlo, g_xlo);
    cudaGetSymbolAddress((void**)&ohi, g_ohi);
    cudaGetSymbolAddress((void**)&wqkvTh, g_wqkvT_hi);
    cudaGetSymbolAddress((void**)&wqkvTl, g_wqkvT_lo);
    cudaGetSymbolAddress((void**)&woTh, g_woT_hi);
    cudaGetSymbolAddress((void**)&woTl, g_woT_lo);
    cudaGetSymbolAddress((void**)&WffTh, g_WffT_hi);
    cudaGetSymbolAddress((void**)&WffTl, g_WffT_lo);
    cudaGetSymbolAddress((void**)&w1h, g_w1_hi);
    cudaGetSymbolAddress((void**)&w2Th, g_w2T_hi);
    cudaGetSymbolAddress((void**)&w2Tl, g_w2T_lo);

    detect_kernel<<<1, 1>>>(ids);
    embed_kernel<<<BB * LL, 256>>>(ids, emb, pe);

    dim3 tb(32, 8);
    tconv<<<dim3(32, 32), tb>>>(wq, nullptr, wqkvTh, wqkvTl, DD, DD, 0);
    tconv<<<dim3(32, 32), tb>>>(wk, nullptr, wqkvTh, wqkvTl, DD, DD, DD);
    tconv<<<dim3(32, 32), tb>>>(wv, nullptr, wqkvTh, wqkvTl, DD, DD, 2 * DD);
    tconv<<<dim3(32, 32), tb>>>(wo, nullptr, woTh, woTl, DD, DD, 0);
    tconv<<<dim3(32, 128), tb>>>(w2, nullptr, w2Th, w2Tl, FF, DD, 0);
    conv_h<<<(DD * FF) / 1024, 256>>>(w1, w1h);
    concat_bias<<<3, 1024>>>(bq, bk, bv);
    bff_part<<<32, 256>>>(b1, w2);
    bff_reduce<<<4, 256>>>(b2);
    gemm_tc<64><<<dim3(DD / 128, DD / 64, 2), 128, SM64>>>(w1h, w2Th, w2Tl, nullptr,
                                                           Wff, FF / 2, FF, DD, DD * DD);
    tconv<<<dim3(32, 32), tb>>>(Wff, Wff + (size_t)DD * DD, WffTh, WffTl, DD, DD, 0);

    for (int layer = 0; layer < NLAYER; layer++) {
        gemm_tc<64><<<dim3(3 * DD / 128, LL / 64, 1), 128, SM64>>>(xhi, wqkvTh, wqkvTl,
                                                                   bqkv, qkv, DD, DD, 3 * DD, 0);
        flash_attn<<<dim3(8, HH), 256, SMFA>>>(qkv);
        gemm_tc<64><<<dim3(DD / 128, LL / 64, 2), 128, SM64>>>(ohi, woTh, woTl, nullptr,
                                                               src2, DD / 2, DD, DD, LL * DD);
        add_ln<<<BB * LL, 256>>>(xhi, xlo, src2, src2 + (size_t)LL * DD, bo, LL - 1, g1, be1);
        gemm_tc<128><<<dim3(DD / 128, (BB * LL) / 128, 1), 256, SM128>>>(xhi, WffTh, WffTl,
                                                                         bff, tmp, DD, DD, DD, 0);
        add_ln<<<BB * LL, 256>>>(xhi, xlo, tmp, nullptr, nullptr, BB * LL - 1, g2, be2);
    }

    pool_mean<<<dim3(DD / 256, BB), 256>>>();
    logits_kernel<<<BB * CC, 256>>>(wf, bf, out);
}

// round 8
// speedup vs baseline: 4.2696x; 1.2573x over previous
#include <cuda_runtime.h>
#include <cuda_bf16.h>
#include <cuda_fp16.h>
#include <cstdint>

#define BB 16
#define LL 512
#define DD 1024
#define HH 16
#define FF 4096
#define CC 10
#define NLAYER 6

typedef __half f16;

__device__ float g_tmp[BB * LL * DD];
__device__ f16 g_xhi[BB * LL * DD];
__device__ f16 g_xlo[BB * LL * DD];
__device__ float g_qkv[LL * 3 * DD];
__device__ f16 g_ohi[LL * DD];
__device__ float g_src2[2 * LL * DD];
__device__ float g_Wff[2 * DD * DD];
__device__ float g_bff[DD];
__device__ float g_bffpart[32 * DD];
__device__ float g_bqkv[3 * DD];
__device__ float g_pooled[BB * DD];
__device__ int g_ids64;
__device__ f16 g_wqkvT[3 * DD * DD];
__device__ f16 g_woT[DD * DD];
__device__ f16 g_WffT[DD * DD];
__device__ f16 g_w1h[DD * FF];
__device__ f16 g_w2T[DD * FF];

__device__ __forceinline__ void f2hl(float v, f16& h, f16& l) {
    h = __float2half(v);
    l = __float2half(v - __half2float(h));
}
__device__ __forceinline__ float warpSum(float v) {
    #pragma unroll
    for (int o = 16; o > 0; o >>= 1) v += __shfl_xor_sync(0xffffffffu, v, o);
    return v;
}
__device__ __forceinline__ float blockSum(float v) {
    __shared__ float sm[32];
    int lane = threadIdx.x & 31, w = threadIdx.x >> 5;
    v = warpSum(v);
    if (lane == 0) sm[w] = v;
    __syncthreads();
    if (w == 0) {
        float x = (lane < (int)(blockDim.x >> 5)) ? sm[lane] : 0.f;
        x = warpSum(x);
        if (lane == 0) sm[0] = x;
    }
    __syncthreads();
    float r = sm[0];
    __syncthreads();
    return r;
}

__device__ __forceinline__ uint32_t s2u(const void* p) {
    uint32_t a;
    asm("{ .reg .u64 t; cvta.to.shared.u64 t, %1; cvt.u32.u64 %0, t; }" : "=r"(a) : "l"(p));
    return a;
}
__device__ __forceinline__ void cpa(uint32_t dst, const void* src) {
    asm volatile("cp.async.cg.shared.global [%0], [%1], 16;" :: "r"(dst), "l"(src));
}
__device__ __forceinline__ void cpcommit() { asm volatile("cp.async.commit_group;"); }
template <int N> __device__ __forceinline__ void cpwait() {
    asm volatile("cp.async.wait_group %0;" :: "n"(N));
}
__device__ __forceinline__ void ldmx4(uint32_t* r, uint32_t a) {
    asm volatile("ldmatrix.sync.aligned.m8n8.x4.shared.b16 {%0,%1,%2,%3}, [%4];"
                 : "=r"(r[0]), "=r"(r[1]), "=r"(r[2]), "=r"(r[3]) : "r"(a));
}
__device__ __forceinline__ void mmah(float* d, const uint32_t* a, const uint32_t* b) {
    asm volatile(
        "mma.sync.aligned.m16n8k16.row.col.f32.f16.f16.f32 "
        "{%0,%1,%2,%3}, {%4,%5,%6,%7}, {%8,%9}, {%0,%1,%2,%3};"
        : "+f"(d[0]), "+f"(d[1]), "+f"(d[2]), "+f"(d[3])
        : "r"(a[0]), "r"(a[1]), "r"(a[2]), "r"(a[3]), "r"(b[0]), "r"(b[1]));
}

#define PITCH 80

// C[M,N] = A @ B^T + bias ; both single fp16, 1 MMA per 16x8x16 step.
template <int MT>
__global__ __launch_bounds__(MT * 2, (MT == 64) ? 4 : 2) void gemm_tc(
    const f16* __restrict__ A, const f16* __restrict__ B,
    const float* __restrict__ bias, float* __restrict__ C,
    int Kiter, int Kstride, int N, int Czoff) {
    constexpr int THREADS = MT * 2;
    constexpr int OFS_B = MT * PITCH;
    constexpr int STB = (MT + 128) * PITCH;
    extern __shared__ char smem[];
    uint32_t sb = s2u(smem);
    const int t = threadIdx.x, lane = t & 31, wid = t >> 5;
    const int m0 = blockIdx.y * MT, n0 = blockIdx.x * 128;
    const int wr = wid >> 2, wc = wid & 3;
    const size_t kz = (size_t)blockIdx.z * Kiter;
    C += (size_t)blockIdx.z * Czoff;
    const int NKB = Kiter / 32;

    float acc[4][4][4];
    #pragma unroll
    for (int i = 0; i < 4; i++)
        #pragma unroll
        for (int j = 0; j < 4; j++)
            #pragma unroll
            for (int r = 0; r < 4; r++) acc[i][j][r] = 0.f;

    const uint32_t aoff = (uint32_t)((wr * 64 + (lane & 15)) * PITCH + ((lane >> 4) << 4));
    const int brow = wc * 32 + (lane & 7) + ((lane & 16) ? 8 : 0);
    const uint32_t boff = (uint32_t)(brow * PITCH + ((lane & 8) ? 16 : 0));

    auto load_stage = [&](int kb0, uint32_t base) {
        #pragma unroll
        for (int idx = t; idx < MT * 4; idx += THREADS) {
            int row = idx >> 2, c = idx & 3;
            uint32_t so = (uint32_t)(row * PITCH + c * 16);
            cpa(base + so, A + (size_t)(m0 + row) * Kstride + kz + kb0 + c * 8);
        }
        #pragma unroll
        for (int idx = t; idx < 512; idx += THREADS) {
            int row = idx >> 2, c = idx & 3;
            uint32_t so = (uint32_t)(row * PITCH + c * 16);
            cpa(base + OFS_B + so, B + (size_t)(n0 + row) * Kstride + kz + kb0 + c * 8);
        }
        cpcommit();
    };

    load_stage(0, sb);

    for (int kb = 0; kb < NKB; kb++) {
        int cur = kb & 1;
        if (kb + 1 < NKB) {
            load_stage((kb + 1) * 32, sb + (uint32_t)(cur ^ 1) * STB);
            cpwait<1>();
        } else {
            cpwait<0>();
        }
        __syncthreads();
        uint32_t base = sb + (uint32_t)cur * STB;
        #pragma unroll
        for (int ks = 0; ks < 2; ks++) {
            uint32_t kbyte = (uint32_t)(ks * 32);
            uint32_t ah[4][4], bh[2][4];
            #pragma unroll
            for (int mt = 0; mt < 4; mt++)
                ldmx4(ah[mt], base + aoff + (uint32_t)(mt * 16 * PITCH) + kbyte);
            #pragma unroll
            for (int ng = 0; ng < 2; ng++)
                ldmx4(bh[ng], base + OFS_B + boff + (uint32_t)(ng * 16 * PITCH) + kbyte);
            #pragma unroll
            for (int mt = 0; mt < 4; mt++)
                #pragma unroll
                for (int nt = 0; nt < 4; nt++)
                    mmah(acc[mt][nt], ah[mt], &bh[nt >> 1][(nt & 1) * 2]);
        }
        __syncthreads();
    }

    #pragma unroll
    for (int mt = 0; mt < 4; mt++) {
        int m = m0 + wr * 64 + mt * 16 + (lane >> 2);
        #pragma unroll
        for (int nt = 0; nt < 4; nt++) {
            int n = n0 + wc * 32 + nt * 8 + (lane & 3) * 2;
            float b0 = 0.f, b1 = 0.f;
            if (bias) { b0 = bias[n]; b1 = bias[n + 1]; }
            *(float2*)(C + (size_t)m * N + n) = make_float2(acc[mt][nt][0] + b0, acc[mt][nt][1] + b1);
            *(float2*)(C + (size_t)(m + 8) * N + n) = make_float2(acc[mt][nt][2] + b0, acc[mt][nt][3] + b1);
        }
    }
}

__global__ void detect_kernel(const void* ids) {
    const int* p = (const int*)ids;
    int nz = 0;
    for (int i = 0; i < 256; i += 2)
        if (p[i + 1] != 0) nz++;
    g_ids64 = (nz == 0) ? 1 : 0;
}
__global__ void embed_kernel(const void* ids, const float* __restrict__ emb,
                             const float* __restrict__ pe) {
    int row = blockIdx.x;
    int d = threadIdx.x * 4;
    long long id;
    if (g_ids64) id = ((const long long*)ids)[row];
    else         id = (long long)((const int*)ids)[row];
    int l = row & (LL - 1);
    float4 e = *(const float4*)(emb + (size_t)id * DD + d);
    float4 p = *(const float4*)(pe + (size_t)l * DD + d);
    float v[4] = {e.x * 32.f + p.x, e.y * 32.f + p.y, e.z * 32.f + p.z, e.w * 32.f + p.w};
    size_t base = (size_t)row * DD + d;
    #pragma unroll
    for (int j = 0; j < 4; j++) {
        f16 h, lo;
        f2hl(v[j], h, lo);
        g_xhi[base + j] = h;
        g_xlo[base + j] = lo;
    }
}
// transpose+convert (optional sum of two inputs): out[(nOff+c)*R + r] fp16
__global__ void tconv(const float* __restrict__ in, const float* __restrict__ in2,
                      f16* __restrict__ oh, int R, int C, int nOff) {
    __shared__ float tl[32][33];
    int n0 = blockIdx.x * 32, k0 = blockIdx.y * 32;
    int tx = threadIdx.x, ty = threadIdx.y;
    #pragma unroll
    for (int i = 0; i < 4; i++) {
        size_t idx = (size_t)(k0 + ty + i * 8) * C + n0 + tx;
        float v = in[idx];
        if (in2) v += in2[idx];
        tl[ty + i * 8][tx] = v;
    }
    __syncthreads();
    #pragma unroll
    for (int i = 0; i < 4; i++) {
        int nn = ty + i * 8;
        oh[(size_t)(nOff + n0 + nn) * R + k0 + tx] = __float2half(tl[tx][nn]);
    }
}
__global__ void conv_h(const float* __restrict__ in, f16* __restrict__ oh) {
    size_t i = ((size_t)blockIdx.x * 256 + threadIdx.x) * 4;
    float4 v = *(const float4*)(in + i);
    oh[i + 0] = __float2half(v.x);
    oh[i + 1] = __float2half(v.y);
    oh[i + 2] = __float2half(v.z);
    oh[i + 3] = __float2half(v.w);
}
__global__ void concat_bias(const float* __restrict__ bq, const float* __restrict__ bk,
                            const float* __restrict__ bv) {
    int t = threadIdx.x, s = blockIdx.x;
    const float* src = (s == 0) ? bq : (s == 1) ? bk : bv;
    g_bqkv[s * DD + t] = src[t];
}
__global__ __launch_bounds__(256) void bff_part(const float* __restrict__ b1,
                                                const float* __restrict__ w2) {
    int y = blockIdx.x, t = threadIdx.x;
    float s[4] = {0.f, 0.f, 0.f, 0.f};
    for (int f = y * 128; f < y * 128 + 128; f++) {
        float bv = b1[f];
        const float* wr = w2 + (size_t)f * DD;
        #pragma unroll
        for (int j = 0; j < 4; j++) s[j] = fmaf(bv, wr[t + j * 256], s[j]);
    }
    #pragma unroll
    for (int j = 0; j < 4; j++) g_bffpart[y * DD + t + j * 256] = s[j];
}
__global__ __launch_bounds__(256) void bff_reduce(const float* __restrict__ b2) {
    int d = blockIdx.x * 256 + threadIdx.x;
    float s = b2[d];
    for (int y = 0; y < 32; y++) s += g_bffpart[y * DD + d];
    g_bff[d] = s;
}

// flash-fused attention (batch 0): grid (8 m-tiles, 16 heads), 256 thr, 4x4 microtiles
__global__ __launch_bounds__(256, 2) void flash_attn(const float* __restrict__ qkv) {
    extern __shared__ float fs[];
    float (*Qs)[68] = (float(*)[68])fs;
    float (*Ks)[68] = (float(*)[68])(fs + 64 * 68);
    float (*Vs)[68] = (float(*)[68])(fs + 2 * 64 * 68);
    float (*Ps)[68] = (float(*)[68])(fs + 3 * 64 * 68);
    int h = blockIdx.y, m0 = blockIdx.x * 64;
    int t = threadIdx.x, tx = t & 15, ty = t >> 4;

    #pragma unroll
    for (int i = 0; i < 4; i++) {
        int idx = t + i * 256;
        int m = idx >> 4, kg = (idx & 15) * 4;
        float4 q4 = *(const float4*)(qkv + (size_t)(m0 + m) * (3 * DD) + h * 64 + kg);
        Qs[kg + 0][m] = q4.x; Qs[kg + 1][m] = q4.y;
        Qs[kg + 2][m] = q4.z; Qs[kg + 3][m] = q4.w;
    }

    float m_run[4], l_run[4], oa[4][4];
    #pragma unroll
    for (int i = 0; i < 4; i++) {
        m_run[i] = -1e30f; l_run[i] = 0.f;
        #pragma unroll
        for (int j = 0; j < 4; j++) oa[i][j] = 0.f;
    }

    for (int kb = 0; kb < LL; kb += 64) {
        __syncthreads();
        #pragma unroll
        for (int i = 0; i < 4; i++) {
            int idx = t + i * 256;
            int n = idx >> 4, kg = (idx & 15) * 4;
            float4 k4 = *(const float4*)(qkv + (size_t)(kb + n) * (3 * DD) + DD + h * 64 + kg);
            Ks[kg + 0][n] = k4.x; Ks[kg + 1][n] = k4.y;
            Ks[kg + 2][n] = k4.z; Ks[kg + 3][n] = k4.w;
            *(float4*)&Vs[n][kg] =
                *(const float4*)(qkv + (size_t)(kb + n) * (3 * DD) + 2 * DD + h * 64 + kg);
        }
        __syncthreads();

        float s[4][4];
        #pragma unroll
        for (int i = 0; i < 4; i++)
            #pragma unroll
            for (int j = 0; j < 4; j++) s[i][j] = 0.f;
        #pragma unroll 8
        for (int k = 0; k < 64; k++) {
            float4 a = *(const float4*)&Qs[k][ty * 4];
            float4 b = *(const float4*)&Ks[k][tx * 4];
            float av[4] = {a.x, a.y, a.z, a.w}, bv[4] = {b.x, b.y, b.z, b.w};
            #pragma unroll
            for (int i = 0; i < 4; i++)
                #pragma unroll
                for (int j = 0; j < 4; j++)
                    s[i][j] = fmaf(av[i], bv[j], s[i][j]);
        }

        #pragma unroll
        for (int i = 0; i < 4; i++) {
            float rm = fmaxf(fmaxf(s[i][0], s[i][1]), fmaxf(s[i][2], s[i][3])) * 0.125f;
            #pragma unroll
            for (int o = 8; o > 0; o >>= 1)
                rm = fmaxf(rm, __shfl_xor_sync(0xffffffffu, rm, o));
            float mn = fmaxf(m_run[i], rm);
            float corr = __expf(m_run[i] - mn);
            float p[4], rs = 0.f;
            #pragma unroll
            for (int j = 0; j < 4; j++) {
                p[j] = __expf(s[i][j] * 0.125f - mn);
                rs += p[j];
            }
            #pragma unroll
            for (int o = 8; o > 0; o >>= 1)
                rs += __shfl_xor_sync(0xffffffffu, rs, o);
            l_run[i] = l_run[i] * corr + rs;
            m_run[i] = mn;
            #pragma unroll
            for (int j = 0; j < 4; j++) {
                oa[i][j] *= corr;
                Ps[tx * 4 + j][ty * 4 + i] = p[j];
            }
        }
        __syncthreads();

        #pragma unroll 8
        for (int k = 0; k < 64; k++) {
            float4 a = *(const float4*)&Ps[k][ty * 4];
            float4 b = *(const float4*)&Vs[k][tx * 4];
            float av[4] = {a.x, a.y, a.z, a.w}, bv[4] = {b.x, b.y, b.z, b.w};
            #pragma unroll
            for (int i = 0; i < 4; i++)
                #pragma unroll
                for (int j = 0; j < 4; j++)
                    oa[i][j] = fmaf(av[i], bv[j], oa[i][j]);
        }
    }

    #pragma unroll
    for (int i = 0; i < 4; i++) {
        float inv = 1.f / l_run[i];
        int m = m0 + ty * 4 + i;
        size_t base = (size_t)m * DD + h * 64 + tx * 4;
        #pragma unroll
        for (int j = 0; j < 4; j++)
            g_ohi[base + j] = __float2half(oa[i][j] * inv);
    }
}

__global__ __launch_bounds__(256) void add_ln(f16* __restrict__ xhi, f16* __restrict__ xlo,
                                              const float* __restrict__ add,
                                              const float* __restrict__ add2,
                                              const float* __restrict__ cbias, int addMask,
                                              const float* __restrict__ g,
                                              const float* __restrict__ b) {
    int row = blockIdx.x, t = threadIdx.x;
    size_t base = (size_t)row * DD + t * 4;
    __half2 h0 = *(const __half2*)(xhi + base);
    __half2 h1 = *(const __half2*)(xhi + base + 2);
    __half2 l0 = *(const __half2*)(xlo + base);
    __half2 l1 = *(const __half2*)(xlo + base + 2);
    size_t aoff = (size_t)(row & addMask) * DD + t * 4;
    float4 av = *(const float4*)(add + aoff);
    if (add2) {
        float4 a2 = *(const float4*)(add2 + aoff);
        av.x += a2.x; av.y += a2.y; av.z += a2.z; av.w += a2.w;
    }
    if (cbias) {
        float4 cb = *(const float4*)(cbias + t * 4);
        av.x += cb.x; av.y += cb.y; av.z += cb.z; av.w += cb.w;
    }
    float v0 = __half2float(h0.x) + __half2float(l0.x) + av.x;
    float v1 = __half2float(h0.y) + __half2float(l0.y) + av.y;
    float v2 = __half2float(h1.x) + __half2float(l1.x) + av.z;
    float v3 = __half2float(h1.y) + __half2float(l1.y) + av.w;
    float mean = blockSum(v0 + v1 + v2 + v3) * (1.f / DD);
    float d0 = v0 - mean, d1 = v1 - mean, d2 = v2 - mean, d3 = v3 - mean;
    float var = blockSum(d0 * d0 + d1 * d1 + d2 * d2 + d3 * d3) * (1.f / DD);
    float rs = rsqrtf(var + 1e-5f);
    float4 gv = *(const float4*)(g + t * 4);
    float4 bv = *(const float4*)(b + t * 4);
    float o0 = d0 * rs * gv.x + bv.x, o1 = d1 * rs * gv.y + bv.y;
    float o2 = d2 * rs * gv.z + bv.z, o3 = d3 * rs * gv.w + bv.w;
    f16 hh, ll;
    f2hl(o0, hh, ll); xhi[base + 0] = hh; xlo[base + 0] = ll;
    f2hl(o1, hh, ll); xhi[base + 1] = hh; xlo[base + 1] = ll;
    f2hl(o2, hh, ll); xhi[base + 2] = hh; xlo[base + 2] = ll;
    f2hl(o3, hh, ll); xhi[base + 3] = hh; xlo[base + 3] = ll;
}

__global__ __launch_bounds__(256) void pool_mean() {
    int b = blockIdx.y;
    int d = blockIdx.x * 256 + threadIdx.x;
    size_t base = (size_t)b * LL * DD + d;
    float s = 0.f;
    for (int l = 0; l < LL; l++)
        s += __half2float(g_xhi[base + (size_t)l * DD]) +
             __half2float(g_xlo[base + (size_t)l * DD]);
    g_pooled[b * DD + d] = s * (1.f / LL);
}
__global__ __launch_bounds__(256) void logits_kernel(const float* __restrict__ wf,
                                                     const float* __restrict__ bf,
                                                     float* __restrict__ out) {
    int b = blockIdx.x / CC, c = blockIdx.x % CC;
    float s = 0.f;
    for (int d = threadIdx.x; d < DD; d += 256)
        s += g_pooled[b * DD + d] * wf[(size_t)d * CC + c];
    s = blockSum(s);
    if (threadIdx.x == 0) out[b * CC + c] = s + bf[c];
}

extern "C" void kernel_launch(void* const* d_in, const int* in_sizes, int n_in,
                              void* d_out, int out_size) {
    const void*  ids = d_in[0];
    const float* emb = (const float*)d_in[1];
    const float* pe  = (const float*)d_in[2];
    const float* wq  = (const float*)d_in[3];
    const float* bq  = (const float*)d_in[4];
    const float* wk  = (const float*)d_in[5];
    const float* bk  = (const float*)d_in[6];
    const float* wv  = (const float*)d_in[7];
    const float* bv  = (const float*)d_in[8];
    const float* wo  = (const float*)d_in[9];
    const float* bo  = (const float*)d_in[10];
    const float* w1  = (const float*)d_in[11];
    const float* b1  = (const float*)d_in[12];
    const float* w2  = (const float*)d_in[13];
    const float* b2  = (const float*)d_in[14];
    const float* g1  = (const float*)d_in[15];
    const float* be1 = (const float*)d_in[16];
    const float* g2  = (const float*)d_in[17];
    const float* be2 = (const float*)d_in[18];
    const float* wf  = (const float*)d_in[19];
    const float* bf  = (const float*)d_in[20];
    float* out = (float*)d_out;

    const int SM128 = (128 + 128) * PITCH * 2;
    const int SM64  = (64 + 128) * PITCH * 2;
    const int SMFA  = 4 * 64 * 68 * 4;
    cudaFuncSetAttribute(gemm_tc<128>, cudaFuncAttributeMaxDynamicSharedMemorySize, SM128);
    cudaFuncSetAttribute(gemm_tc<64>, cudaFuncAttributeMaxDynamicSharedMemorySize, SM64);
    cudaFuncSetAttribute(flash_attn, cudaFuncAttributeMaxDynamicSharedMemorySize, SMFA);

    float *tmp, *qkv, *src2, *Wff, *bff, *bqkv;
    f16 *xhi, *xlo, *ohi, *wqkvT, *woT, *WffT, *w1h, *w2T;
    cudaGetSymbolAddress((void**)&tmp, g_tmp);
    cudaGetSymbolAddress((void**)&qkv, g_qkv);
    cudaGetSymbolAddress((void**)&src2, g_src2);
    cudaGetSymbolAddress((void**)&Wff, g_Wff);
    cudaGetSymbolAddress((void**)&bff, g_bff);
    cudaGetSymbolAddress((void**)&bqkv, g_bqkv);
    cudaGetSymbolAddress((void**)&xhi, g_xhi);
    cudaGetSymbolAddress((void**)&xlo, g_xlo);
    cudaGetSymbolAddress((void**)&ohi, g_ohi);
    cudaGetSymbolAddress((void**)&wqkvT, g_wqkvT);
    cudaGetSymbolAddress((void**)&woT, g_woT);
    cudaGetSymbolAddress((void**)&WffT, g_WffT);
    cudaGetSymbolAddress((void**)&w1h, g_w1h);
    cudaGetSymbolAddress((void**)&w2T, g_w2T);

    detect_kernel<<<1, 1>>>(ids);
    embed_kernel<<<BB * LL, 256>>>(ids, emb, pe);

    dim3 tb(32, 8);
    tconv<<<dim3(32, 32), tb>>>(wq, nullptr, wqkvT, DD, DD, 0);
    tconv<<<dim3(32, 32), tb>>>(wk, nullptr, wqkvT, DD, DD, DD);
    tconv<<<dim3(32, 32), tb>>>(wv, nullptr, wqkvT, DD, DD, 2 * DD);
    tconv<<<dim3(32, 32), tb>>>(wo, nullptr, woT, DD, DD, 0);
    tconv<<<dim3(32, 128), tb>>>(w2, nullptr, w2T, FF, DD, 0);
    conv_h<<<(DD * FF) / 1024, 256>>>(w1, w1h);
    concat_bias<<<3, 1024>>>(bq, bk, bv);
    bff_part<<<32, 256>>>(b1, w2);
    bff_reduce<<<4, 256>>>(b2);
    gemm_tc<64><<<dim3(DD / 128, DD / 64, 2), 128, SM64>>>(w1h, w2T, nullptr,
                                                           Wff, FF / 2, FF, DD, DD * DD);
    tconv<<<dim3(32, 32), tb>>>(Wff, Wff + (size_t)DD * DD, WffT, DD, DD, 0);

    for (int layer = 0; layer < NLAYER; layer++) {
        gemm_tc<64><<<dim3(3 * DD / 128, LL / 64, 1), 128, SM64>>>(xhi, wqkvT,
                                                                   bqkv, qkv, DD, DD, 3 * DD, 0);
        flash_attn<<<dim3(8, HH), 256, SMFA>>>(qkv);
        gemm_tc<64><<<dim3(DD / 128, LL / 64, 2), 128, SM64>>>(ohi, woT, nullptr,
                                                               src2, DD / 2, DD, DD, LL * DD);
        add_ln<<<BB * LL, 256>>>(xhi, xlo, src2, src2 + (size_t)LL * DD, bo, LL - 1, g1, be1);
        gemm_tc<128><<<dim3(DD / 128, (BB * LL) / 128, 1), 256, SM128>>>(xhi, WffT,
                                                                         bff, tmp, DD, DD, DD, 0);
        add_ln<<<BB * LL, 256>>>(xhi, xlo, tmp, nullptr, nullptr, BB * LL - 1, g2, be2);
    }

    pool_mean<<<dim3(DD / 256, BB), 256>>>();
    logits_kernel<<<BB * CC, 256>>>(wf, bf, out);
}

// round 9
// speedup vs baseline: 4.5564x; 1.0672x over previous
#include <cuda_runtime.h>
#include <cuda_bf16.h>
#include <cuda_fp16.h>
#include <cstdint>

#define BB 16
#define LL 512
#define DD 1024
#define HH 16
#define FF 4096
#define CC 10
#define NLAYER 6

typedef __half f16;

__device__ f16 g_xhi[BB * LL * DD];
__device__ f16 g_xlo[BB * LL * DD];
__device__ f16 g_tmph[BB * LL * DD];
__device__ f16 g_qkvh[LL * 3 * DD];
__device__ f16 g_ohi[LL * DD];
__device__ float g_src2[2 * LL * DD];
__device__ float g_Wff[2 * DD * DD];
__device__ float g_bff[DD];
__device__ float g_bffpart[32 * DD];
__device__ float g_bqkv[3 * DD];
__device__ float g_pooled[BB * DD];
__device__ int g_ids64;
__device__ f16 g_wqkvT[3 * DD * DD];
__device__ f16 g_woT[DD * DD];
__device__ f16 g_WffT[DD * DD];
__device__ f16 g_w1h[DD * FF];
__device__ f16 g_w2T[DD * FF];

__device__ __forceinline__ void f2hl(float v, f16& h, f16& l) {
    h = __float2half(v);
    l = __float2half(v - __half2float(h));
}
__device__ __forceinline__ float warpSum(float v) {
    #pragma unroll
    for (int o = 16; o > 0; o >>= 1) v += __shfl_xor_sync(0xffffffffu, v, o);
    return v;
}
__device__ __forceinline__ float blockSum(float v) {
    __shared__ float sm[32];
    int lane = threadIdx.x & 31, w = threadIdx.x >> 5;
    v = warpSum(v);
    if (lane == 0) sm[w] = v;
    __syncthreads();
    if (w == 0) {
        float x = (lane < (int)(blockDim.x >> 5)) ? sm[lane] : 0.f;
        x = warpSum(x);
        if (lane == 0) sm[0] = x;
    }
    __syncthreads();
    float r = sm[0];
    __syncthreads();
    return r;
}

__device__ __forceinline__ uint32_t s2u(const void* p) {
    uint32_t a;
    asm("{ .reg .u64 t; cvta.to.shared.u64 t, %1; cvt.u32.u64 %0, t; }" : "=r"(a) : "l"(p));
    return a;
}
__device__ __forceinline__ void cpa(uint32_t dst, const void* src) {
    asm volatile("cp.async.cg.shared.global [%0], [%1], 16;" :: "r"(dst), "l"(src));
}
__device__ __forceinline__ void cpcommit() { asm volatile("cp.async.commit_group;"); }
template <int N> __device__ __forceinline__ void cpwait() {
    asm volatile("cp.async.wait_group %0;" :: "n"(N));
}
__device__ __forceinline__ void ldmx4(uint32_t* r, uint32_t a) {
    asm volatile("ldmatrix.sync.aligned.m8n8.x4.shared.b16 {%0,%1,%2,%3}, [%4];"
                 : "=r"(r[0]), "=r"(r[1]), "=r"(r[2]), "=r"(r[3]) : "r"(a));
}
__device__ __forceinline__ void mmah(float* d, const uint32_t* a, const uint32_t* b) {
    asm volatile(
        "mma.sync.aligned.m16n8k16.row.col.f32.f16.f16.f32 "
        "{%0,%1,%2,%3}, {%4,%5,%6,%7}, {%8,%9}, {%0,%1,%2,%3};"
        : "+f"(d[0]), "+f"(d[1]), "+f"(d[2]), "+f"(d[3])
        : "r"(a[0]), "r"(a[1]), "r"(a[2]), "r"(a[3]), "r"(b[0]), "r"(b[1]));
}

#define PITCH 80

// C[M,N] = A @ B^T + bias ; single fp16 operands; optional fp16 output (Ch)
template <int MT>
__global__ __launch_bounds__(MT * 2, (MT == 64) ? 4 : 2) void gemm_tc(
    const f16* __restrict__ A, const f16* __restrict__ B,
    const float* __restrict__ bias, float* __restrict__ C, f16* __restrict__ Ch,
    int Kiter, int Kstride, int N, int Czoff) {
    constexpr int THREADS = MT * 2;
    constexpr int OFS_B = MT * PITCH;
    constexpr int STB = (MT + 128) * PITCH;
    extern __shared__ char smem[];
    uint32_t sb = s2u(smem);
    const int t = threadIdx.x, lane = t & 31, wid = t >> 5;
    const int m0 = blockIdx.y * MT, n0 = blockIdx.x * 128;
    const int wr = wid >> 2, wc = wid & 3;
    const size_t kz = (size_t)blockIdx.z * Kiter;
    if (C) C += (size_t)blockIdx.z * Czoff;
    const int NKB = Kiter / 32;

    float acc[4][4][4];
    #pragma unroll
    for (int i = 0; i < 4; i++)
        #pragma unroll
        for (int j = 0; j < 4; j++)
            #pragma unroll
            for (int r = 0; r < 4; r++) acc[i][j][r] = 0.f;

    const uint32_t aoff = (uint32_t)((wr * 64 + (lane & 15)) * PITCH + ((lane >> 4) << 4));
    const int brow = wc * 32 + (lane & 7) + ((lane & 16) ? 8 : 0);
    const uint32_t boff = (uint32_t)(brow * PITCH + ((lane & 8) ? 16 : 0));

    auto load_stage = [&](int kb0, uint32_t base) {
        #pragma unroll
        for (int idx = t; idx < MT * 4; idx += THREADS) {
            int row = idx >> 2, c = idx & 3;
            uint32_t so = (uint32_t)(row * PITCH + c * 16);
            cpa(base + so, A + (size_t)(m0 + row) * Kstride + kz + kb0 + c * 8);
        }
        #pragma unroll
        for (int idx = t; idx < 512; idx += THREADS) {
            int row = idx >> 2, c = idx & 3;
            uint32_t so = (uint32_t)(row * PITCH + c * 16);
            cpa(base + OFS_B + so, B + (size_t)(n0 + row) * Kstride + kz + kb0 + c * 8);
        }
        cpcommit();
    };

    load_stage(0, sb);

    for (int kb = 0; kb < NKB; kb++) {
        int cur = kb & 1;
        if (kb + 1 < NKB) {
            load_stage((kb + 1) * 32, sb + (uint32_t)(cur ^ 1) * STB);
            cpwait<1>();
        } else {
            cpwait<0>();
        }
        __syncthreads();
        uint32_t base = sb + (uint32_t)cur * STB;
        #pragma unroll
        for (int ks = 0; ks < 2; ks++) {
            uint32_t kbyte = (uint32_t)(ks * 32);
            uint32_t ah[4][4], bh[2][4];
            #pragma unroll
            for (int mt = 0; mt < 4; mt++)
                ldmx4(ah[mt], base + aoff + (uint32_t)(mt * 16 * PITCH) + kbyte);
            #pragma unroll
            for (int ng = 0; ng < 2; ng++)
                ldmx4(bh[ng], base + OFS_B + boff + (uint32_t)(ng * 16 * PITCH) + kbyte);
            #pragma unroll
            for (int mt = 0; mt < 4; mt++)
                #pragma unroll
                for (int nt = 0; nt < 4; nt++)
                    mmah(acc[mt][nt], ah[mt], &bh[nt >> 1][(nt & 1) * 2]);
        }
        __syncthreads();
    }

    #pragma unroll
    for (int mt = 0; mt < 4; mt++) {
        int m = m0 + wr * 64 + mt * 16 + (lane >> 2);
        #pragma unroll
        for (int nt = 0; nt < 4; nt++) {
            int n = n0 + wc * 32 + nt * 8 + (lane & 3) * 2;
            float b0 = 0.f, b1 = 0.f;
            if (bias) { b0 = bias[n]; b1 = bias[n + 1]; }
            float v0 = acc[mt][nt][0] + b0, v1 = acc[mt][nt][1] + b1;
            float v2 = acc[mt][nt][2] + b0, v3 = acc[mt][nt][3] + b1;
            if (Ch) {
                *(__half2*)(Ch + (size_t)m * N + n) = __floats2half2_rn(v0, v1);
                *(__half2*)(Ch + (size_t)(m + 8) * N + n) = __floats2half2_rn(v2, v3);
            } else {
                *(float2*)(C + (size_t)m * N + n) = make_float2(v0, v1);
                *(float2*)(C + (size_t)(m + 8) * N + n) = make_float2(v2, v3);
            }
        }
    }
}

__global__ void detect_kernel(const void* ids) {
    const int* p = (const int*)ids;
    int nz = 0;
    for (int i = 0; i < 256; i += 2)
        if (p[i + 1] != 0) nz++;
    g_ids64 = (nz == 0) ? 1 : 0;
}
__global__ void embed_kernel(const void* ids, const float* __restrict__ emb,
                             const float* __restrict__ pe) {
    int row = blockIdx.x;
    int d = threadIdx.x * 4;
    long long id;
    if (g_ids64) id = ((const long long*)ids)[row];
    else         id = (long long)((const int*)ids)[row];
    int l = row & (LL - 1);
    float4 e = *(const float4*)(emb + (size_t)id * DD + d);
    float4 p = *(const float4*)(pe + (size_t)l * DD + d);
    float v[4] = {e.x * 32.f + p.x, e.y * 32.f + p.y, e.z * 32.f + p.z, e.w * 32.f + p.w};
    size_t base = (size_t)row * DD + d;
    #pragma unroll
    for (int j = 0; j < 4; j++) {
        f16 h, lo;
        f2hl(v[j], h, lo);
        g_xhi[base + j] = h;
        g_xlo[base + j] = lo;
    }
}
// transpose+convert with scale (optional sum of two inputs): out[(nOff+c)*R + r] fp16
__global__ void tconv(const float* __restrict__ in, const float* __restrict__ in2,
                      f16* __restrict__ oh, int R, int C, int nOff, float scale) {
    __shared__ float tl[32][33];
    int n0 = blockIdx.x * 32, k0 = blockIdx.y * 32;
    int tx = threadIdx.x, ty = threadIdx.y;
    #pragma unroll
    for (int i = 0; i < 4; i++) {
        size_t idx = (size_t)(k0 + ty + i * 8) * C + n0 + tx;
        float v = in[idx];
        if (in2) v += in2[idx];
        tl[ty + i * 8][tx] = v * scale;
    }
    __syncthreads();
    #pragma unroll
    for (int i = 0; i < 4; i++) {
        int nn = ty + i * 8;
        oh[(size_t)(nOff + n0 + nn) * R + k0 + tx] = __float2half(tl[tx][nn]);
    }
}
__global__ void conv_h(const float* __restrict__ in, f16* __restrict__ oh) {
    size_t i = ((size_t)blockIdx.x * 256 + threadIdx.x) * 4;
    float4 v = *(const float4*)(in + i);
    oh[i + 0] = __float2half(v.x);
    oh[i + 1] = __float2half(v.y);
    oh[i + 2] = __float2half(v.z);
    oh[i + 3] = __float2half(v.w);
}
__global__ void concat_bias(const float* __restrict__ bq, const float* __restrict__ bk,
                            const float* __restrict__ bv) {
    int t = threadIdx.x, s = blockIdx.x;
    const float* src = (s == 0) ? bq : (s == 1) ? bk : bv;
    g_bqkv[s * DD + t] = src[t] * ((s == 0) ? 0.125f : 1.f);
}
__global__ __launch_bounds__(256) void bff_part(const float* __restrict__ b1,
                                                const float* __restrict__ w2) {
    int y = blockIdx.x, t = threadIdx.x;
    float s[4] = {0.f, 0.f, 0.f, 0.f};
    for (int f = y * 128; f < y * 128 + 128; f++) {
        float bv = b1[f];
        const float* wr = w2 + (size_t)f * DD;
        #pragma unroll
        for (int j = 0; j < 4; j++) s[j] = fmaf(bv, wr[t + j * 256], s[j]);
    }
    #pragma unroll
    for (int j = 0; j < 4; j++) g_bffpart[y * DD + t + j * 256] = s[j];
}
__global__ __launch_bounds__(256) void bff_reduce(const float* __restrict__ b2) {
    int d = blockIdx.x * 256 + threadIdx.x;
    float s = b2[d];
    for (int y = 0; y < 32; y++) s += g_bffpart[y * DD + d];
    g_bff[d] = s;
}

// ---------------- HMMA flash attention (batch 0) ----------------
// grid (8 m-tiles of 64, 16 heads), 128 threads (4 warps, one m16 each).
// qkv fp16 [512][3072] (q pre-scaled by 1/8). Online softmax on mma fragments.
__global__ __launch_bounds__(128) void flash_mma(const f16* __restrict__ qkv) {
    __shared__ __align__(16) char fsm[3 * 64 * 144];
    const int OFQ = 0, OFK = 64 * 144, OFV = 2 * 64 * 144;
    uint32_t sb = s2u(fsm);
    int h = blockIdx.y, m0 = blockIdx.x * 64;
    int t = threadIdx.x, lane = t & 31, w = t >> 5;

    // Q tile [64 m][64 dk] fp16, pitch 144
    for (int i = t; i < 512; i += 128) {
        int r = i >> 3, c = i & 7;
        *(uint4*)(fsm + OFQ + r * 144 + c * 16) =
            *(const uint4*)(qkv + (size_t)(m0 + r) * (3 * DD) + h * 64 + c * 8);
    }
    __syncthreads();
    uint32_t qa[4][4];
    {
        uint32_t qoff = (uint32_t)((w * 16 + (lane & 15)) * 144 + ((lane >> 4) << 4));
        #pragma unroll
        for (int kt = 0; kt < 4; kt++) ldmx4(qa[kt], sb + OFQ + qoff + kt * 32);
    }

    const uint32_t brow = (uint32_t)((lane & 7) + ((lane & 16) ? 8 : 0));
    const uint32_t bcol = ((lane & 8) ? 16u : 0u);

    float m_run0 = -1e30f, m_run1 = -1e30f, l_run0 = 0.f, l_run1 = 0.f;
    float oacc[8][4];
    #pragma unroll
    for (int d = 0; d < 8; d++)
        #pragma unroll
        for (int r = 0; r < 4; r++) oacc[d][r] = 0.f;

    for (int kb = 0; kb < LL; kb += 64) {
        __syncthreads();
        // K tile [64 key][64 dk]
        for (int i = t; i < 512; i += 128) {
            int r = i >> 3, c = i & 7;
            *(uint4*)(fsm + OFK + r * 144 + c * 16) =
                *(const uint4*)(qkv + (size_t)(kb + r) * (3 * DD) + DD + h * 64 + c * 8);
        }
        // V transposed: Vt[dk][key]
        for (int i = t; i < 2048; i += 128) {
            int key = i >> 5, d2 = i & 31;
            __half2 v2 = *(const __half2*)(qkv + (size_t)(kb + key) * (3 * DD) + 2 * DD + h * 64 + 2 * d2);
            *(f16*)(fsm + OFV + (2 * d2) * 144 + key * 2) = __low2half(v2);
            *(f16*)(fsm + OFV + (2 * d2 + 1) * 144 + key * 2) = __high2half(v2);
        }
        __syncthreads();

        // S = Q @ K^T  (m16 x n64 per warp)
        float sacc[8][4];
        #pragma unroll
        for (int j = 0; j < 8; j++)
            #pragma unroll
            for (int r = 0; r < 4; r++) sacc[j][r] = 0.f;
        #pragma unroll
        for (int kt = 0; kt < 4; kt++) {
            #pragma unroll
            for (int ng = 0; ng < 4; ng++) {
                uint32_t kbf[4];
                ldmx4(kbf, sb + OFK + (uint32_t)(ng * 16) * 144 + brow * 144 + bcol + kt * 32);
                mmah(sacc[ng * 2 + 0], qa[kt], &kbf[0]);
                mmah(sacc[ng * 2 + 1], qa[kt], &kbf[2]);
            }
        }

        // online softmax (rows r = lane/4 and r+8; quad lanes share a row)
        float ml0 = -1e30f, ml1 = -1e30f;
        #pragma unroll
        for (int j = 0; j < 8; j++) {
            ml0 = fmaxf(ml0, fmaxf(sacc[j][0], sacc[j][1]));
            ml1 = fmaxf(ml1, fmaxf(sacc[j][2], sacc[j][3]));
        }
        #pragma unroll
        for (int o = 1; o <= 2; o <<= 1) {
            ml0 = fmaxf(ml0, __shfl_xor_sync(0xffffffffu, ml0, o));
            ml1 = fmaxf(ml1, __shfl_xor_sync(0xffffffffu, ml1, o));
        }
        float mn0 = fmaxf(m_run0, ml0), mn1 = fmaxf(m_run1, ml1);
        float corr0 = __expf(m_run0 - mn0), corr1 = __expf(m_run1 - mn1);
        float rs0 = 0.f, rs1 = 0.f;
        uint32_t pfrag[4][4];
        #pragma unroll
        for (int kt = 0; kt < 4; kt++) {
            #pragma unroll
            for (int hh = 0; hh < 2; hh++) {
                int j = kt * 2 + hh;
                float p0 = __expf(sacc[j][0] - mn0), p1 = __expf(sacc[j][1] - mn0);
                float p2 = __expf(sacc[j][2] - mn1), p3 = __expf(sacc[j][3] - mn1);
                rs0 += p0 + p1;
                rs1 += p2 + p3;
                __half2 pa = __floats2half2_rn(p0, p1);
                __half2 pb = __floats2half2_rn(p2, p3);
                pfrag[kt][hh * 2 + 0] = *(uint32_t*)&pa;
                pfrag[kt][hh * 2 + 1] = *(uint32_t*)&pb;
            }
        }
        // NOTE: a-frag order must be (row r k0-7, row r+8 k0-7, row r k8-15, row r+8 k8-15)
        // pfrag[kt] = {j0:rowr, j0:rowr+8, j1:rowr, j1:rowr+8} where j1 = keys+8 -> matches a0,a1,a2,a3.
        #pragma unroll
        for (int o = 1; o <= 2; o <<= 1) {
            rs0 += __shfl_xor_sync(0xffffffffu, rs0, o);
            rs1 += __shfl_xor_sync(0xffffffffu, rs1, o);
        }
        l_run0 = l_run0 * corr0 + rs0;
        l_run1 = l_run1 * corr1 + rs1;
        m_run0 = mn0;
        m_run1 = mn1;
        #pragma unroll
        for (int d = 0; d < 8; d++) {
            oacc[d][0] *= corr0; oacc[d][1] *= corr0;
            oacc[d][2] *= corr1; oacc[d][3] *= corr1;
        }
        // O += P @ V  (k = key, n = dk)
        #pragma unroll
        for (int kt = 0; kt < 4; kt++) {
            #pragma unroll
            for (int ng = 0; ng < 4; ng++) {
                uint32_t vb[4];
                ldmx4(vb, sb + OFV + (uint32_t)(ng * 16) * 144 + brow * 144 + bcol + kt * 32);
                mmah(oacc[ng * 2 + 0], pfrag[kt], &vb[0]);
                mmah(oacc[ng * 2 + 1], pfrag[kt], &vb[2]);
            }
        }
    }

    float inv0 = 1.f / l_run0, inv1 = 1.f / l_run1;
    int m = m0 + w * 16 + (lane >> 2);
    #pragma unroll
    for (int d = 0; d < 8; d++) {
        int n = h * 64 + d * 8 + 2 * (lane & 3);
        *(__half2*)(g_ohi + (size_t)m * DD + n) = __floats2half2_rn(oacc[d][0] * inv0, oacc[d][1] * inv0);
        *(__half2*)(g_ohi + (size_t)(m + 8) * DD + n) = __floats2half2_rn(oacc[d][2] * inv1, oacc[d][3] * inv1);
    }
}

__global__ __launch_bounds__(256) void add_ln(f16* __restrict__ xhi, f16* __restrict__ xlo,
                                              const f16* __restrict__ addh,
                                              const float* __restrict__ add,
                                              const float* __restrict__ add2,
                                              const float* __restrict__ cbias, int addMask,
                                              const float* __restrict__ g,
                                              const float* __restrict__ b) {
    int row = blockIdx.x, t = threadIdx.x;
    size_t base = (size_t)row * DD + t * 4;
    __half2 h0 = *(const __half2*)(xhi + base);
    __half2 h1 = *(const __half2*)(xhi + base + 2);
    __half2 l0 = *(const __half2*)(xlo + base);
    __half2 l1 = *(const __half2*)(xlo + base + 2);
    size_t aoff = (size_t)(row & addMask) * DD + t * 4;
    float4 av;
    if (addh) {
        __half2 a0 = *(const __half2*)(addh + aoff);
        __half2 a1 = *(const __half2*)(addh + aoff + 2);
        av = make_float4(__half2float(a0.x), __half2float(a0.y),
                         __half2float(a1.x), __half2float(a1.y));
    } else {
        av = *(const float4*)(add + aoff);
        if (add2) {
            float4 a2 = *(const float4*)(add2 + aoff);
            av.x += a2.x; av.y += a2.y; av.z += a2.z; av.w += a2.w;
        }
        if (cbias) {
            float4 cb = *(const float4*)(cbias + t * 4);
            av.x += cb.x; av.y += cb.y; av.z += cb.z; av.w += cb.w;
        }
    }
    float v0 = __half2float(h0.x) + __half2float(l0.x) + av.x;
    float v1 = __half2float(h0.y) + __half2float(l0.y) + av.y;
    float v2 = __half2float(h1.x) + __half2float(l1.x) + av.z;
    float v3 = __half2float(h1.y) + __half2float(l1.y) + av.w;
    float mean = blockSum(v0 + v1 + v2 + v3) * (1.f / DD);
    float d0 = v0 - mean, d1 = v1 - mean, d2 = v2 - mean, d3 = v3 - mean;
    float var = blockSum(d0 * d0 + d1 * d1 + d2 * d2 + d3 * d3) * (1.f / DD);
    float rs = rsqrtf(var + 1e-5f);
    float4 gv = *(const float4*)(g + t * 4);
    float4 bv = *(const float4*)(b + t * 4);
    float o0 = d0 * rs * gv.x + bv.x, o1 = d1 * rs * gv.y + bv.y;
    float o2 = d2 * rs * gv.z + bv.z, o3 = d3 * rs * gv.w + bv.w;
    f16 hh, ll;
    f2hl(o0, hh, ll); xhi[base + 0] = hh; xlo[base + 0] = ll;
    f2hl(o1, hh, ll); xhi[base + 1] = hh; xlo[base + 1] = ll;
    f2hl(o2, hh, ll); xhi[base + 2] = hh; xlo[base + 2] = ll;
    f2hl(o3, hh, ll); xhi[base + 3] = hh; xlo[base + 3] = ll;
}

__global__ __launch_bounds__(256) void pool_mean() {
    int b = blockIdx.y;
    int d = blockIdx.x * 256 + threadIdx.x;
    size_t base = (size_t)b * LL * DD + d;
    float s = 0.f;
    for (int l = 0; l < LL; l++)
        s += __half2float(g_xhi[base + (size_t)l * DD]) +
             __half2float(g_xlo[base + (size_t)l * DD]);
    g_pooled[b * DD + d] = s * (1.f / LL);
}
__global__ __launch_bounds__(256) void logits_kernel(const float* __restrict__ wf,
                                                     const float* __restrict__ bf,
                                                     float* __restrict__ out) {
    int b = blockIdx.x / CC, c = blockIdx.x % CC;
    float s = 0.f;
    for (int d = threadIdx.x; d < DD; d += 256)
        s += g_pooled[b * DD + d] * wf[(size_t)d * CC + c];
    s = blockSum(s);
    if (threadIdx.x == 0) out[b * CC + c] = s + bf[c];
}

extern "C" void kernel_launch(void* const* d_in, const int* in_sizes, int n_in,
                              void* d_out, int out_size) {
    const void*  ids = d_in[0];
    const float* emb = (const float*)d_in[1];
    const float* pe  = (const float*)d_in[2];
    const float* wq  = (const float*)d_in[3];
    const float* bq  = (const float*)d_in[4];
    const float* wk  = (const float*)d_in[5];
    const float* bk  = (const float*)d_in[6];
    const float* wv  = (const float*)d_in[7];
    const float* bv  = (const float*)d_in[8];
    const float* wo  = (const float*)d_in[9];
    const float* bo  = (const float*)d_in[10];
    const float* w1  = (const float*)d_in[11];
    const float* b1  = (const float*)d_in[12];
    const float* w2  = (const float*)d_in[13];
    const float* b2  = (const float*)d_in[14];
    const float* g1  = (const float*)d_in[15];
    const float* be1 = (const float*)d_in[16];
    const float* g2  = (const float*)d_in[17];
    const float* be2 = (const float*)d_in[18];
    const float* wf  = (const float*)d_in[19];
    const float* bf  = (const float*)d_in[20];
    float* out = (float*)d_out;

    const int SM128 = (128 + 128) * PITCH * 2;
    const int SM64  = (64 + 128) * PITCH * 2;
    cudaFuncSetAttribute(gemm_tc<128>, cudaFuncAttributeMaxDynamicSharedMemorySize, SM128);
    cudaFuncSetAttribute(gemm_tc<64>, cudaFuncAttributeMaxDynamicSharedMemorySize, SM64);

    float *src2, *Wff, *bff, *bqkv;
    f16 *xhi, *xlo, *tmph, *qkvh, *ohi, *wqkvT, *woT, *WffT, *w1h, *w2T;
    cudaGetSymbolAddress((void**)&src2, g_src2);
    cudaGetSymbolAddress((void**)&Wff, g_Wff);
    cudaGetSymbolAddress((void**)&bff, g_bff);
    cudaGetSymbolAddress((void**)&bqkv, g_bqkv);
    cudaGetSymbolAddress((void**)&xhi, g_xhi);
    cudaGetSymbolAddress((void**)&xlo, g_xlo);
    cudaGetSymbolAddress((void**)&tmph, g_tmph);
    cudaGetSymbolAddress((void**)&qkvh, g_qkvh);
    cudaGetSymbolAddress((void**)&ohi, g_ohi);
    cudaGetSymbolAddress((void**)&wqkvT, g_wqkvT);
    cudaGetSymbolAddress((void**)&woT, g_woT);
    cudaGetSymbolAddress((void**)&WffT, g_WffT);
    cudaGetSymbolAddress((void**)&w1h, g_w1h);
    cudaGetSymbolAddress((void**)&w2T, g_w2T);

    detect_kernel<<<1, 1>>>(ids);
    embed_kernel<<<BB * LL, 256>>>(ids, emb, pe);

    dim3 tb(32, 8);
    tconv<<<dim3(32, 32), tb>>>(wq, nullptr, wqkvT, DD, DD, 0, 0.125f);
    tconv<<<dim3(32, 32), tb>>>(wk, nullptr, wqkvT, DD, DD, DD, 1.f);
    tconv<<<dim3(32, 32), tb>>>(wv, nullptr, wqkvT, DD, DD, 2 * DD, 1.f);
    tconv<<<dim3(32, 32), tb>>>(wo, nullptr, woT, DD, DD, 0, 1.f);
    tconv<<<dim3(32, 128), tb>>>(w2, nullptr, w2T, FF, DD, 0, 1.f);
    conv_h<<<(DD * FF) / 1024, 256>>>(w1, w1h);
    concat_bias<<<3, 1024>>>(bq, bk, bv);
    bff_part<<<32, 256>>>(b1, w2);
    bff_reduce<<<4, 256>>>(b2);
    gemm_tc<64><<<dim3(DD / 128, DD / 64, 2), 128, SM64>>>(w1h, w2T, nullptr,
                                                           Wff, nullptr, FF / 2, FF, DD, DD * DD);
    tconv<<<dim3(32, 32), tb>>>(Wff, Wff + (size_t)DD * DD, WffT, DD, DD, 0, 1.f);

    for (int layer = 0; layer < NLAYER; layer++) {
        gemm_tc<64><<<dim3(3 * DD / 128, LL / 64, 1), 128, SM64>>>(xhi, wqkvT, bqkv,
                                                                   nullptr, qkvh, DD, DD, 3 * DD, 0);
        flash_mma<<<dim3(8, HH), 128>>>(qkvh);
        gemm_tc<64><<<dim3(DD / 128, LL / 64, 2), 128, SM64>>>(ohi, woT, nullptr,
                                                               src2, nullptr, DD / 2, DD, DD, LL * DD);
        add_ln<<<BB * LL, 256>>>(xhi, xlo, nullptr, src2, src2 + (size_t)LL * DD, bo,
                                 LL - 1, g1, be1);
        gemm_tc<128><<<dim3(DD / 128, (BB * LL) / 128, 1), 256, SM128>>>(xhi, WffT, bff,
                                                                         nullptr, tmph, DD, DD, DD, 0);
        add_ln<<<BB * LL, 256>>>(xhi, xlo, tmph, nullptr, nullptr, nullptr,
                                 BB * LL - 1, g2, be2);
    }

    pool_mean<<<dim3(DD / 256, BB), 256>>>();
    logits_kernel<<<BB * CC, 256>>>(wf, bf, out);
}

// round 10
// speedup vs baseline: 4.8633x; 1.0673x over previous
#include <cuda_runtime.h>
#include <cuda_bf16.h>
#include <cuda_fp16.h>
#include <cstdint>

#define BB 16
#define LL 512
#define DD 1024
#define HH 16
#define FF 4096
#define CC 10
#define NLAYER 6

typedef __half f16;

__device__ f16 g_xhi[BB * LL * DD];
__device__ f16 g_xlo[BB * LL * DD];
__device__ f16 g_tmph[BB * LL * DD];
__device__ f16 g_qkvh[LL * 3 * DD];
__device__ f16 g_ohi[LL * DD];
__device__ float g_src2[2 * LL * DD];
__device__ float g_Wff[2 * DD * DD];
__device__ float g_bff[DD];
__device__ float g_bffpart[32 * DD];
__device__ float g_bqkv[3 * DD];
__device__ float g_pooled[BB * DD];
__device__ int g_ids64;
__device__ f16 g_wqkvT[3 * DD * DD];
__device__ f16 g_woT[DD * DD];
__device__ f16 g_WffT[DD * DD];
__device__ f16 g_w1h[DD * FF];
__device__ f16 g_w2T[DD * FF];

__device__ __forceinline__ void f2hl(float v, f16& h, f16& l) {
    h = __float2half(v);
    l = __float2half(v - __half2float(h));
}
__device__ __forceinline__ float warpSum(float v) {
    #pragma unroll
    for (int o = 16; o > 0; o >>= 1) v += __shfl_xor_sync(0xffffffffu, v, o);
    return v;
}
__device__ __forceinline__ float blockSum(float v) {
    __shared__ float sm[32];
    int lane = threadIdx.x & 31, w = threadIdx.x >> 5;
    v = warpSum(v);
    if (lane == 0) sm[w] = v;
    __syncthreads();
    if (w == 0) {
        float x = (lane < (int)(blockDim.x >> 5)) ? sm[lane] : 0.f;
        x = warpSum(x);
        if (lane == 0) sm[0] = x;
    }
    __syncthreads();
    float r = sm[0];
    __syncthreads();
    return r;
}

__device__ __forceinline__ uint32_t s2u(const void* p) {
    uint32_t a;
    asm("{ .reg .u64 t; cvta.to.shared.u64 t, %1; cvt.u32.u64 %0, t; }" : "=r"(a) : "l"(p));
    return a;
}
__device__ __forceinline__ void cpa(uint32_t dst, const void* src) {
    asm volatile("cp.async.cg.shared.global [%0], [%1], 16;" :: "r"(dst), "l"(src));
}
__device__ __forceinline__ void cpcommit() { asm volatile("cp.async.commit_group;"); }
template <int N> __device__ __forceinline__ void cpwait() {
    asm volatile("cp.async.wait_group %0;" :: "n"(N));
}
__device__ __forceinline__ void ldmx4(uint32_t* r, uint32_t a) {
    asm volatile("ldmatrix.sync.aligned.m8n8.x4.shared.b16 {%0,%1,%2,%3}, [%4];"
                 : "=r"(r[0]), "=r"(r[1]), "=r"(r[2]), "=r"(r[3]) : "r"(a));
}
__device__ __forceinline__ void mmah(float* d, const uint32_t* a, const uint32_t* b) {
    asm volatile(
        "mma.sync.aligned.m16n8k16.row.col.f32.f16.f16.f32 "
        "{%0,%1,%2,%3}, {%4,%5,%6,%7}, {%8,%9}, {%0,%1,%2,%3};"
        : "+f"(d[0]), "+f"(d[1]), "+f"(d[2]), "+f"(d[3])
        : "r"(a[0]), "r"(a[1]), "r"(a[2]), "r"(a[3]), "r"(b[0]), "r"(b[1]));
}

#define PITCH 80

// C[M,N] = A @ B^T + bias ; single fp16 operands; optional fp16 output (Ch)
template <int MT>
__global__ __launch_bounds__(MT * 2, (MT == 64) ? 4 : 2) void gemm_tc(
    const f16* __restrict__ A, const f16* __restrict__ B,
    const float* __restrict__ bias, float* __restrict__ C, f16* __restrict__ Ch,
    int Kiter, int Kstride, int N, int Czoff) {
    constexpr int THREADS = MT * 2;
    constexpr int OFS_B = MT * PITCH;
    constexpr int STB = (MT + 128) * PITCH;
    extern __shared__ char smem[];
    uint32_t sb = s2u(smem);
    const int t = threadIdx.x, lane = t & 31, wid = t >> 5;
    const int m0 = blockIdx.y * MT, n0 = blockIdx.x * 128;
    const int wr = wid >> 2, wc = wid & 3;
    const size_t kz = (size_t)blockIdx.z * Kiter;
    if (C) C += (size_t)blockIdx.z * Czoff;
    const int NKB = Kiter / 32;

    float acc[4][4][4];
    #pragma unroll
    for (int i = 0; i < 4; i++)
        #pragma unroll
        for (int j = 0; j < 4; j++)
            #pragma unroll
            for (int r = 0; r < 4; r++) acc[i][j][r] = 0.f;

    const uint32_t aoff = (uint32_t)((wr * 64 + (lane & 15)) * PITCH + ((lane >> 4) << 4));
    const int brow = wc * 32 + (lane & 7) + ((lane & 16) ? 8 : 0);
    const uint32_t boff = (uint32_t)(brow * PITCH + ((lane & 8) ? 16 : 0));

    auto load_stage = [&](int kb0, uint32_t base) {
        #pragma unroll
        for (int idx = t; idx < MT * 4; idx += THREADS) {
            int row = idx >> 2, c = idx & 3;
            uint32_t so = (uint32_t)(row * PITCH + c * 16);
            cpa(base + so, A + (size_t)(m0 + row) * Kstride + kz + kb0 + c * 8);
        }
        #pragma unroll
        for (int idx = t; idx < 512; idx += THREADS) {
            int row = idx >> 2, c = idx & 3;
            uint32_t so = (uint32_t)(row * PITCH + c * 16);
            cpa(base + OFS_B + so, B + (size_t)(n0 + row) * Kstride + kz + kb0 + c * 8);
        }
        cpcommit();
    };

    load_stage(0, sb);

    for (int kb = 0; kb < NKB; kb++) {
        int cur = kb & 1;
        if (kb + 1 < NKB) {
            load_stage((kb + 1) * 32, sb + (uint32_t)(cur ^ 1) * STB);
            cpwait<1>();
        } else {
            cpwait<0>();
        }
        __syncthreads();
        uint32_t base = sb + (uint32_t)cur * STB;
        #pragma unroll
        for (int ks = 0; ks < 2; ks++) {
            uint32_t kbyte = (uint32_t)(ks * 32);
            uint32_t ah[4][4], bh[2][4];
            #pragma unroll
            for (int mt = 0; mt < 4; mt++)
                ldmx4(ah[mt], base + aoff + (uint32_t)(mt * 16 * PITCH) + kbyte);
            #pragma unroll
            for (int ng = 0; ng < 2; ng++)
                ldmx4(bh[ng], base + OFS_B + boff + (uint32_t)(ng * 16 * PITCH) + kbyte);
            #pragma unroll
            for (int mt = 0; mt < 4; mt++)
                #pragma unroll
                for (int nt = 0; nt < 4; nt++)
                    mmah(acc[mt][nt], ah[mt], &bh[nt >> 1][(nt & 1) * 2]);
        }
        __syncthreads();
    }

    #pragma unroll
    for (int mt = 0; mt < 4; mt++) {
        int m = m0 + wr * 64 + mt * 16 + (lane >> 2);
        #pragma unroll
        for (int nt = 0; nt < 4; nt++) {
            int n = n0 + wc * 32 + nt * 8 + (lane & 3) * 2;
            float b0 = 0.f, b1 = 0.f;
            if (bias) { b0 = bias[n]; b1 = bias[n + 1]; }
            float v0 = acc[mt][nt][0] + b0, v1 = acc[mt][nt][1] + b1;
            float v2 = acc[mt][nt][2] + b0, v3 = acc[mt][nt][3] + b1;
            if (Ch) {
                *(__half2*)(Ch + (size_t)m * N + n) = __floats2half2_rn(v0, v1);
                *(__half2*)(Ch + (size_t)(m + 8) * N + n) = __floats2half2_rn(v2, v3);
            } else {
                *(float2*)(C + (size_t)m * N + n) = make_float2(v0, v1);
                *(float2*)(C + (size_t)(m + 8) * N + n) = make_float2(v2, v3);
            }
        }
    }
}

__global__ void detect_kernel(const void* ids) {
    const int* p = (const int*)ids;
    int nz = 0;
    for (int i = 0; i < 256; i += 2)
        if (p[i + 1] != 0) nz++;
    g_ids64 = (nz == 0) ? 1 : 0;
}
__global__ void embed_kernel(const void* ids, const float* __restrict__ emb,
                             const float* __restrict__ pe) {
    int row = blockIdx.x;
    int d = threadIdx.x * 4;
    long long id;
    if (g_ids64) id = ((const long long*)ids)[row];
    else         id = (long long)((const int*)ids)[row];
    int l = row & (LL - 1);
    float4 e = *(const float4*)(emb + (size_t)id * DD + d);
    float4 p = *(const float4*)(pe + (size_t)l * DD + d);
    float v[4] = {e.x * 32.f + p.x, e.y * 32.f + p.y, e.z * 32.f + p.z, e.w * 32.f + p.w};
    size_t base = (size_t)row * DD + d;
    #pragma unroll
    for (int j = 0; j < 4; j++) {
        f16 h, lo;
        f2hl(v[j], h, lo);
        g_xhi[base + j] = h;
        g_xlo[base + j] = lo;
    }
}
__global__ void tconv(const float* __restrict__ in, const float* __restrict__ in2,
                      f16* __restrict__ oh, int R, int C, int nOff, float scale) {
    __shared__ float tl[32][33];
    int n0 = blockIdx.x * 32, k0 = blockIdx.y * 32;
    int tx = threadIdx.x, ty = threadIdx.y;
    #pragma unroll
    for (int i = 0; i < 4; i++) {
        size_t idx = (size_t)(k0 + ty + i * 8) * C + n0 + tx;
        float v = in[idx];
        if (in2) v += in2[idx];
        tl[ty + i * 8][tx] = v * scale;
    }
    __syncthreads();
    #pragma unroll
    for (int i = 0; i < 4; i++) {
        int nn = ty + i * 8;
        oh[(size_t)(nOff + n0 + nn) * R + k0 + tx] = __float2half(tl[tx][nn]);
    }
}
__global__ void conv_h(const float* __restrict__ in, f16* __restrict__ oh) {
    size_t i = ((size_t)blockIdx.x * 256 + threadIdx.x) * 4;
    float4 v = *(const float4*)(in + i);
    oh[i + 0] = __float2half(v.x);
    oh[i + 1] = __float2half(v.y);
    oh[i + 2] = __float2half(v.z);
    oh[i + 3] = __float2half(v.w);
}
__global__ void concat_bias(const float* __restrict__ bq, const float* __restrict__ bk,
                            const float* __restrict__ bv) {
    int t = threadIdx.x, s = blockIdx.x;
    const float* src = (s == 0) ? bq : (s == 1) ? bk : bv;
    g_bqkv[s * DD + t] = src[t] * ((s == 0) ? 0.125f : 1.f);
}
__global__ __launch_bounds__(256) void bff_part(const float* __restrict__ b1,
                                                const float* __restrict__ w2) {
    int y = blockIdx.x, t = threadIdx.x;
    float s[4] = {0.f, 0.f, 0.f, 0.f};
    for (int f = y * 128; f < y * 128 + 128; f++) {
        float bv = b1[f];
        const float* wr = w2 + (size_t)f * DD;
        #pragma unroll
        for (int j = 0; j < 4; j++) s[j] = fmaf(bv, wr[t + j * 256], s[j]);
    }
    #pragma unroll
    for (int j = 0; j < 4; j++) g_bffpart[y * DD + t + j * 256] = s[j];
}
__global__ __launch_bounds__(256) void bff_reduce(const float* __restrict__ b2) {
    int d = blockIdx.x * 256 + threadIdx.x;
    float s = b2[d];
    for (int y = 0; y < 32; y++) s += g_bffpart[y * DD + d];
    g_bff[d] = s;
}

// ---------------- HMMA flash attention (batch 0) ----------------
// grid (16 m-tiles of 32, 16 heads), 64 threads (2 warps, one m16 each).
__global__ __launch_bounds__(64) void flash_mma(const f16* __restrict__ qkv) {
    __shared__ __align__(16) char fsm[(32 + 64 + 64) * 144];
    const int OFQ = 0, OFK = 32 * 144, OFV = (32 + 64) * 144;
    uint32_t sb = s2u(fsm);
    int h = blockIdx.y, m0 = blockIdx.x * 32;
    int t = threadIdx.x, lane = t & 31, w = t >> 5;

    // Q tile [32 m][64 dk] fp16, pitch 144
    for (int i = t; i < 256; i += 64) {
        int r = i >> 3, c = i & 7;
        *(uint4*)(fsm + OFQ + r * 144 + c * 16) =
            *(const uint4*)(qkv + (size_t)(m0 + r) * (3 * DD) + h * 64 + c * 8);
    }
    __syncthreads();
    uint32_t qa[4][4];
    {
        uint32_t qoff = (uint32_t)((w * 16 + (lane & 15)) * 144 + ((lane >> 4) << 4));
        #pragma unroll
        for (int kt = 0; kt < 4; kt++) ldmx4(qa[kt], sb + OFQ + qoff + kt * 32);
    }

    const uint32_t brow = (uint32_t)((lane & 7) + ((lane & 16) ? 8 : 0));
    const uint32_t bcol = ((lane & 8) ? 16u : 0u);

    float m_run0 = -1e30f, m_run1 = -1e30f, l_run0 = 0.f, l_run1 = 0.f;
    float oacc[8][4];
    #pragma unroll
    for (int d = 0; d < 8; d++)
        #pragma unroll
        for (int r = 0; r < 4; r++) oacc[d][r] = 0.f;

    for (int kb = 0; kb < LL; kb += 64) {
        __syncthreads();
        // K tile [64 key][64 dk]
        for (int i = t; i < 512; i += 64) {
            int r = i >> 3, c = i & 7;
            *(uint4*)(fsm + OFK + r * 144 + c * 16) =
                *(const uint4*)(qkv + (size_t)(kb + r) * (3 * DD) + DD + h * 64 + c * 8);
        }
        // V transposed: Vt[dk][key]
        for (int i = t; i < 2048; i += 64) {
            int key = i >> 5, d2 = i & 31;
            __half2 v2 = *(const __half2*)(qkv + (size_t)(kb + key) * (3 * DD) + 2 * DD + h * 64 + 2 * d2);
            *(f16*)(fsm + OFV + (2 * d2) * 144 + key * 2) = __low2half(v2);
            *(f16*)(fsm + OFV + (2 * d2 + 1) * 144 + key * 2) = __high2half(v2);
        }
        __syncthreads();

        // S = Q @ K^T  (m16 x n64 per warp)
        float sacc[8][4];
        #pragma unroll
        for (int j = 0; j < 8; j++)
            #pragma unroll
            for (int r = 0; r < 4; r++) sacc[j][r] = 0.f;
        #pragma unroll
        for (int kt = 0; kt < 4; kt++) {
            #pragma unroll
            for (int ng = 0; ng < 4; ng++) {
                uint32_t kbf[4];
                ldmx4(kbf, sb + OFK + (uint32_t)(ng * 16) * 144 + brow * 144 + bcol + kt * 32);
                mmah(sacc[ng * 2 + 0], qa[kt], &kbf[0]);
                mmah(sacc[ng * 2 + 1], qa[kt], &kbf[2]);
            }
        }

        // online softmax (rows r = lane/4 and r+8; quad lanes share a row)
        float ml0 = -1e30f, ml1 = -1e30f;
        #pragma unroll
        for (int j = 0; j < 8; j++) {
            ml0 = fmaxf(ml0, fmaxf(sacc[j][0], sacc[j][1]));
            ml1 = fmaxf(ml1, fmaxf(sacc[j][2], sacc[j][3]));
        }
        #pragma unroll
        for (int o = 1; o <= 2; o <<= 1) {
            ml0 = fmaxf(ml0, __shfl_xor_sync(0xffffffffu, ml0, o));
            ml1 = fmaxf(ml1, __shfl_xor_sync(0xffffffffu, ml1, o));
        }
        float mn0 = fmaxf(m_run0, ml0), mn1 = fmaxf(m_run1, ml1);
        float corr0 = __expf(m_run0 - mn0), corr1 = __expf(m_run1 - mn1);
        float rs0 = 0.f, rs1 = 0.f;
        uint32_t pfrag[4][4];
        #pragma unroll
        for (int kt = 0; kt < 4; kt++) {
            #pragma unroll
            for (int hh = 0; hh < 2; hh++) {
                int j = kt * 2 + hh;
                float p0 = __expf(sacc[j][0] - mn0), p1 = __expf(sacc[j][1] - mn0);
                float p2 = __expf(sacc[j][2] - mn1), p3 = __expf(sacc[j][3] - mn1);
                rs0 += p0 + p1;
                rs1 += p2 + p3;
                __half2 pa = __floats2half2_rn(p0, p1);
                __half2 pb = __floats2half2_rn(p2, p3);
                pfrag[kt][hh * 2 + 0] = *(uint32_t*)&pa;
                pfrag[kt][hh * 2 + 1] = *(uint32_t*)&pb;
            }
        }
        #pragma unroll
        for (int o = 1; o <= 2; o <<= 1) {
            rs0 += __shfl_xor_sync(0xffffffffu, rs0, o);
            rs1 += __shfl_xor_sync(0xffffffffu, rs1, o);
        }
        l_run0 = l_run0 * corr0 + rs0;
        l_run1 = l_run1 * corr1 + rs1;
        m_run0 = mn0;
        m_run1 = mn1;
        #pragma unroll
        for (int d = 0; d < 8; d++) {
            oacc[d][0] *= corr0; oacc[d][1] *= corr0;
            oacc[d][2] *= corr1; oacc[d][3] *= corr1;
        }
        // O += P @ V
        #pragma unroll
        for (int kt = 0; kt < 4; kt++) {
            #pragma unroll
            for (int ng = 0; ng < 4; ng++) {
                uint32_t vb[4];
                ldmx4(vb, sb + OFV + (uint32_t)(ng * 16) * 144 + brow * 144 + bcol + kt * 32);
                mmah(oacc[ng * 2 + 0], pfrag[kt], &vb[0]);
                mmah(oacc[ng * 2 + 1], pfrag[kt], &vb[2]);
            }
        }
    }

    float inv0 = 1.f / l_run0, inv1 = 1.f / l_run1;
    int m = m0 + w * 16 + (lane >> 2);
    #pragma unroll
    for (int d = 0; d < 8; d++) {
        int n = h * 64 + d * 8 + 2 * (lane & 3);
        *(__half2*)(g_ohi + (size_t)m * DD + n) = __floats2half2_rn(oacc[d][0] * inv0, oacc[d][1] * inv0);
        *(__half2*)(g_ohi + (size_t)(m + 8) * DD + n) = __floats2half2_rn(oacc[d][2] * inv1, oacc[d][3] * inv1);
    }
}

// ---------------- warp-per-row residual + LayerNorm ----------------
__global__ __launch_bounds__(256) void add_ln(f16* __restrict__ xhi, f16* __restrict__ xlo,
                                              const f16* __restrict__ addh,
                                              const float* __restrict__ add,
                                              const float* __restrict__ add2,
                                              const float* __restrict__ cbias, int addMask,
                                              const float* __restrict__ g,
                                              const float* __restrict__ b) {
    int row = blockIdx.x * 8 + (threadIdx.x >> 5);
    int lane = threadIdx.x & 31;
    size_t base = (size_t)row * DD;
    size_t abase = (size_t)(row & addMask) * DD;
    float v[32];
    #pragma unroll
    for (int c = 0; c < 4; c++) {
        int e0 = c * 256 + lane * 8;
        uint4 hv = *(const uint4*)(xhi + base + e0);
        uint4 lv = *(const uint4*)(xlo + base + e0);
        __half2* hp = (__half2*)&hv;
        __half2* lp = (__half2*)&lv;
        float a[8];
        if (addh) {
            uint4 av4 = *(const uint4*)(addh + abase + e0);
            __half2* ap = (__half2*)&av4;
            #pragma unroll
            for (int j = 0; j < 4; j++) {
                a[2 * j] = __half2float(ap[j].x);
                a[2 * j + 1] = __half2float(ap[j].y);
            }
        } else {
            float4 a0 = *(const float4*)(add + abase + e0);
            float4 a1 = *(const float4*)(add + abase + e0 + 4);
            a[0] = a0.x; a[1] = a0.y; a[2] = a0.z; a[3] = a0.w;
            a[4] = a1.x; a[5] = a1.y; a[6] = a1.z; a[7] = a1.w;
            if (add2) {
                float4 c0 = *(const float4*)(add2 + abase + e0);
                float4 c1 = *(const float4*)(add2 + abase + e0 + 4);
                a[0] += c0.x; a[1] += c0.y; a[2] += c0.z; a[3] += c0.w;
                a[4] += c1.x; a[5] += c1.y; a[6] += c1.z; a[7] += c1.w;
            }
            if (cbias) {
                float4 c0 = *(const float4*)(cbias + e0);
                float4 c1 = *(const float4*)(cbias + e0 + 4);
                a[0] += c0.x; a[1] += c0.y; a[2] += c0.z; a[3] += c0.w;
                a[4] += c1.x; a[5] += c1.y; a[6] += c1.z; a[7] += c1.w;
            }
        }
        #pragma unroll
        for (int j = 0; j < 4; j++) {
            v[c * 8 + 2 * j]     = __half2float(hp[j].x) + __half2float(lp[j].x) + a[2 * j];
            v[c * 8 + 2 * j + 1] = __half2float(hp[j].y) + __half2float(lp[j].y) + a[2 * j + 1];
        }
    }
    float s = 0.f;
    #pragma unroll
    for (int i = 0; i < 32; i++) s += v[i];
    float mean = warpSum(s) * (1.f / DD);
    float q = 0.f;
    #pragma unroll
    for (int i = 0; i < 32; i++) {
        float d = v[i] - mean;
        q += d * d;
    }
    float rstd = rsqrtf(warpSum(q) * (1.f / DD) + 1e-5f);
    #pragma unroll
    for (int c = 0; c < 4; c++) {
        int e0 = c * 256 + lane * 8;
        float4 g0 = *(const float4*)(g + e0);
        float4 g1 = *(const float4*)(g + e0 + 4);
        float4 b0 = *(const float4*)(b + e0);
        float4 b1 = *(const float4*)(b + e0 + 4);
        float gg[8] = {g0.x, g0.y, g0.z, g0.w, g1.x, g1.y, g1.z, g1.w};
        float bb[8] = {b0.x, b0.y, b0.z, b0.w, b1.x, b1.y, b1.z, b1.w};
        uint4 ho, lo4;
        __half2* hop = (__half2*)&ho;
        __half2* lop = (__half2*)&lo4;
        #pragma unroll
        for (int j = 0; j < 4; j++) {
            float o0 = (v[c * 8 + 2 * j] - mean) * rstd * gg[2 * j] + bb[2 * j];
            float o1 = (v[c * 8 + 2 * j + 1] - mean) * rstd * gg[2 * j + 1] + bb[2 * j + 1];
            f16 h0, l0, h1, l1;
            f2hl(o0, h0, l0);
            f2hl(o1, h1, l1);
            hop[j] = __halves2half2(h0, h1);
            lop[j] = __halves2half2(l0, l1);
        }
        *(uint4*)(xhi + base + e0) = ho;
        *(uint4*)(xlo + base + e0) = lo4;
    }
}

__global__ __launch_bounds__(256) void pool_mean() {
    int b = blockIdx.y;
    int d = blockIdx.x * 256 + threadIdx.x;
    size_t base = (size_t)b * LL * DD + d;
    float s = 0.f;
    for (int l = 0; l < LL; l++)
        s += __half2float(g_xhi[base + (size_t)l * DD]) +
             __half2float(g_xlo[base + (size_t)l * DD]);
    g_pooled[b * DD + d] = s * (1.f / LL);
}
__global__ __launch_bounds__(256) void logits_kernel(const float* __restrict__ wf,
                                                     const float* __restrict__ bf,
                                                     float* __restrict__ out) {
    int b = blockIdx.x / CC, c = blockIdx.x % CC;
    float s = 0.f;
    for (int d = threadIdx.x; d < DD; d += 256)
        s += g_pooled[b * DD + d] * wf[(size_t)d * CC + c];
    s = blockSum(s);
    if (threadIdx.x == 0) out[b * CC + c] = s + bf[c];
}

extern "C" void kernel_launch(void* const* d_in, const int* in_sizes, int n_in,
                              void* d_out, int out_size) {
    const void*  ids = d_in[0];
    const float* emb = (const float*)d_in[1];
    const float* pe  = (const float*)d_in[2];
    const float* wq  = (const float*)d_in[3];
    const float* bq  = (const float*)d_in[4];
    const float* wk  = (const float*)d_in[5];
    const float* bk  = (const float*)d_in[6];
    const float* wv  = (const float*)d_in[7];
    const float* bv  = (const float*)d_in[8];
    const float* wo  = (const float*)d_in[9];
    const float* bo  = (const float*)d_in[10];
    const float* w1  = (const float*)d_in[11];
    const float* b1  = (const float*)d_in[12];
    const float* w2  = (const float*)d_in[13];
    const float* b2  = (const float*)d_in[14];
    const float* g1  = (const float*)d_in[15];
    const float* be1 = (const float*)d_in[16];
    const float* g2  = (const float*)d_in[17];
    const float* be2 = (const float*)d_in[18];
    const float* wf  = (const float*)d_in[19];
    const float* bf  = (const float*)d_in[20];
    float* out = (float*)d_out;

    const int SM128 = (128 + 128) * PITCH * 2;
    const int SM64  = (64 + 128) * PITCH * 2;
    cudaFuncSetAttribute(gemm_tc<128>, cudaFuncAttributeMaxDynamicSharedMemorySize, SM128);
    cudaFuncSetAttribute(gemm_tc<64>, cudaFuncAttributeMaxDynamicSharedMemorySize, SM64);

    float *src2, *Wff, *bff, *bqkv;
    f16 *xhi, *xlo, *tmph, *qkvh, *ohi, *wqkvT, *woT, *WffT, *w1h, *w2T;
    cudaGetSymbolAddress((void**)&src2, g_src2);
    cudaGetSymbolAddress((void**)&Wff, g_Wff);
    cudaGetSymbolAddress((void**)&bff, g_bff);
    cudaGetSymbolAddress((void**)&bqkv, g_bqkv);
    cudaGetSymbolAddress((void**)&xhi, g_xhi);
    cudaGetSymbolAddress((void**)&xlo, g_xlo);
    cudaGetSymbolAddress((void**)&tmph, g_tmph);
    cudaGetSymbolAddress((void**)&qkvh, g_qkvh);
    cudaGetSymbolAddress((void**)&ohi, g_ohi);
    cudaGetSymbolAddress((void**)&wqkvT, g_wqkvT);
    cudaGetSymbolAddress((void**)&woT, g_woT);
    cudaGetSymbolAddress((void**)&WffT, g_WffT);
    cudaGetSymbolAddress((void**)&w1h, g_w1h);
    cudaGetSymbolAddress((void**)&w2T, g_w2T);

    detect_kernel<<<1, 1>>>(ids);
    embed_kernel<<<BB * LL, 256>>>(ids, emb, pe);

    dim3 tb(32, 8);
    tconv<<<dim3(32, 32), tb>>>(wq, nullptr, wqkvT, DD, DD, 0, 0.125f);
    tconv<<<dim3(32, 32), tb>>>(wk, nullptr, wqkvT, DD, DD, DD, 1.f);
    tconv<<<dim3(32, 32), tb>>>(wv, nullptr, wqkvT, DD, DD, 2 * DD, 1.f);
    tconv<<<dim3(32, 32), tb>>>(wo, nullptr, woT, DD, DD, 0, 1.f);
    tconv<<<dim3(32, 128), tb>>>(w2, nullptr, w2T, FF, DD, 0, 1.f);
    conv_h<<<(DD * FF) / 1024, 256>>>(w1, w1h);
    concat_bias<<<3, 1024>>>(bq, bk, bv);
    bff_part<<<32, 256>>>(b1, w2);
    bff_reduce<<<4, 256>>>(b2);
    gemm_tc<64><<<dim3(DD / 128, DD / 64, 2), 128, SM64>>>(w1h, w2T, nullptr,
                                                           Wff, nullptr, FF / 2, FF, DD, DD * DD);
    tconv<<<dim3(32, 32), tb>>>(Wff, Wff + (size_t)DD * DD, WffT, DD, DD, 0, 1.f);

    for (int layer = 0; layer < NLAYER; layer++) {
        gemm_tc<64><<<dim3(3 * DD / 128, LL / 64, 1), 128, SM64>>>(xhi, wqkvT, bqkv,
                                                                   nullptr, qkvh, DD, DD, 3 * DD, 0);
        flash_mma<<<dim3(16, HH), 64>>>(qkvh);
        gemm_tc<64><<<dim3(DD / 128, LL / 64, 2), 128, SM64>>>(ohi, woT, nullptr,
                                                               src2, nullptr, DD / 2, DD, DD, LL * DD);
        add_ln<<<BB * LL / 8, 256>>>(xhi, xlo, nullptr, src2, src2 + (size_t)LL * DD, bo,
                                     LL - 1, g1, be1);
        gemm_tc<128><<<dim3(DD / 128, (BB * LL) / 128, 1), 256, SM128>>>(xhi, WffT, bff,
                                                                         nullptr, tmph, DD, DD, DD, 0);
        add_ln<<<BB * LL / 8, 256>>>(xhi, xlo, tmph, nullptr, nullptr, nullptr,
                                     BB * LL - 1, g2, be2);
    }

    pool_mean<<<dim3(DD / 256, BB), 256>>>();
    logits_kernel<<<BB * CC, 256>>>(wf, bf, out);
}

// round 11
// speedup vs baseline: 5.1543x; 1.0598x over previous
#include <cuda_runtime.h>
#include <cuda_bf16.h>
#include <cuda_fp16.h>
#include <cstdint>

#define BB 16
#define LL 512
#define DD 1024
#define HH 16
#define FF 4096
#define CC 10
#define NLAYER 6

typedef __half f16;

__device__ f16 g_xhi[BB * LL * DD];
__device__ f16 g_xlo[BB * LL * DD];
__device__ f16 g_tmph[BB * LL * DD];
__device__ f16 g_qkvh[LL * 3 * DD];
__device__ f16 g_ohi[LL * DD];
__device__ float g_src2[2 * LL * DD];
__device__ float g_Wff[2 * DD * DD];
__device__ float g_bff[DD];
__device__ float g_bffpart[32 * DD];
__device__ float g_bqkv[3 * DD];
__device__ float g_pooled[BB * DD];
__device__ int g_ids64;
__device__ f16 g_wqkvT[3 * DD * DD];
__device__ f16 g_woT[DD * DD];
__device__ f16 g_WffT[DD * DD];
__device__ f16 g_w1h[DD * FF];
__device__ f16 g_w2T[DD * FF];

__device__ __forceinline__ void f2hl(float v, f16& h, f16& l) {
    h = __float2half(v);
    l = __float2half(v - __half2float(h));
}
__device__ __forceinline__ float warpSum(float v) {
    #pragma unroll
    for (int o = 16; o > 0; o >>= 1) v += __shfl_xor_sync(0xffffffffu, v, o);
    return v;
}
__device__ __forceinline__ float blockSum(float v) {
    __shared__ float sm[32];
    int lane = threadIdx.x & 31, w = threadIdx.x >> 5;
    v = warpSum(v);
    if (lane == 0) sm[w] = v;
    __syncthreads();
    if (w == 0) {
        float x = (lane < (int)(blockDim.x >> 5)) ? sm[lane] : 0.f;
        x = warpSum(x);
        if (lane == 0) sm[0] = x;
    }
    __syncthreads();
    float r = sm[0];
    __syncthreads();
    return r;
}

__device__ __forceinline__ uint32_t s2u(const void* p) {
    uint32_t a;
    asm("{ .reg .u64 t; cvta.to.shared.u64 t, %1; cvt.u32.u64 %0, t; }" : "=r"(a) : "l"(p));
    return a;
}
__device__ __forceinline__ void cpa(uint32_t dst, const void* src) {
    asm volatile("cp.async.cg.shared.global [%0], [%1], 16;" :: "r"(dst), "l"(src));
}
__device__ __forceinline__ void cpcommit() { asm volatile("cp.async.commit_group;"); }
template <int N> __device__ __forceinline__ void cpwait() {
    asm volatile("cp.async.wait_group %0;" :: "n"(N));
}
__device__ __forceinline__ void ldmx4(uint32_t* r, uint32_t a) {
    asm volatile("ldmatrix.sync.aligned.m8n8.x4.shared.b16 {%0,%1,%2,%3}, [%4];"
                 : "=r"(r[0]), "=r"(r[1]), "=r"(r[2]), "=r"(r[3]) : "r"(a));
}
__device__ __forceinline__ void mmah(float* d, const uint32_t* a, const uint32_t* b) {
    asm volatile(
        "mma.sync.aligned.m16n8k16.row.col.f32.f16.f16.f32 "
        "{%0,%1,%2,%3}, {%4,%5,%6,%7}, {%8,%9}, {%0,%1,%2,%3};"
        : "+f"(d[0]), "+f"(d[1]), "+f"(d[2]), "+f"(d[3])
        : "r"(a[0]), "r"(a[1]), "r"(a[2]), "r"(a[3]), "r"(b[0]), "r"(b[1]));
}

#define PITCH 80

// C[M,N] = A @ B^T + bias ; single fp16 operands; multi-stage cp.async pipeline.
template <int MT>
__global__ __launch_bounds__(MT * 2, (MT == 64) ? 4 : 2) void gemm_tc(
    const f16* __restrict__ A, const f16* __restrict__ B,
    const float* __restrict__ bias, float* __restrict__ C, f16* __restrict__ Ch,
    int Kiter, int Kstride, int N, int Czoff) {
    constexpr int THREADS = MT * 2;
    constexpr int OFS_B = MT * PITCH;
    constexpr int STB = (MT + 128) * PITCH;
    constexpr int NST = (MT == 128) ? 4 : 3;
    extern __shared__ char smem[];
    uint32_t sb = s2u(smem);
    const int t = threadIdx.x, lane = t & 31, wid = t >> 5;
    const int m0 = blockIdx.y * MT, n0 = blockIdx.x * 128;
    const int wr = wid >> 2, wc = wid & 3;
    const size_t kz = (size_t)blockIdx.z * Kiter;
    if (C) C += (size_t)blockIdx.z * Czoff;
    const int NKB = Kiter / 32;

    float acc[4][4][4];
    #pragma unroll
    for (int i = 0; i < 4; i++)
        #pragma unroll
        for (int j = 0; j < 4; j++)
            #pragma unroll
            for (int r = 0; r < 4; r++) acc[i][j][r] = 0.f;

    const uint32_t aoff = (uint32_t)((wr * 64 + (lane & 15)) * PITCH + ((lane >> 4) << 4));
    const int brow = wc * 32 + (lane & 7) + ((lane & 16) ? 8 : 0);
    const uint32_t boff = (uint32_t)(brow * PITCH + ((lane & 8) ? 16 : 0));

    auto load_stage = [&](int kb0, uint32_t base) {
        #pragma unroll
        for (int idx = t; idx < MT * 4; idx += THREADS) {
            int row = idx >> 2, c = idx & 3;
            uint32_t so = (uint32_t)(row * PITCH + c * 16);
            cpa(base + so, A + (size_t)(m0 + row) * Kstride + kz + kb0 + c * 8);
        }
        #pragma unroll
        for (int idx = t; idx < 512; idx += THREADS) {
            int row = idx >> 2, c = idx & 3;
            uint32_t so = (uint32_t)(row * PITCH + c * 16);
            cpa(base + OFS_B + so, B + (size_t)(n0 + row) * Kstride + kz + kb0 + c * 8);
        }
        cpcommit();
    };

    // prologue: NST-1 stages in flight (all our K have NKB >= 16 > NST-1)
    #pragma unroll
    for (int s = 0; s < NST - 1; s++)
        load_stage(s * 32, sb + (uint32_t)s * STB);

    for (int kb = 0; kb < NKB; kb++) {
        int nxt = kb + NST - 1;
        if (nxt < NKB)
            load_stage(nxt * 32, sb + (uint32_t)(nxt % NST) * STB);
        else
            cpcommit();   // keep group count uniform so wait<NST-2> pins stage kb
        cpwait<NST - 2>();
        __syncthreads();
        uint32_t base = sb + (uint32_t)(kb % NST) * STB;
        #pragma unroll
        for (int ks = 0; ks < 2; ks++) {
            uint32_t kbyte = (uint32_t)(ks * 32);
            uint32_t ah[4][4], bh[2][4];
            #pragma unroll
            for (int mt = 0; mt < 4; mt++)
                ldmx4(ah[mt], base + aoff + (uint32_t)(mt * 16 * PITCH) + kbyte);
            #pragma unroll
            for (int ng = 0; ng < 2; ng++)
                ldmx4(bh[ng], base + OFS_B + boff + (uint32_t)(ng * 16 * PITCH) + kbyte);
            #pragma unroll
            for (int mt = 0; mt < 4; mt++)
                #pragma unroll
                for (int nt = 0; nt < 4; nt++)
                    mmah(acc[mt][nt], ah[mt], &bh[nt >> 1][(nt & 1) * 2]);
        }
        __syncthreads();
    }

    #pragma unroll
    for (int mt = 0; mt < 4; mt++) {
        int m = m0 + wr * 64 + mt * 16 + (lane >> 2);
        #pragma unroll
        for (int nt = 0; nt < 4; nt++) {
            int n = n0 + wc * 32 + nt * 8 + (lane & 3) * 2;
            float b0 = 0.f, b1 = 0.f;
            if (bias) { b0 = bias[n]; b1 = bias[n + 1]; }
            float v0 = acc[mt][nt][0] + b0, v1 = acc[mt][nt][1] + b1;
            float v2 = acc[mt][nt][2] + b0, v3 = acc[mt][nt][3] + b1;
            if (Ch) {
                *(__half2*)(Ch + (size_t)m * N + n) = __floats2half2_rn(v0, v1);
                *(__half2*)(Ch + (size_t)(m + 8) * N + n) = __floats2half2_rn(v2, v3);
            } else {
                *(float2*)(C + (size_t)m * N + n) = make_float2(v0, v1);
                *(float2*)(C + (size_t)(m + 8) * N + n) = make_float2(v2, v3);
            }
        }
    }
}

__global__ void detect_kernel(const void* ids) {
    const int* p = (const int*)ids;
    int nz = 0;
    for (int i = 0; i < 256; i += 2)
        if (p[i + 1] != 0) nz++;
    g_ids64 = (nz == 0) ? 1 : 0;
}
__global__ void embed_kernel(const void* ids, const float* __restrict__ emb,
                             const float* __restrict__ pe) {
    int row = blockIdx.x;
    int d = threadIdx.x * 4;
    long long id;
    if (g_ids64) id = ((const long long*)ids)[row];
    else         id = (long long)((const int*)ids)[row];
    int l = row & (LL - 1);
    float4 e = *(const float4*)(emb + (size_t)id * DD + d);
    float4 p = *(const float4*)(pe + (size_t)l * DD + d);
    float v[4] = {e.x * 32.f + p.x, e.y * 32.f + p.y, e.z * 32.f + p.z, e.w * 32.f + p.w};
    size_t base = (size_t)row * DD + d;
    #pragma unroll
    for (int j = 0; j < 4; j++) {
        f16 h, lo;
        f2hl(v[j], h, lo);
        g_xhi[base + j] = h;
        g_xlo[base + j] = lo;
    }
}
__global__ void tconv(const float* __restrict__ in, const float* __restrict__ in2,
                      f16* __restrict__ oh, int R, int C, int nOff, float scale) {
    __shared__ float tl[32][33];
    int n0 = blockIdx.x * 32, k0 = blockIdx.y * 32;
    int tx = threadIdx.x, ty = threadIdx.y;
    #pragma unroll
    for (int i = 0; i < 4; i++) {
        size_t idx = (size_t)(k0 + ty + i * 8) * C + n0 + tx;
        float v = in[idx];
        if (in2) v += in2[idx];
        tl[ty + i * 8][tx] = v * scale;
    }
    __syncthreads();
    #pragma unroll
    for (int i = 0; i < 4; i++) {
        int nn = ty + i * 8;
        oh[(size_t)(nOff + n0 + nn) * R + k0 + tx] = __float2half(tl[tx][nn]);
    }
}
__global__ void conv_h(const float* __restrict__ in, f16* __restrict__ oh) {
    size_t i = ((size_t)blockIdx.x * 256 + threadIdx.x) * 4;
    float4 v = *(const float4*)(in + i);
    oh[i + 0] = __float2half(v.x);
    oh[i + 1] = __float2half(v.y);
    oh[i + 2] = __float2half(v.z);
    oh[i + 3] = __float2half(v.w);
}
__global__ void concat_bias(const float* __restrict__ bq, const float* __restrict__ bk,
                            const float* __restrict__ bv) {
    int t = threadIdx.x, s = blockIdx.x;
    const float* src = (s == 0) ? bq : (s == 1) ? bk : bv;
    g_bqkv[s * DD + t] = src[t] * ((s == 0) ? 0.125f : 1.f);
}
__global__ __launch_bounds__(256) void bff_part(const float* __restrict__ b1,
                                                const float* __restrict__ w2) {
    int y = blockIdx.x, t = threadIdx.x;
    float s[4] = {0.f, 0.f, 0.f, 0.f};
    for (int f = y * 128; f < y * 128 + 128; f++) {
        float bv = b1[f];
        const float* wr = w2 + (size_t)f * DD;
        #pragma unroll
        for (int j = 0; j < 4; j++) s[j] = fmaf(bv, wr[t + j * 256], s[j]);
    }
    #pragma unroll
    for (int j = 0; j < 4; j++) g_bffpart[y * DD + t + j * 256] = s[j];
}
__global__ __launch_bounds__(256) void bff_reduce(const float* __restrict__ b2) {
    int d = blockIdx.x * 256 + threadIdx.x;
    float s = b2[d];
    for (int y = 0; y < 32; y++) s += g_bffpart[y * DD + d];
    g_bff[d] = s;
}

// ---------------- HMMA flash attention (batch 0) ----------------
// grid (16 m-tiles of 32, 16 heads), 64 threads (2 warps, one m16 each).
__global__ __launch_bounds__(64) void flash_mma(const f16* __restrict__ qkv) {
    __shared__ __align__(16) char fsm[(32 + 64 + 64) * 144];
    const int OFQ = 0, OFK = 32 * 144, OFV = (32 + 64) * 144;
    uint32_t sb = s2u(fsm);
    int h = blockIdx.y, m0 = blockIdx.x * 32;
    int t = threadIdx.x, lane = t & 31, w = t >> 5;

    for (int i = t; i < 256; i += 64) {
        int r = i >> 3, c = i & 7;
        *(uint4*)(fsm + OFQ + r * 144 + c * 16) =
            *(const uint4*)(qkv + (size_t)(m0 + r) * (3 * DD) + h * 64 + c * 8);
    }
    __syncthreads();
    uint32_t qa[4][4];
    {
        uint32_t qoff = (uint32_t)((w * 16 + (lane & 15)) * 144 + ((lane >> 4) << 4));
        #pragma unroll
        for (int kt = 0; kt < 4; kt++) ldmx4(qa[kt], sb + OFQ + qoff + kt * 32);
    }

    const uint32_t brow = (uint32_t)((lane & 7) + ((lane & 16) ? 8 : 0));
    const uint32_t bcol = ((lane & 8) ? 16u : 0u);

    float m_run0 = -1e30f, m_run1 = -1e30f, l_run0 = 0.f, l_run1 = 0.f;
    float oacc[8][4];
    #pragma unroll
    for (int d = 0; d < 8; d++)
        #pragma unroll
        for (int r = 0; r < 4; r++) oacc[d][r] = 0.f;

    for (int kb = 0; kb < LL; kb += 64) {
        __syncthreads();
        for (int i = t; i < 512; i += 64) {
            int r = i >> 3, c = i & 7;
            *(uint4*)(fsm + OFK + r * 144 + c * 16) =
                *(const uint4*)(qkv + (size_t)(kb + r) * (3 * DD) + DD + h * 64 + c * 8);
        }
        // V transposed (vectorized): two keys per thread, half2 stores
        for (int i = t; i < 1024; i += 64) {
            int key2 = (i >> 5) * 2, d2 = i & 31;
            const f16* vsrc = qkv + 2 * DD + h * 64 + 2 * d2;
            __half2 a = *(const __half2*)(vsrc + (size_t)(kb + key2) * (3 * DD));
            __half2 b = *(const __half2*)(vsrc + (size_t)(kb + key2 + 1) * (3 * DD));
            *(__half2*)(fsm + OFV + (2 * d2) * 144 + key2 * 2) = __halves2half2(a.x, b.x);
            *(__half2*)(fsm + OFV + (2 * d2 + 1) * 144 + key2 * 2) = __halves2half2(a.y, b.y);
        }
        __syncthreads();

        float sacc[8][4];
        #pragma unroll
        for (int j = 0; j < 8; j++)
            #pragma unroll
            for (int r = 0; r < 4; r++) sacc[j][r] = 0.f;
        #pragma unroll
        for (int kt = 0; kt < 4; kt++) {
            #pragma unroll
            for (int ng = 0; ng < 4; ng++) {
                uint32_t kbf[4];
                ldmx4(kbf, sb + OFK + (uint32_t)(ng * 16) * 144 + brow * 144 + bcol + kt * 32);
                mmah(sacc[ng * 2 + 0], qa[kt], &kbf[0]);
                mmah(sacc[ng * 2 + 1], qa[kt], &kbf[2]);
            }
        }

        float ml0 = -1e30f, ml1 = -1e30f;
        #pragma unroll
        for (int j = 0; j < 8; j++) {
            ml0 = fmaxf(ml0, fmaxf(sacc[j][0], sacc[j][1]));
            ml1 = fmaxf(ml1, fmaxf(sacc[j][2], sacc[j][3]));
        }
        #pragma unroll
        for (int o = 1; o <= 2; o <<= 1) {
            ml0 = fmaxf(ml0, __shfl_xor_sync(0xffffffffu, ml0, o));
            ml1 = fmaxf(ml1, __shfl_xor_sync(0xffffffffu, ml1, o));
        }
        float mn0 = fmaxf(m_run0, ml0), mn1 = fmaxf(m_run1, ml1);
        float corr0 = __expf(m_run0 - mn0), corr1 = __expf(m_run1 - mn1);
        float rs0 = 0.f, rs1 = 0.f;
        uint32_t pfrag[4][4];
        #pragma unroll
        for (int kt = 0; kt < 4; kt++) {
            #pragma unroll
            for (int hh = 0; hh < 2; hh++) {
                int j = kt * 2 + hh;
                float p0 = __expf(sacc[j][0] - mn0), p1 = __expf(sacc[j][1] - mn0);
                float p2 = __expf(sacc[j][2] - mn1), p3 = __expf(sacc[j][3] - mn1);
                rs0 += p0 + p1;
                rs1 += p2 + p3;
                __half2 pa = __floats2half2_rn(p0, p1);
                __half2 pb = __floats2half2_rn(p2, p3);
                pfrag[kt][hh * 2 + 0] = *(uint32_t*)&pa;
                pfrag[kt][hh * 2 + 1] = *(uint32_t*)&pb;
            }
        }
        #pragma unroll
        for (int o = 1; o <= 2; o <<= 1) {
            rs0 += __shfl_xor_sync(0xffffffffu, rs0, o);
            rs1 += __shfl_xor_sync(0xffffffffu, rs1, o);
        }
        l_run0 = l_run0 * corr0 + rs0;
        l_run1 = l_run1 * corr1 + rs1;
        m_run0 = mn0;
        m_run1 = mn1;
        #pragma unroll
        for (int d = 0; d < 8; d++) {
            oacc[d][0] *= corr0; oacc[d][1] *= corr0;
            oacc[d][2] *= corr1; oacc[d][3] *= corr1;
        }
        #pragma unroll
        for (int kt = 0; kt < 4; kt++) {
            #pragma unroll
            for (int ng = 0; ng < 4; ng++) {
                uint32_t vb[4];
                ldmx4(vb, sb + OFV + (uint32_t)(ng * 16) * 144 + brow * 144 + bcol + kt * 32);
                mmah(oacc[ng * 2 + 0], pfrag[kt], &vb[0]);
                mmah(oacc[ng * 2 + 1], pfrag[kt], &vb[2]);
            }
        }
    }

    float inv0 = 1.f / l_run0, inv1 = 1.f / l_run1;
    int m = m0 + w * 16 + (lane >> 2);
    #pragma unroll
    for (int d = 0; d < 8; d++) {
        int n = h * 64 + d * 8 + 2 * (lane & 3);
        *(__half2*)(g_ohi + (size_t)m * DD + n) = __floats2half2_rn(oacc[d][0] * inv0, oacc[d][1] * inv0);
        *(__half2*)(g_ohi + (size_t)(m + 8) * DD + n) = __floats2half2_rn(oacc[d][2] * inv1, oacc[d][3] * inv1);
    }
}

// ---------------- warp-per-row residual + LayerNorm ----------------
__global__ __launch_bounds__(256) void add_ln(f16* __restrict__ xhi, f16* __restrict__ xlo,
                                              const f16* __restrict__ addh,
                                              const float* __restrict__ add,
                                              const float* __restrict__ add2,
                                              const float* __restrict__ cbias, int addMask,
                                              const float* __restrict__ g,
                                              const float* __restrict__ b) {
    int row = blockIdx.x * 8 + (threadIdx.x >> 5);
    int lane = threadIdx.x & 31;
    size_t base = (size_t)row * DD;
    size_t abase = (size_t)(row & addMask) * DD;
    float v[32];
    #pragma unroll
    for (int c = 0; c < 4; c++) {
        int e0 = c * 256 + lane * 8;
        uint4 hv = *(const uint4*)(xhi + base + e0);
        uint4 lv = *(const uint4*)(xlo + base + e0);
        __half2* hp = (__half2*)&hv;
        __half2* lp = (__half2*)&lv;
        float a[8];
        if (addh) {
            uint4 av4 = *(const uint4*)(addh + abase + e0);
            __half2* ap = (__half2*)&av4;
            #pragma unroll
            for (int j = 0; j < 4; j++) {
                a[2 * j] = __half2float(ap[j].x);
                a[2 * j + 1] = __half2float(ap[j].y);
            }
        } else {
            float4 a0 = *(const float4*)(add + abase + e0);
            float4 a1 = *(const float4*)(add + abase + e0 + 4);
            a[0] = a0.x; a[1] = a0.y; a[2] = a0.z; a[3] = a0.w;
            a[4] = a1.x; a[5] = a1.y; a[6] = a1.z; a[7] = a1.w;
            if (add2) {
                float4 c0 = *(const float4*)(add2 + abase + e0);
                float4 c1 = *(const float4*)(add2 + abase + e0 + 4);
                a[0] += c0.x; a[1] += c0.y; a[2] += c0.z; a[3] += c0.w;
                a[4] += c1.x; a[5] += c1.y; a[6] += c1.z; a[7] += c1.w;
            }
            if (cbias) {
                float4 c0 = *(const float4*)(cbias + e0);
                float4 c1 = *(const float4*)(cbias + e0 + 4);
                a[0] += c0.x; a[1] += c0.y; a[2] += c0.z; a[3] += c0.w;
                a[4] += c1.x; a[5] += c1.y; a[6] += c1.z; a[7] += c1.w;
            }
        }
        #pragma unroll
        for (int j = 0; j < 4; j++) {
            v[c * 8 + 2 * j]     = __half2float(hp[j].x) + __half2float(lp[j].x) + a[2 * j];
            v[c * 8 + 2 * j + 1] = __half2float(hp[j].y) + __half2float(lp[j].y) + a[2 * j + 1];
        }
    }
    float s = 0.f;
    #pragma unroll
    for (int i = 0; i < 32; i++) s += v[i];
    float mean = warpSum(s) * (1.f / DD);
    float q = 0.f;
    #pragma unroll
    for (int i = 0; i < 32; i++) {
        float d = v[i] - mean;
        q += d * d;
    }
    float rstd = rsqrtf(warpSum(q) * (1.f / DD) + 1e-5f);
    #pragma unroll
    for (int c = 0; c < 4; c++) {
        int e0 = c * 256 + lane * 8;
        float4 g0 = *(const float4*)(g + e0);
        float4 g1 = *(const float4*)(g + e0 + 4);
        float4 b0 = *(const float4*)(b + e0);
        float4 b1 = *(const float4*)(b + e0 + 4);
        float gg[8] = {g0.x, g0.y, g0.z, g0.w, g1.x, g1.y, g1.z, g1.w};
        float bb[8] = {b0.x, b0.y, b0.z, b0.w, b1.x, b1.y, b1.z, b1.w};
        uint4 ho, lo4;
        __half2* hop = (__half2*)&ho;
        __half2* lop = (__half2*)&lo4;
        #pragma unroll
        for (int j = 0; j < 4; j++) {
            float o0 = (v[c * 8 + 2 * j] - mean) * rstd * gg[2 * j] + bb[2 * j];
            float o1 = (v[c * 8 + 2 * j + 1] - mean) * rstd * gg[2 * j + 1] + bb[2 * j + 1];
            f16 h0, l0, h1, l1;
            f2hl(o0, h0, l0);
            f2hl(o1, h1, l1);
            hop[j] = __halves2half2(h0, h1);
            lop[j] = __halves2half2(l0, l1);
        }
        *(uint4*)(xhi + base + e0) = ho;
        *(uint4*)(xlo + base + e0) = lo4;
    }
}

__global__ __launch_bounds__(256) void pool_mean() {
    int b = blockIdx.y;
    int d = blockIdx.x * 256 + threadIdx.x;
    size_t base = (size_t)b * LL * DD + d;
    float s = 0.f;
    for (int l = 0; l < LL; l++)
        s += __half2float(g_xhi[base + (size_t)l * DD]) +
             __half2float(g_xlo[base + (size_t)l * DD]);
    g_pooled[b * DD + d] = s * (1.f / LL);
}
__global__ __launch_bounds__(256) void logits_kernel(const float* __restrict__ wf,
                                                     const float* __restrict__ bf,
                                                     float* __restrict__ out) {
    int b = blockIdx.x / CC, c = blockIdx.x % CC;
    float s = 0.f;
    for (int d = threadIdx.x; d < DD; d += 256)
        s += g_pooled[b * DD + d] * wf[(size_t)d * CC + c];
    s = blockSum(s);
    if (threadIdx.x == 0) out[b * CC + c] = s + bf[c];
}

extern "C" void kernel_launch(void* const* d_in, const int* in_sizes, int n_in,
                              void* d_out, int out_size) {
    const void*  ids = d_in[0];
    const float* emb = (const float*)d_in[1];
    const float* pe  = (const float*)d_in[2];
    const float* wq  = (const float*)d_in[3];
    const float* bq  = (const float*)d_in[4];
    const float* wk  = (const float*)d_in[5];
    const float* bk  = (const float*)d_in[6];
    const float* wv  = (const float*)d_in[7];
    const float* bv  = (const float*)d_in[8];
    const float* wo  = (const float*)d_in[9];
    const float* bo  = (const float*)d_in[10];
    const float* w1  = (const float*)d_in[11];
    const float* b1  = (const float*)d_in[12];
    const float* w2  = (const float*)d_in[13];
    const float* b2  = (const float*)d_in[14];
    const float* g1  = (const float*)d_in[15];
    const float* be1 = (const float*)d_in[16];
    const float* g2  = (const float*)d_in[17];
    const float* be2 = (const float*)d_in[18];
    const float* wf  = (const float*)d_in[19];
    const float* bf  = (const float*)d_in[20];
    float* out = (float*)d_out;

    const int SM128 = (128 + 128) * PITCH * 4;   // 4 stages
    const int SM64  = (64 + 128) * PITCH * 3;    // 3 stages
    cudaFuncSetAttribute(gemm_tc<128>, cudaFuncAttributeMaxDynamicSharedMemorySize, SM128);
    cudaFuncSetAttribute(gemm_tc<64>, cudaFuncAttributeMaxDynamicSharedMemorySize, SM64);

    float *src2, *Wff, *bff, *bqkv;
    f16 *xhi, *xlo, *tmph, *qkvh, *ohi, *wqkvT, *woT, *WffT, *w1h, *w2T;
    cudaGetSymbolAddress((void**)&src2, g_src2);
    cudaGetSymbolAddress((void**)&Wff, g_Wff);
    cudaGetSymbolAddress((void**)&bff, g_bff);
    cudaGetSymbolAddress((void**)&bqkv, g_bqkv);
    cudaGetSymbolAddress((void**)&xhi, g_xhi);
    cudaGetSymbolAddress((void**)&xlo, g_xlo);
    cudaGetSymbolAddress((void**)&tmph, g_tmph);
    cudaGetSymbolAddress((void**)&qkvh, g_qkvh);
    cudaGetSymbolAddress((void**)&ohi, g_ohi);
    cudaGetSymbolAddress((void**)&wqkvT, g_wqkvT);
    cudaGetSymbolAddress((void**)&woT, g_woT);
    cudaGetSymbolAddress((void**)&WffT, g_WffT);
    cudaGetSymbolAddress((void**)&w1h, g_w1h);
    cudaGetSymbolAddress((void**)&w2T, g_w2T);

    detect_kernel<<<1, 1>>>(ids);
    embed_kernel<<<BB * LL, 256>>>(ids, emb, pe);

    dim3 tb(32, 8);
    tconv<<<dim3(32, 32), tb>>>(wq, nullptr, wqkvT, DD, DD, 0, 0.125f);
    tconv<<<dim3(32, 32), tb>>>(wk, nullptr, wqkvT, DD, DD, DD, 1.f);
    tconv<<<dim3(32, 32), tb>>>(wv, nullptr, wqkvT, DD, DD, 2 * DD, 1.f);
    tconv<<<dim3(32, 32), tb>>>(wo, nullptr, woT, DD, DD, 0, 1.f);
    tconv<<<dim3(32, 128), tb>>>(w2, nullptr, w2T, FF, DD, 0, 1.f);
    conv_h<<<(DD * FF) / 1024, 256>>>(w1, w1h);
    concat_bias<<<3, 1024>>>(bq, bk, bv);
    bff_part<<<32, 256>>>(b1, w2);
    bff_reduce<<<4, 256>>>(b2);
    gemm_tc<64><<<dim3(DD / 128, DD / 64, 2), 128, SM64>>>(w1h, w2T, nullptr,
                                                           Wff, nullptr, FF / 2, FF, DD, DD * DD);
    tconv<<<dim3(32, 32), tb>>>(Wff, Wff + (size_t)DD * DD, WffT, DD, DD, 0, 1.f);

    for (int layer = 0; layer < NLAYER; layer++) {
        gemm_tc<64><<<dim3(3 * DD / 128, LL / 64, 1), 128, SM64>>>(xhi, wqkvT, bqkv,
                                                                   nullptr, qkvh, DD, DD, 3 * DD, 0);
        flash_mma<<<dim3(16, HH), 64>>>(qkvh);
        gemm_tc<64><<<dim3(DD / 128, LL / 64, 2), 128, SM64>>>(ohi, woT, nullptr,
                                                               src2, nullptr, DD / 2, DD, DD, LL * DD);
        add_ln<<<BB * LL / 8, 256>>>(xhi, xlo, nullptr, src2, src2 + (size_t)LL * DD, bo,
                                     LL - 1, g1, be1);
        gemm_tc<128><<<dim3(DD / 128, (BB * LL) / 128, 1), 256, SM128>>>(xhi, WffT, bff,
                                                                         nullptr, tmph, DD, DD, DD, 0);
        add_ln<<<BB * LL / 8, 256>>>(xhi, xlo, tmph, nullptr, nullptr, nullptr,
                                     BB * LL - 1, g2, be2);
    }

    pool_mean<<<dim3(DD / 256, BB), 256>>>();
    logits_kernel<<<BB * CC, 256>>>(wf, bf, out);
}

// round 12
// speedup vs baseline: 5.5620x; 1.0791x over previous
#include <cuda_runtime.h>
#include <cuda_bf16.h>
#include <cuda_fp16.h>
#include <cstdint>

#define BB 16
#define LL 512
#define DD 1024
#define HH 16
#define FF 4096
#define CC 10
#define NLAYER 6

typedef __half f16;

__device__ f16 g_xhi[BB * LL * DD];
__device__ f16 g_xlo[BB * LL * DD];
__device__ f16 g_tmph[BB * LL * DD];
__device__ f16 g_qkvh[LL * 3 * DD];
__device__ f16 g_ohi[LL * DD];
__device__ float g_src2[2 * LL * DD];
__device__ float g_bff[DD];
__device__ float g_bffpart[32 * DD];
__device__ float g_bqkv[3 * DD];
__device__ float g_pooled[BB * DD];
__device__ int g_ids64;
__device__ f16 g_wqkvT[3 * DD * DD];
__device__ f16 g_woT[DD * DD];
__device__ f16 g_WffT[DD * DD];
__device__ f16 g_w1h[DD * FF];
__device__ f16 g_w2T[DD * FF];

__device__ __forceinline__ void f2hl(float v, f16& h, f16& l) {
    h = __float2half(v);
    l = __float2half(v - __half2float(h));
}
__device__ __forceinline__ float warpSum(float v) {
    #pragma unroll
    for (int o = 16; o > 0; o >>= 1) v += __shfl_xor_sync(0xffffffffu, v, o);
    return v;
}
__device__ __forceinline__ float blockSum(float v) {
    __shared__ float sm[32];
    int lane = threadIdx.x & 31, w = threadIdx.x >> 5;
    v = warpSum(v);
    if (lane == 0) sm[w] = v;
    __syncthreads();
    if (w == 0) {
        float x = (lane < (int)(blockDim.x >> 5)) ? sm[lane] : 0.f;
        x = warpSum(x);
        if (lane == 0) sm[0] = x;
    }
    __syncthreads();
    float r = sm[0];
    __syncthreads();
    return r;
}

__device__ __forceinline__ uint32_t s2u(const void* p) {
    uint32_t a;
    asm("{ .reg .u64 t; cvta.to.shared.u64 t, %1; cvt.u32.u64 %0, t; }" : "=r"(a) : "l"(p));
    return a;
}
__device__ __forceinline__ void cpa(uint32_t dst, const void* src) {
    asm volatile("cp.async.cg.shared.global [%0], [%1], 16;" :: "r"(dst), "l"(src));
}
__device__ __forceinline__ void cpcommit() { asm volatile("cp.async.commit_group;"); }
template <int N> __device__ __forceinline__ void cpwait() {
    asm volatile("cp.async.wait_group %0;" :: "n"(N));
}
__device__ __forceinline__ void ldmx4(uint32_t* r, uint32_t a) {
    asm volatile("ldmatrix.sync.aligned.m8n8.x4.shared.b16 {%0,%1,%2,%3}, [%4];"
                 : "=r"(r[0]), "=r"(r[1]), "=r"(r[2]), "=r"(r[3]) : "r"(a));
}
__device__ __forceinline__ void mmah(float* d, const uint32_t* a, const uint32_t* b) {
    asm volatile(
        "mma.sync.aligned.m16n8k16.row.col.f32.f16.f16.f32 "
        "{%0,%1,%2,%3}, {%4,%5,%6,%7}, {%8,%9}, {%0,%1,%2,%3};"
        : "+f"(d[0]), "+f"(d[1]), "+f"(d[2]), "+f"(d[3])
        : "r"(a[0]), "r"(a[1]), "r"(a[2]), "r"(a[3]), "r"(b[0]), "r"(b[1]));
}

#define PITCH 80

// C[M,N] = A @ B^T + bias ; single fp16 operands; multi-stage cp.async pipeline,
// single __syncthreads per k-iteration (prefetch issued after consume).
template <int MT>
__global__ __launch_bounds__(MT * 2, (MT == 64) ? 4 : 2) void gemm_tc(
    const f16* __restrict__ A, const f16* __restrict__ B,
    const float* __restrict__ bias, float* __restrict__ C, f16* __restrict__ Ch,
    int Kiter, int Kstride, int N, int Czoff) {
    constexpr int THREADS = MT * 2;
    constexpr int OFS_B = MT * PITCH;
    constexpr int STB = (MT + 128) * PITCH;
    constexpr int NST = (MT == 128) ? 4 : 3;
    extern __shared__ char smem[];
    uint32_t sb = s2u(smem);
    const int t = threadIdx.x, lane = t & 31, wid = t >> 5;
    const int m0 = blockIdx.y * MT, n0 = blockIdx.x * 128;
    const int wr = wid >> 2, wc = wid & 3;
    const size_t kz = (size_t)blockIdx.z * Kiter;
    if (C) C += (size_t)blockIdx.z * Czoff;
    const int NKB = Kiter / 32;

    float acc[4][4][4];
    #pragma unroll
    for (int i = 0; i < 4; i++)
        #pragma unroll
        for (int j = 0; j < 4; j++)
            #pragma unroll
            for (int r = 0; r < 4; r++) acc[i][j][r] = 0.f;

    const uint32_t aoff = (uint32_t)((wr * 64 + (lane & 15)) * PITCH + ((lane >> 4) << 4));
    const int brow = wc * 32 + (lane & 7) + ((lane & 16) ? 8 : 0);
    const uint32_t boff = (uint32_t)(brow * PITCH + ((lane & 8) ? 16 : 0));

    auto load_stage = [&](int kb0, uint32_t base) {
        #pragma unroll
        for (int idx = t; idx < MT * 4; idx += THREADS) {
            int row = idx >> 2, c = idx & 3;
            uint32_t so = (uint32_t)(row * PITCH + c * 16);
            cpa(base + so, A + (size_t)(m0 + row) * Kstride + kz + kb0 + c * 8);
        }
        #pragma unroll
        for (int idx = t; idx < 512; idx += THREADS) {
            int row = idx >> 2, c = idx & 3;
            uint32_t so = (uint32_t)(row * PITCH + c * 16);
            cpa(base + OFS_B + so, B + (size_t)(n0 + row) * Kstride + kz + kb0 + c * 8);
        }
        cpcommit();
    };

    // prologue: NST-1 stages in flight (all K here have NKB >= 16 > NST-1)
    #pragma unroll
    for (int s = 0; s < NST - 1; s++)
        load_stage(s * 32, sb + (uint32_t)s * STB);

    for (int kb = 0; kb < NKB; kb++) {
        cpwait<NST - 2>();
        __syncthreads();   // data of stage kb visible to all; all reads of stage (kb-1) done
        uint32_t base = sb + (uint32_t)(kb % NST) * STB;
        #pragma unroll
        for (int ks = 0; ks < 2; ks++) {
            uint32_t kbyte = (uint32_t)(ks * 32);
            uint32_t ah[4][4], bh[2][4];
            #pragma unroll
            for (int mt = 0; mt < 4; mt++)
                ldmx4(ah[mt], base + aoff + (uint32_t)(mt * 16 * PITCH) + kbyte);
            #pragma unroll
            for (int ng = 0; ng < 2; ng++)
                ldmx4(bh[ng], base + OFS_B + boff + (uint32_t)(ng * 16 * PITCH) + kbyte);
            #pragma unroll
            for (int mt = 0; mt < 4; mt++)
                #pragma unroll
                for (int nt = 0; nt < 4; nt++)
                    mmah(acc[mt][nt], ah[mt], &bh[nt >> 1][(nt & 1) * 2]);
        }
        // prefetch AFTER consume: target stage (kb+NST-1)%NST == (kb-1)%NST, whose
        // reads completed before this iteration's __syncthreads.
        int nxt = kb + NST - 1;
        if (nxt < NKB)
            load_stage(nxt * 32, sb + (uint32_t)(nxt % NST) * STB);
        else
            cpcommit();   // keep group count uniform for the wait at the loop head
    }

    #pragma unroll
    for (int mt = 0; mt < 4; mt++) {
        int m = m0 + wr * 64 + mt * 16 + (lane >> 2);
        #pragma unroll
        for (int nt = 0; nt < 4; nt++) {
            int n = n0 + wc * 32 + nt * 8 + (lane & 3) * 2;
            float b0 = 0.f, b1 = 0.f;
            if (bias) { b0 = bias[n]; b1 = bias[n + 1]; }
            float v0 = acc[mt][nt][0] + b0, v1 = acc[mt][nt][1] + b1;
            float v2 = acc[mt][nt][2] + b0, v3 = acc[mt][nt][3] + b1;
            if (Ch) {
                *(__half2*)(Ch + (size_t)m * N + n) = __floats2half2_rn(v0, v1);
                *(__half2*)(Ch + (size_t)(m + 8) * N + n) = __floats2half2_rn(v2, v3);
            } else {
                *(float2*)(C + (size_t)m * N + n) = make_float2(v0, v1);
                *(float2*)(C + (size_t)(m + 8) * N + n) = make_float2(v2, v3);
            }
        }
    }
}

__global__ void detect_kernel(const void* ids) {
    const int* p = (const int*)ids;
    int nz = 0;
    for (int i = 0; i < 256; i += 2)
        if (p[i + 1] != 0) nz++;
    g_ids64 = (nz == 0) ? 1 : 0;
}
__global__ void embed_kernel(const void* ids, const float* __restrict__ emb,
                             const float* __restrict__ pe) {
    int row = blockIdx.x;
    int d = threadIdx.x * 4;
    long long id;
    if (g_ids64) id = ((const long long*)ids)[row];
    else         id = (long long)((const int*)ids)[row];
    int l = row & (LL - 1);
    float4 e = *(const float4*)(emb + (size_t)id * DD + d);
    float4 p = *(const float4*)(pe + (size_t)l * DD + d);
    float v[4] = {e.x * 32.f + p.x, e.y * 32.f + p.y, e.z * 32.f + p.z, e.w * 32.f + p.w};
    size_t base = (size_t)row * DD + d;
    #pragma unroll
    for (int j = 0; j < 4; j++) {
        f16 h, lo;
        f2hl(v[j], h, lo);
        g_xhi[base + j] = h;
        g_xlo[base + j] = lo;
    }
}
// fused transpose+convert for wq/wk/wv/wo selected by blockIdx.z
__global__ void tconv4(const float* __restrict__ wq, const float* __restrict__ wk,
                       const float* __restrict__ wv, const float* __restrict__ wo) {
    __shared__ float tl[32][33];
    int z = blockIdx.z;
    const float* in = (z == 0) ? wq : (z == 1) ? wk : (z == 2) ? wv : wo;
    f16* oh = (z == 3) ? g_woT : g_wqkvT + (size_t)z * DD * DD;
    float scale = (z == 0) ? 0.125f : 1.f;
    int n0 = blockIdx.x * 32, k0 = blockIdx.y * 32;
    int tx = threadIdx.x, ty = threadIdx.y;
    #pragma unroll
    for (int i = 0; i < 4; i++)
        tl[ty + i * 8][tx] = in[(size_t)(k0 + ty + i * 8) * DD + n0 + tx] * scale;
    __syncthreads();
    #pragma unroll
    for (int i = 0; i < 4; i++) {
        int nn = ty + i * 8;
        oh[(size_t)(n0 + nn) * DD + k0 + tx] = __float2half(tl[tx][nn]);
    }
}
__global__ void tconv(const float* __restrict__ in, f16* __restrict__ oh,
                      int R, int C) {
    __shared__ float tl[32][33];
    int n0 = blockIdx.x * 32, k0 = blockIdx.y * 32;
    int tx = threadIdx.x, ty = threadIdx.y;
    #pragma unroll
    for (int i = 0; i < 4; i++)
        tl[ty + i * 8][tx] = in[(size_t)(k0 + ty + i * 8) * C + n0 + tx];
    __syncthreads();
    #pragma unroll
    for (int i = 0; i < 4; i++) {
        int nn = ty + i * 8;
        oh[(size_t)(n0 + nn) * R + k0 + tx] = __float2half(tl[tx][nn]);
    }
}
__global__ void conv_h(const float* __restrict__ in, f16* __restrict__ oh) {
    size_t i = ((size_t)blockIdx.x * 256 + threadIdx.x) * 4;
    float4 v = *(const float4*)(in + i);
    oh[i + 0] = __float2half(v.x);
    oh[i + 1] = __float2half(v.y);
    oh[i + 2] = __float2half(v.z);
    oh[i + 3] = __float2half(v.w);
}
__global__ void concat_bias(const float* __restrict__ bq, const float* __restrict__ bk,
                            const float* __restrict__ bv) {
    int t = threadIdx.x, s = blockIdx.x;
    const float* src = (s == 0) ? bq : (s == 1) ? bk : bv;
    g_bqkv[s * DD + t] = src[t] * ((s == 0) ? 0.125f : 1.f);
}
__global__ __launch_bounds__(256) void bff_part(const float* __restrict__ b1,
                                                const float* __restrict__ w2) {
    int y = blockIdx.x, t = threadIdx.x;
    float s[4] = {0.f, 0.f, 0.f, 0.f};
    for (int f = y * 128; f < y * 128 + 128; f++) {
        float bv = b1[f];
        const float* wr = w2 + (size_t)f * DD;
        #pragma unroll
        for (int j = 0; j < 4; j++) s[j] = fmaf(bv, wr[t + j * 256], s[j]);
    }
    #pragma unroll
    for (int j = 0; j < 4; j++) g_bffpart[y * DD + t + j * 256] = s[j];
}
__global__ __launch_bounds__(256) void bff_reduce(const float* __restrict__ b2) {
    int d = blockIdx.x * 256 + threadIdx.x;
    float s = b2[d];
    for (int y = 0; y < 32; y++) s += g_bffpart[y * DD + d];
    g_bff[d] = s;
}

// ---------------- HMMA flash attention (batch 0) ----------------
__global__ __launch_bounds__(64) void flash_mma(const f16* __restrict__ qkv) {
    __shared__ __align__(16) char fsm[(32 + 64 + 64) * 144];
    const int OFQ = 0, OFK = 32 * 144, OFV = (32 + 64) * 144;
    uint32_t sb = s2u(fsm);
    int h = blockIdx.y, m0 = blockIdx.x * 32;
    int t = threadIdx.x, lane = t & 31, w = t >> 5;

    for (int i = t; i < 256; i += 64) {
        int r = i >> 3, c = i & 7;
        *(uint4*)(fsm + OFQ + r * 144 + c * 16) =
            *(const uint4*)(qkv + (size_t)(m0 + r) * (3 * DD) + h * 64 + c * 8);
    }
    __syncthreads();
    uint32_t qa[4][4];
    {
        uint32_t qoff = (uint32_t)((w * 16 + (lane & 15)) * 144 + ((lane >> 4) << 4));
        #pragma unroll
        for (int kt = 0; kt < 4; kt++) ldmx4(qa[kt], sb + OFQ + qoff + kt * 32);
    }

    const uint32_t brow = (uint32_t)((lane & 7) + ((lane & 16) ? 8 : 0));
    const uint32_t bcol = ((lane & 8) ? 16u : 0u);

    float m_run0 = -1e30f, m_run1 = -1e30f, l_run0 = 0.f, l_run1 = 0.f;
    float oacc[8][4];
    #pragma unroll
    for (int d = 0; d < 8; d++)
        #pragma unroll
        for (int r = 0; r < 4; r++) oacc[d][r] = 0.f;

    for (int kb = 0; kb < LL; kb += 64) {
        __syncthreads();
        for (int i = t; i < 512; i += 64) {
            int r = i >> 3, c = i & 7;
            *(uint4*)(fsm + OFK + r * 144 + c * 16) =
                *(const uint4*)(qkv + (size_t)(kb + r) * (3 * DD) + DD + h * 64 + c * 8);
        }
        for (int i = t; i < 1024; i += 64) {
            int key2 = (i >> 5) * 2, d2 = i & 31;
            const f16* vsrc = qkv + 2 * DD + h * 64 + 2 * d2;
            __half2 a = *(const __half2*)(vsrc + (size_t)(kb + key2) * (3 * DD));
            __half2 b = *(const __half2*)(vsrc + (size_t)(kb + key2 + 1) * (3 * DD));
            *(__half2*)(fsm + OFV + (2 * d2) * 144 + key2 * 2) = __halves2half2(a.x, b.x);
            *(__half2*)(fsm + OFV + (2 * d2 + 1) * 144 + key2 * 2) = __halves2half2(a.y, b.y);
        }
        __syncthreads();

        float sacc[8][4];
        #pragma unroll
        for (int j = 0; j < 8; j++)
            #pragma unroll
            for (int r = 0; r < 4; r++) sacc[j][r] = 0.f;
        #pragma unroll
        for (int kt = 0; kt < 4; kt++) {
            #pragma unroll
            for (int ng = 0; ng < 4; ng++) {
                uint32_t kbf[4];
                ldmx4(kbf, sb + OFK + (uint32_t)(ng * 16) * 144 + brow * 144 + bcol + kt * 32);
                mmah(sacc[ng * 2 + 0], qa[kt], &kbf[0]);
                mmah(sacc[ng * 2 + 1], qa[kt], &kbf[2]);
            }
        }

        float ml0 = -1e30f, ml1 = -1e30f;
        #pragma unroll
        for (int j = 0; j < 8; j++) {
            ml0 = fmaxf(ml0, fmaxf(sacc[j][0], sacc[j][1]));
            ml1 = fmaxf(ml1, fmaxf(sacc[j][2], sacc[j][3]));
        }
        #pragma unroll
        for (int o = 1; o <= 2; o <<= 1) {
            ml0 = fmaxf(ml0, __shfl_xor_sync(0xffffffffu, ml0, o));
            ml1 = fmaxf(ml1, __shfl_xor_sync(0xffffffffu, ml1, o));
        }
        float mn0 = fmaxf(m_run0, ml0), mn1 = fmaxf(m_run1, ml1);
        float corr0 = __expf(m_run0 - mn0), corr1 = __expf(m_run1 - mn1);
        float rs0 = 0.f, rs1 = 0.f;
        uint32_t pfrag[4][4];
        #pragma unroll
        for (int kt = 0; kt < 4; kt++) {
            #pragma unroll
            for (int hh = 0; hh < 2; hh++) {
                int j = kt * 2 + hh;
                float p0 = __expf(sacc[j][0] - mn0), p1 = __expf(sacc[j][1] - mn0);
                float p2 = __expf(sacc[j][2] - mn1), p3 = __expf(sacc[j][3] - mn1);
                rs0 += p0 + p1;
                rs1 += p2 + p3;
                __half2 pa = __floats2half2_rn(p0, p1);
                __half2 pb = __floats2half2_rn(p2, p3);
                pfrag[kt][hh * 2 + 0] = *(uint32_t*)&pa;
                pfrag[kt][hh * 2 + 1] = *(uint32_t*)&pb;
            }
        }
        #pragma unroll
        for (int o = 1; o <= 2; o <<= 1) {
            rs0 += __shfl_xor_sync(0xffffffffu, rs0, o);
            rs1 += __shfl_xor_sync(0xffffffffu, rs1, o);
        }
        l_run0 = l_run0 * corr0 + rs0;
        l_run1 = l_run1 * corr1 + rs1;
        m_run0 = mn0;
        m_run1 = mn1;
        #pragma unroll
        for (int d = 0; d < 8; d++) {
            oacc[d][0] *= corr0; oacc[d][1] *= corr0;
            oacc[d][2] *= corr1; oacc[d][3] *= corr1;
        }
        #pragma unroll
        for (int kt = 0; kt < 4; kt++) {
            #pragma unroll
            for (int ng = 0; ng < 4; ng++) {
                uint32_t vb[4];
                ldmx4(vb, sb + OFV + (uint32_t)(ng * 16) * 144 + brow * 144 + bcol + kt * 32);
                mmah(oacc[ng * 2 + 0], pfrag[kt], &vb[0]);
                mmah(oacc[ng * 2 + 1], pfrag[kt], &vb[2]);
            }
        }
    }

    float inv0 = 1.f / l_run0, inv1 = 1.f / l_run1;
    int m = m0 + w * 16 + (lane >> 2);
    #pragma unroll
    for (int d = 0; d < 8; d++) {
        int n = h * 64 + d * 8 + 2 * (lane & 3);
        *(__half2*)(g_ohi + (size_t)m * DD + n) = __floats2half2_rn(oacc[d][0] * inv0, oacc[d][1] * inv0);
        *(__half2*)(g_ohi + (size_t)(m + 8) * DD + n) = __floats2half2_rn(oacc[d][2] * inv1, oacc[d][3] * inv1);
    }
}

// ---------------- warp-per-row residual + LayerNorm ----------------
__global__ __launch_bounds__(256) void add_ln(f16* __restrict__ xhi, f16* __restrict__ xlo,
                                              const f16* __restrict__ addh,
                                              const float* __restrict__ add,
                                              const float* __restrict__ add2,
                                              const float* __restrict__ cbias, int addMask,
                                              const float* __restrict__ g,
                                              const float* __restrict__ b) {
    int row = blockIdx.x * 8 + (threadIdx.x >> 5);
    int lane = threadIdx.x & 31;
    size_t base = (size_t)row * DD;
    size_t abase = (size_t)(row & addMask) * DD;
    float v[32];
    #pragma unroll
    for (int c = 0; c < 4; c++) {
        int e0 = c * 256 + lane * 8;
        uint4 hv = *(const uint4*)(xhi + base + e0);
        uint4 lv = *(const uint4*)(xlo + base + e0);
        __half2* hp = (__half2*)&hv;
        __half2* lp = (__half2*)&lv;
        float a[8];
        if (addh) {
            uint4 av4 = *(const uint4*)(addh + abase + e0);
            __half2* ap = (__half2*)&av4;
            #pragma unroll
            for (int j = 0; j < 4; j++) {
                a[2 * j] = __half2float(ap[j].x);
                a[2 * j + 1] = __half2float(ap[j].y);
            }
        } else {
            float4 a0 = *(const float4*)(add + abase + e0);
            float4 a1 = *(const float4*)(add + abase + e0 + 4);
            a[0] = a0.x; a[1] = a0.y; a[2] = a0.z; a[3] = a0.w;
            a[4] = a1.x; a[5] = a1.y; a[6] = a1.z; a[7] = a1.w;
            if (add2) {
                float4 c0 = *(const float4*)(add2 + abase + e0);
                float4 c1 = *(const float4*)(add2 + abase + e0 + 4);
                a[0] += c0.x; a[1] += c0.y; a[2] += c0.z; a[3] += c0.w;
                a[4] += c1.x; a[5] += c1.y; a[6] += c1.z; a[7] += c1.w;
            }
            if (cbias) {
                float4 c0 = *(const float4*)(cbias + e0);
                float4 c1 = *(const float4*)(cbias + e0 + 4);
                a[0] += c0.x; a[1] += c0.y; a[2] += c0.z; a[3] += c0.w;
                a[4] += c1.x; a[5] += c1.y; a[6] += c1.z; a[7] += c1.w;
            }
        }
        #pragma unroll
        for (int j = 0; j < 4; j++) {
            v[c * 8 + 2 * j]     = __half2float(hp[j].x) + __half2float(lp[j].x) + a[2 * j];
            v[c * 8 + 2 * j + 1] = __half2float(hp[j].y) + __half2float(lp[j].y) + a[2 * j + 1];
        }
    }
    float s = 0.f;
    #pragma unroll
    for (int i = 0; i < 32; i++) s += v[i];
    float mean = warpSum(s) * (1.f / DD);
    float q = 0.f;
    #pragma unroll
    for (int i = 0; i < 32; i++) {
        float d = v[i] - mean;
        q += d * d;
    }
    float rstd = rsqrtf(warpSum(q) * (1.f / DD) + 1e-5f);
    #pragma unroll
    for (int c = 0; c < 4; c++) {
        int e0 = c * 256 + lane * 8;
        float4 g0 = *(const float4*)(g + e0);
        float4 g1 = *(const float4*)(g + e0 + 4);
        float4 b0 = *(const float4*)(b + e0);
        float4 b1 = *(const float4*)(b + e0 + 4);
        float gg[8] = {g0.x, g0.y, g0.z, g0.w, g1.x, g1.y, g1.z, g1.w};
        float bb[8] = {b0.x, b0.y, b0.z, b0.w, b1.x, b1.y, b1.z, b1.w};
        uint4 ho, lo4;
        __half2* hop = (__half2*)&ho;
        __half2* lop = (__half2*)&lo4;
        #pragma unroll
        for (int j = 0; j < 4; j++) {
            float o0 = (v[c * 8 + 2 * j] - mean) * rstd * gg[2 * j] + bb[2 * j];
            float o1 = (v[c * 8 + 2 * j + 1] - mean) * rstd * gg[2 * j + 1] + bb[2 * j + 1];
            f16 h0, l0, h1, l1;
            f2hl(o0, h0, l0);
            f2hl(o1, h1, l1);
            hop[j] = __halves2half2(h0, h1);
            lop[j] = __halves2half2(l0, l1);
        }
        *(uint4*)(xhi + base + e0) = ho;
        *(uint4*)(xlo + base + e0) = lo4;
    }
}

__global__ __launch_bounds__(256) void pool_mean() {
    int b = blockIdx.y;
    int d = blockIdx.x * 256 + threadIdx.x;
    size_t base = (size_t)b * LL * DD + d;
    float s = 0.f;
    for (int l = 0; l < LL; l++)
        s += __half2float(g_xhi[base + (size_t)l * DD]) +
             __half2float(g_xlo[base + (size_t)l * DD]);
    g_pooled[b * DD + d] = s * (1.f / LL);
}
__global__ __launch_bounds__(256) void logits_kernel(const float* __restrict__ wf,
                                                     const float* __restrict__ bf,
                                                     float* __restrict__ out) {
    int b = blockIdx.x / CC, c = blockIdx.x % CC;
    float s = 0.f;
    for (int d = threadIdx.x; d < DD; d += 256)
        s += g_pooled[b * DD + d] * wf[(size_t)d * CC + c];
    s = blockSum(s);
    if (threadIdx.x == 0) out[b * CC + c] = s + bf[c];
}

extern "C" void kernel_launch(void* const* d_in, const int* in_sizes, int n_in,
                              void* d_out, int out_size) {
    const void*  ids = d_in[0];
    const float* emb = (const float*)d_in[1];
    const float* pe  = (const float*)d_in[2];
    const float* wq  = (const float*)d_in[3];
    const float* bq  = (const float*)d_in[4];
    const float* wk  = (const float*)d_in[5];
    const float* bk  = (const float*)d_in[6];
    const float* wv  = (const float*)d_in[7];
    const float* bv  = (const float*)d_in[8];
    const float* wo  = (const float*)d_in[9];
    const float* bo  = (const float*)d_in[10];
    const float* w1  = (const float*)d_in[11];
    const float* b1  = (const float*)d_in[12];
    const float* w2  = (const float*)d_in[13];
    const float* b2  = (const float*)d_in[14];
    const float* g1  = (const float*)d_in[15];
    const float* be1 = (const float*)d_in[16];
    const float* g2  = (const float*)d_in[17];
    const float* be2 = (const float*)d_in[18];
    const float* wf  = (const float*)d_in[19];
    const float* bf  = (const float*)d_in[20];
    float* out = (float*)d_out;

    const int SM128 = (128 + 128) * PITCH * 4;   // 4 stages
    const int SM64  = (64 + 128) * PITCH * 3;    // 3 stages
    cudaFuncSetAttribute(gemm_tc<128>, cudaFuncAttributeMaxDynamicSharedMemorySize, SM128);
    cudaFuncSetAttribute(gemm_tc<64>, cudaFuncAttributeMaxDynamicSharedMemorySize, SM64);

    float *src2, *bff, *bqkv;
    f16 *xhi, *xlo, *tmph, *qkvh, *ohi, *wqkvT, *woT, *WffT, *w1h, *w2T;
    cudaGetSymbolAddress((void**)&src2, g_src2);
    cudaGetSymbolAddress((void**)&bff, g_bff);
    cudaGetSymbolAddress((void**)&bqkv, g_bqkv);
    cudaGetSymbolAddress((void**)&xhi, g_xhi);
    cudaGetSymbolAddress((void**)&xlo, g_xlo);
    cudaGetSymbolAddress((void**)&tmph, g_tmph);
    cudaGetSymbolAddress((void**)&qkvh, g_qkvh);
    cudaGetSymbolAddress((void**)&ohi, g_ohi);
    cudaGetSymbolAddress((void**)&wqkvT, g_wqkvT);
    cudaGetSymbolAddress((void**)&woT, g_woT);
    cudaGetSymbolAddress((void**)&WffT, g_WffT);
    cudaGetSymbolAddress((void**)&w1h, g_w1h);
    cudaGetSymbolAddress((void**)&w2T, g_w2T);

    detect_kernel<<<1, 1>>>(ids);
    embed_kernel<<<BB * LL, 256>>>(ids, emb, pe);

    dim3 tb(32, 8);
    tconv4<<<dim3(32, 32, 4), tb>>>(wq, wk, wv, wo);
    tconv<<<dim3(32, 128), tb>>>(w2, w2T, FF, DD);
    conv_h<<<(DD * FF) / 1024, 256>>>(w1, w1h);
    concat_bias<<<3, 1024>>>(bq, bk, bv);
    bff_part<<<32, 256>>>(b1, w2);
    bff_reduce<<<4, 256>>>(b2);
    // WffT[m][k] = Wff[k][m] = sum_f w2T[m][f] * w1h[k][f] -> direct fp16 output
    gemm_tc<64><<<dim3(DD / 128, DD / 64, 1), 128, SM64>>>(w2T, w1h, nullptr,
                                                           nullptr, WffT, FF, FF, DD, 0);

    for (int layer = 0; layer < NLAYER; layer++) {
        gemm_tc<64><<<dim3(3 * DD / 128, LL / 64, 1), 128, SM64>>>(xhi, wqkvT, bqkv,
                                                                   nullptr, qkvh, DD, DD, 3 * DD, 0);
        flash_mma<<<dim3(16, HH), 64>>>(qkvh);
        gemm_tc<64><<<dim3(DD / 128, LL / 64, 2), 128, SM64>>>(ohi, woT, nullptr,
                                                               src2, nullptr, DD / 2, DD, DD, LL * DD);
        add_ln<<<BB * LL / 8, 256>>>(xhi, xlo, nullptr, src2, src2 + (size_t)LL * DD, bo,
                                     LL - 1, g1, be1);
        gemm_tc<128><<<dim3(DD / 128, (BB * LL) / 128, 1), 256, SM128>>>(xhi, WffT, bff,
                                                                         nullptr, tmph, DD, DD, DD, 0);
        add_ln<<<BB * LL / 8, 256>>>(xhi, xlo, tmph, nullptr, nullptr, nullptr,
                                     BB * LL - 1, g2, be2);
    }

    pool_mean<<<dim3(DD / 256, BB), 256>>>();
    logits_kernel<<<BB * CC, 256>>>(wf, bf, out);
}

// round 13
// speedup vs baseline: 6.3114x; 1.1347x over previous
#include <cuda_runtime.h>
#include <cuda_bf16.h>
#include <cuda_fp16.h>
#include <cstdint>

#define BB 16
#define LL 512
#define DD 1024
#define HH 16
#define FF 4096
#define CC 10
#define NLAYER 6

typedef __half f16;

__device__ f16 g_xhi[BB * LL * DD];
__device__ f16 g_xlo[BB * LL * DD];
__device__ f16 g_tmph[BB * LL * DD];
__device__ f16 g_qkvh[LL * 3 * DD];
__device__ f16 g_ohi[LL * DD];
__device__ f16 g_src2h[2 * LL * DD];
__device__ float g_bff[DD];
__device__ float g_bffpart[32 * DD];
__device__ float g_bqkv[3 * DD];
__device__ float g_pooled[BB * DD];
__device__ int g_ids64;
__device__ f16 g_wqkvT[3 * DD * DD];
__device__ f16 g_woT[DD * DD];
__device__ f16 g_WffT[DD * DD];
__device__ f16 g_w1h[DD * FF];
__device__ f16 g_w2T[DD * FF];

__device__ __forceinline__ void f2hl(float v, f16& h, f16& l) {
    h = __float2half(v);
    l = __float2half(v - __half2float(h));
}
__device__ __forceinline__ float warpSum(float v) {
    #pragma unroll
    for (int o = 16; o > 0; o >>= 1) v += __shfl_xor_sync(0xffffffffu, v, o);
    return v;
}
__device__ __forceinline__ float blockSum(float v) {
    __shared__ float sm[32];
    int lane = threadIdx.x & 31, w = threadIdx.x >> 5;
    v = warpSum(v);
    if (lane == 0) sm[w] = v;
    __syncthreads();
    if (w == 0) {
        float x = (lane < (int)(blockDim.x >> 5)) ? sm[lane] : 0.f;
        x = warpSum(x);
        if (lane == 0) sm[0] = x;
    }
    __syncthreads();
    float r = sm[0];
    __syncthreads();
    return r;
}

__device__ __forceinline__ uint32_t s2u(const void* p) {
    uint32_t a;
    asm("{ .reg .u64 t; cvta.to.shared.u64 t, %1; cvt.u32.u64 %0, t; }" : "=r"(a) : "l"(p));
    return a;
}
__device__ __forceinline__ void cpa(uint32_t dst, const void* src) {
    asm volatile("cp.async.cg.shared.global [%0], [%1], 16;" :: "r"(dst), "l"(src));
}
__device__ __forceinline__ void cpcommit() { asm volatile("cp.async.commit_group;"); }
template <int N> __device__ __forceinline__ void cpwait() {
    asm volatile("cp.async.wait_group %0;" :: "n"(N));
}
__device__ __forceinline__ void ldmx4(uint32_t* r, uint32_t a) {
    asm volatile("ldmatrix.sync.aligned.m8n8.x4.shared.b16 {%0,%1,%2,%3}, [%4];"
                 : "=r"(r[0]), "=r"(r[1]), "=r"(r[2]), "=r"(r[3]) : "r"(a));
}
__device__ __forceinline__ void mmah(float* d, const uint32_t* a, const uint32_t* b) {
    asm volatile(
        "mma.sync.aligned.m16n8k16.row.col.f32.f16.f16.f32 "
        "{%0,%1,%2,%3}, {%4,%5,%6,%7}, {%8,%9}, {%0,%1,%2,%3};"
        : "+f"(d[0]), "+f"(d[1]), "+f"(d[2]), "+f"(d[3])
        : "r"(a[0]), "r"(a[1]), "r"(a[2]), "r"(a[3]), "r"(b[0]), "r"(b[1]));
}

#define PITCH 80

// C[M,N] = A @ B^T + bias ; fp16 operands; multi-stage cp.async, 1 barrier/iter.
template <int MT>
__global__ __launch_bounds__(MT * 2, (MT == 64) ? 4 : 2) void gemm_tc(
    const f16* __restrict__ A, const f16* __restrict__ B,
    const float* __restrict__ bias, float* __restrict__ C, f16* __restrict__ Ch,
    int Kiter, int Kstride, int N, int Czoff) {
    constexpr int THREADS = MT * 2;
    constexpr int OFS_B = MT * PITCH;
    constexpr int STB = (MT + 128) * PITCH;
    constexpr int NST = (MT == 128) ? 5 : 3;
    extern __shared__ char smem[];
    uint32_t sb = s2u(smem);
    const int t = threadIdx.x, lane = t & 31, wid = t >> 5;
    const int m0 = blockIdx.y * MT, n0 = blockIdx.x * 128;
    const int wr = wid >> 2, wc = wid & 3;
    const size_t kz = (size_t)blockIdx.z * Kiter;
    if (C) C += (size_t)blockIdx.z * Czoff;
    if (Ch) Ch += (size_t)blockIdx.z * Czoff;
    const int NKB = Kiter / 32;

    float acc[4][4][4];
    #pragma unroll
    for (int i = 0; i < 4; i++)
        #pragma unroll
        for (int j = 0; j < 4; j++)
            #pragma unroll
            for (int r = 0; r < 4; r++) acc[i][j][r] = 0.f;

    const uint32_t aoff = (uint32_t)((wr * 64 + (lane & 15)) * PITCH + ((lane >> 4) << 4));
    const int brow = wc * 32 + (lane & 7) + ((lane & 16) ? 8 : 0);
    const uint32_t boff = (uint32_t)(brow * PITCH + ((lane & 8) ? 16 : 0));

    auto load_stage = [&](int kb0, uint32_t base) {
        #pragma unroll
        for (int idx = t; idx < MT * 4; idx += THREADS) {
            int row = idx >> 2, c = idx & 3;
            uint32_t so = (uint32_t)(row * PITCH + c * 16);
            cpa(base + so, A + (size_t)(m0 + row) * Kstride + kz + kb0 + c * 8);
        }
        #pragma unroll
        for (int idx = t; idx < 512; idx += THREADS) {
            int row = idx >> 2, c = idx & 3;
            uint32_t so = (uint32_t)(row * PITCH + c * 16);
            cpa(base + OFS_B + so, B + (size_t)(n0 + row) * Kstride + kz + kb0 + c * 8);
        }
        cpcommit();
    };

    #pragma unroll
    for (int s = 0; s < NST - 1; s++)
        load_stage(s * 32, sb + (uint32_t)s * STB);

    for (int kb = 0; kb < NKB; kb++) {
        cpwait<NST - 2>();
        __syncthreads();
        uint32_t base = sb + (uint32_t)(kb % NST) * STB;
        #pragma unroll
        for (int ks = 0; ks < 2; ks++) {
            uint32_t kbyte = (uint32_t)(ks * 32);
            uint32_t ah[4][4], bh[2][4];
            #pragma unroll
            for (int mt = 0; mt < 4; mt++)
                ldmx4(ah[mt], base + aoff + (uint32_t)(mt * 16 * PITCH) + kbyte);
            #pragma unroll
            for (int ng = 0; ng < 2; ng++)
                ldmx4(bh[ng], base + OFS_B + boff + (uint32_t)(ng * 16 * PITCH) + kbyte);
            #pragma unroll
            for (int mt = 0; mt < 4; mt++)
                #pragma unroll
                for (int nt = 0; nt < 4; nt++)
                    mmah(acc[mt][nt], ah[mt], &bh[nt >> 1][(nt & 1) * 2]);
        }
        int nxt = kb + NST - 1;
        if (nxt < NKB)
            load_stage(nxt * 32, sb + (uint32_t)(nxt % NST) * STB);
        else
            cpcommit();
    }

    #pragma unroll
    for (int mt = 0; mt < 4; mt++) {
        int m = m0 + wr * 64 + mt * 16 + (lane >> 2);
        #pragma unroll
        for (int nt = 0; nt < 4; nt++) {
            int n = n0 + wc * 32 + nt * 8 + (lane & 3) * 2;
            float b0 = 0.f, b1 = 0.f;
            if (bias) { b0 = bias[n]; b1 = bias[n + 1]; }
            float v0 = acc[mt][nt][0] + b0, v1 = acc[mt][nt][1] + b1;
            float v2 = acc[mt][nt][2] + b0, v3 = acc[mt][nt][3] + b1;
            if (Ch) {
                *(__half2*)(Ch + (size_t)m * N + n) = __floats2half2_rn(v0, v1);
                *(__half2*)(Ch + (size_t)(m + 8) * N + n) = __floats2half2_rn(v2, v3);
            } else {
                *(float2*)(C + (size_t)m * N + n) = make_float2(v0, v1);
                *(float2*)(C + (size_t)(m + 8) * N + n) = make_float2(v2, v3);
            }
        }
    }
}

__global__ void detect_kernel(const void* ids) {
    const int* p = (const int*)ids;
    int nz = 0;
    for (int i = 0; i < 256; i += 2)
        if (p[i + 1] != 0) nz++;
    g_ids64 = (nz == 0) ? 1 : 0;
}
__global__ void embed_kernel(const void* ids, const float* __restrict__ emb,
                             const float* __restrict__ pe) {
    int row = blockIdx.x;
    int d = threadIdx.x * 4;
    long long id;
    if (g_ids64) id = ((const long long*)ids)[row];
    else         id = (long long)((const int*)ids)[row];
    int l = row & (LL - 1);
    float4 e = *(const float4*)(emb + (size_t)id * DD + d);
    float4 p = *(const float4*)(pe + (size_t)l * DD + d);
    float v[4] = {e.x * 32.f + p.x, e.y * 32.f + p.y, e.z * 32.f + p.z, e.w * 32.f + p.w};
    size_t base = (size_t)row * DD + d;
    #pragma unroll
    for (int j = 0; j < 4; j++) {
        f16 h, lo;
        f2hl(v[j], h, lo);
        g_xhi[base + j] = h;
        g_xlo[base + j] = lo;
    }
}
__global__ void tconv4(const float* __restrict__ wq, const float* __restrict__ wk,
                       const float* __restrict__ wv, const float* __restrict__ wo) {
    __shared__ float tl[32][33];
    int z = blockIdx.z;
    const float* in = (z == 0) ? wq : (z == 1) ? wk : (z == 2) ? wv : wo;
    f16* oh = (z == 3) ? g_woT : g_wqkvT + (size_t)z * DD * DD;
    float scale = (z == 0) ? 0.125f : 1.f;
    int n0 = blockIdx.x * 32, k0 = blockIdx.y * 32;
    int tx = threadIdx.x, ty = threadIdx.y;
    #pragma unroll
    for (int i = 0; i < 4; i++)
        tl[ty + i * 8][tx] = in[(size_t)(k0 + ty + i * 8) * DD + n0 + tx] * scale;
    __syncthreads();
    #pragma unroll
    for (int i = 0; i < 4; i++) {
        int nn = ty + i * 8;
        oh[(size_t)(n0 + nn) * DD + k0 + tx] = __float2half(tl[tx][nn]);
    }
}
__global__ void tconv(const float* __restrict__ in, f16* __restrict__ oh,
                      int R, int C) {
    __shared__ float tl[32][33];
    int n0 = blockIdx.x * 32, k0 = blockIdx.y * 32;
    int tx = threadIdx.x, ty = threadIdx.y;
    #pragma unroll
    for (int i = 0; i < 4; i++)
        tl[ty + i * 8][tx] = in[(size_t)(k0 + ty + i * 8) * C + n0 + tx];
    __syncthreads();
    #pragma unroll
    for (int i = 0; i < 4; i++) {
        int nn = ty + i * 8;
        oh[(size_t)(n0 + nn) * R + k0 + tx] = __float2half(tl[tx][nn]);
    }
}
__global__ void conv_h(const float* __restrict__ in, f16* __restrict__ oh) {
    size_t i = ((size_t)blockIdx.x * 256 + threadIdx.x) * 4;
    float4 v = *(const float4*)(in + i);
    oh[i + 0] = __float2half(v.x);
    oh[i + 1] = __float2half(v.y);
    oh[i + 2] = __float2half(v.z);
    oh[i + 3] = __float2half(v.w);
}
__global__ void concat_bias(const float* __restrict__ bq, const float* __restrict__ bk,
                            const float* __restrict__ bv) {
    int t = threadIdx.x, s = blockIdx.x;
    const float* src = (s == 0) ? bq : (s == 1) ? bk : bv;
    g_bqkv[s * DD + t] = src[t] * ((s == 0) ? 0.125f : 1.f);
}
__global__ __launch_bounds__(256) void bff_part(const float* __restrict__ b1,
                                                const float* __restrict__ w2) {
    int y = blockIdx.x, t = threadIdx.x;
    float s[4] = {0.f, 0.f, 0.f, 0.f};
    for (int f = y * 128; f < y * 128 + 128; f++) {
        float bv = b1[f];
        const float* wr = w2 + (size_t)f * DD;
        #pragma unroll
        for (int j = 0; j < 4; j++) s[j] = fmaf(bv, wr[t + j * 256], s[j]);
    }
    #pragma unroll
    for (int j = 0; j < 4; j++) g_bffpart[y * DD + t + j * 256] = s[j];
}
__global__ __launch_bounds__(256) void bff_reduce(const float* __restrict__ b2) {
    int d = blockIdx.x * 256 + threadIdx.x;
    float s = b2[d];
    for (int y = 0; y < 32; y++) s += g_bffpart[y * DD + d];
    g_bff[d] = s;
}

// ---------------- HMMA flash attention, register-pipelined loads ----------------
__global__ __launch_bounds__(64) void flash_mma(const f16* __restrict__ qkv) {
    __shared__ __align__(16) char fsm[(32 + 64 + 64) * 144];
    const int OFQ = 0, OFK = 32 * 144, OFV = (32 + 64) * 144;
    uint32_t sb = s2u(fsm);
    int h = blockIdx.y, m0 = blockIdx.x * 32;
    int t = threadIdx.x, lane = t & 31, w = t >> 5;

    for (int i = t; i < 256; i += 64) {
        int r = i >> 3, c = i & 7;
        *(uint4*)(fsm + OFQ + r * 144 + c * 16) =
            *(const uint4*)(qkv + (size_t)(m0 + r) * (3 * DD) + h * 64 + c * 8);
    }
    __syncthreads();
    uint32_t qa[4][4];
    {
        uint32_t qoff = (uint32_t)((w * 16 + (lane & 15)) * 144 + ((lane >> 4) << 4));
        #pragma unroll
        for (int kt = 0; kt < 4; kt++) ldmx4(qa[kt], sb + OFQ + qoff + kt * 32);
    }

    const uint32_t brow = (uint32_t)((lane & 7) + ((lane & 16) ? 8 : 0));
    const uint32_t bcol = ((lane & 8) ? 16u : 0u);

    float m_run0 = -1e30f, m_run1 = -1e30f, l_run0 = 0.f, l_run1 = 0.f;
    float oacc[8][4];
    #pragma unroll
    for (int d = 0; d < 8; d++)
        #pragma unroll
        for (int r = 0; r < 4; r++) oacc[d][r] = 0.f;

    // register staging: per thread 8 uint4 of K, 16x2 half2 of V
    uint4 kreg[8];
    __half2 vreg[16][2];
    auto preload = [&](int kb) {
        #pragma unroll
        for (int i = 0; i < 8; i++) {
            int idx = t + i * 64;
            int r = idx >> 3, c = idx & 7;
            kreg[i] = *(const uint4*)(qkv + (size_t)(kb + r) * (3 * DD) + DD + h * 64 + c * 8);
        }
        #pragma unroll
        for (int i = 0; i < 16; i++) {
            int idx = t + i * 64;
            int key2 = (idx >> 5) * 2, d2 = idx & 31;
            const f16* vsrc = qkv + 2 * DD + h * 64 + 2 * d2;
            vreg[i][0] = *(const __half2*)(vsrc + (size_t)(kb + key2) * (3 * DD));
            vreg[i][1] = *(const __half2*)(vsrc + (size_t)(kb + key2 + 1) * (3 * DD));
        }
    };
    preload(0);

    for (int kb = 0; kb < LL; kb += 64) {
        __syncthreads();
        #pragma unroll
        for (int i = 0; i < 8; i++) {
            int idx = t + i * 64;
            int r = idx >> 3, c = idx & 7;
            *(uint4*)(fsm + OFK + r * 144 + c * 16) = kreg[i];
        }
        #pragma unroll
        for (int i = 0; i < 16; i++) {
            int idx = t + i * 64;
            int key2 = (idx >> 5) * 2, d2 = idx & 31;
            __half2 a = vreg[i][0], b = vreg[i][1];
            *(__half2*)(fsm + OFV + (2 * d2) * 144 + key2 * 2) = __halves2half2(a.x, b.x);
            *(__half2*)(fsm + OFV + (2 * d2 + 1) * 144 + key2 * 2) = __halves2half2(a.y, b.y);
        }
        __syncthreads();
        if (kb + 64 < LL) preload(kb + 64);   // latency hidden behind compute below

        float sacc[8][4];
        #pragma unroll
        for (int j = 0; j < 8; j++)
            #pragma unroll
            for (int r = 0; r < 4; r++) sacc[j][r] = 0.f;
        #pragma unroll
        for (int kt = 0; kt < 4; kt++) {
            #pragma unroll
            for (int ng = 0; ng < 4; ng++) {
                uint32_t kbf[4];
                ldmx4(kbf, sb + OFK + (uint32_t)(ng * 16) * 144 + brow * 144 + bcol + kt * 32);
                mmah(sacc[ng * 2 + 0], qa[kt], &kbf[0]);
                mmah(sacc[ng * 2 + 1], qa[kt], &kbf[2]);
            }
        }

        float ml0 = -1e30f, ml1 = -1e30f;
        #pragma unroll
        for (int j = 0; j < 8; j++) {
            ml0 = fmaxf(ml0, fmaxf(sacc[j][0], sacc[j][1]));
            ml1 = fmaxf(ml1, fmaxf(sacc[j][2], sacc[j][3]));
        }
        #pragma unroll
        for (int o = 1; o <= 2; o <<= 1) {
            ml0 = fmaxf(ml0, __shfl_xor_sync(0xffffffffu, ml0, o));
            ml1 = fmaxf(ml1, __shfl_xor_sync(0xffffffffu, ml1, o));
        }
        float mn0 = fmaxf(m_run0, ml0), mn1 = fmaxf(m_run1, ml1);
        float corr0 = __expf(m_run0 - mn0), corr1 = __expf(m_run1 - mn1);
        float rs0 = 0.f, rs1 = 0.f;
        uint32_t pfrag[4][4];
        #pragma unroll
        for (int kt = 0; kt < 4; kt++) {
            #pragma unroll
            for (int hh = 0; hh < 2; hh++) {
                int j = kt * 2 + hh;
                float p0 = __expf(sacc[j][0] - mn0), p1 = __expf(sacc[j][1] - mn0);
                float p2 = __expf(sacc[j][2] - mn1), p3 = __expf(sacc[j][3] - mn1);
                rs0 += p0 + p1;
                rs1 += p2 + p3;
                __half2 pa = __floats2half2_rn(p0, p1);
                __half2 pb = __floats2half2_rn(p2, p3);
                pfrag[kt][hh * 2 + 0] = *(uint32_t*)&pa;
                pfrag[kt][hh * 2 + 1] = *(uint32_t*)&pb;
            }
        }
        #pragma unroll
        for (int o = 1; o <= 2; o <<= 1) {
            rs0 += __shfl_xor_sync(0xffffffffu, rs0, o);
            rs1 += __shfl_xor_sync(0xffffffffu, rs1, o);
        }
        l_run0 = l_run0 * corr0 + rs0;
        l_run1 = l_run1 * corr1 + rs1;
        m_run0 = mn0;
        m_run1 = mn1;
        #pragma unroll
        for (int d = 0; d < 8; d++) {
            oacc[d][0] *= corr0; oacc[d][1] *= corr0;
            oacc[d][2] *= corr1; oacc[d][3] *= corr1;
        }
        #pragma unroll
        for (int kt = 0; kt < 4; kt++) {
            #pragma unroll
            for (int ng = 0; ng < 4; ng++) {
                uint32_t vb[4];
                ldmx4(vb, sb + OFV + (uint32_t)(ng * 16) * 144 + brow * 144 + bcol + kt * 32);
                mmah(oacc[ng * 2 + 0], pfrag[kt], &vb[0]);
                mmah(oacc[ng * 2 + 1], pfrag[kt], &vb[2]);
            }
        }
    }

    float inv0 = 1.f / l_run0, inv1 = 1.f / l_run1;
    int m = m0 + w * 16 + (lane >> 2);
    #pragma unroll
    for (int d = 0; d < 8; d++) {
        int n = h * 64 + d * 8 + 2 * (lane & 3);
        *(__half2*)(g_ohi + (size_t)m * DD + n) = __floats2half2_rn(oacc[d][0] * inv0, oacc[d][1] * inv0);
        *(__half2*)(g_ohi + (size_t)(m + 8) * DD + n) = __floats2half2_rn(oacc[d][2] * inv1, oacc[d][3] * inv1);
    }
}

// ---------------- warp-per-row residual + LayerNorm ----------------
__global__ __launch_bounds__(256) void add_ln(f16* __restrict__ xhi, f16* __restrict__ xlo,
                                              const f16* __restrict__ addh,
                                              const f16* __restrict__ addh2,
                                              const float* __restrict__ cbias, int addMask,
                                              const float* __restrict__ g,
                                              const float* __restrict__ b) {
    int row = blockIdx.x * 8 + (threadIdx.x >> 5);
    int lane = threadIdx.x & 31;
    size_t base = (size_t)row * DD;
    size_t abase = (size_t)(row & addMask) * DD;
    float v[32];
    #pragma unroll
    for (int c = 0; c < 4; c++) {
        int e0 = c * 256 + lane * 8;
        uint4 hv = *(const uint4*)(xhi + base + e0);
        uint4 lv = *(const uint4*)(xlo + base + e0);
        __half2* hp = (__half2*)&hv;
        __half2* lp = (__half2*)&lv;
        float a[8];
        uint4 av4 = *(const uint4*)(addh + abase + e0);
        __half2* ap = (__half2*)&av4;
        #pragma unroll
        for (int j = 0; j < 4; j++) {
            a[2 * j] = __half2float(ap[j].x);
            a[2 * j + 1] = __half2float(ap[j].y);
        }
        if (addh2) {
            uint4 a2 = *(const uint4*)(addh2 + abase + e0);
            __half2* a2p = (__half2*)&a2;
            #pragma unroll
            for (int j = 0; j < 4; j++) {
                a[2 * j] += __half2float(a2p[j].x);
                a[2 * j + 1] += __half2float(a2p[j].y);
            }
        }
        if (cbias) {
            float4 c0 = *(const float4*)(cbias + e0);
            float4 c1 = *(const float4*)(cbias + e0 + 4);
            a[0] += c0.x; a[1] += c0.y; a[2] += c0.z; a[3] += c0.w;
            a[4] += c1.x; a[5] += c1.y; a[6] += c1.z; a[7] += c1.w;
        }
        #pragma unroll
        for (int j = 0; j < 4; j++) {
            v[c * 8 + 2 * j]     = __half2float(hp[j].x) + __half2float(lp[j].x) + a[2 * j];
            v[c * 8 + 2 * j + 1] = __half2float(hp[j].y) + __half2float(lp[j].y) + a[2 * j + 1];
        }
    }
    float s = 0.f;
    #pragma unroll
    for (int i = 0; i < 32; i++) s += v[i];
    float mean = warpSum(s) * (1.f / DD);
    float q = 0.f;
    #pragma unroll
    for (int i = 0; i < 32; i++) {
        float d = v[i] - mean;
        q += d * d;
    }
    float rstd = rsqrtf(warpSum(q) * (1.f / DD) + 1e-5f);
    #pragma unroll
    for (int c = 0; c < 4; c++) {
        int e0 = c * 256 + lane * 8;
        float4 g0 = *(const float4*)(g + e0);
        float4 g1 = *(const float4*)(g + e0 + 4);
        float4 b0 = *(const float4*)(b + e0);
        float4 b1 = *(const float4*)(b + e0 + 4);
        float gg[8] = {g0.x, g0.y, g0.z, g0.w, g1.x, g1.y, g1.z, g1.w};
        float bb[8] = {b0.x, b0.y, b0.z, b0.w, b1.x, b1.y, b1.z, b1.w};
        uint4 ho, lo4;
        __half2* hop = (__half2*)&ho;
        __half2* lop = (__half2*)&lo4;
        #pragma unroll
        for (int j = 0; j < 4; j++) {
            float o0 = (v[c * 8 + 2 * j] - mean) * rstd * gg[2 * j] + bb[2 * j];
            float o1 = (v[c * 8 + 2 * j + 1] - mean) * rstd * gg[2 * j + 1] + bb[2 * j + 1];
            f16 h0, l0, h1, l1;
            f2hl(o0, h0, l0);
            f2hl(o1, h1, l1);
            hop[j] = __halves2half2(h0, h1);
            lop[j] = __halves2half2(l0, l1);
        }
        *(uint4*)(xhi + base + e0) = ho;
        *(uint4*)(xlo + base + e0) = lo4;
    }
}

__global__ __launch_bounds__(256) void pool_mean() {
    int b = blockIdx.y;
    int d = blockIdx.x * 256 + threadIdx.x;
    size_t base = (size_t)b * LL * DD + d;
    float s = 0.f;
    for (int l = 0; l < LL; l++)
        s += __half2float(g_xhi[base + (size_t)l * DD]) +
             __half2float(g_xlo[base + (size_t)l * DD]);
    g_pooled[b * DD + d] = s * (1.f / LL);
}
__global__ __launch_bounds__(256) void logits_kernel(const float* __restrict__ wf,
                                                     const float* __restrict__ bf,
                                                     float* __restrict__ out) {
    int b = blockIdx.x / CC, c = blockIdx.x % CC;
    float s = 0.f;
    for (int d = threadIdx.x; d < DD; d += 256)
        s += g_pooled[b * DD + d] * wf[(size_t)d * CC + c];
    s = blockSum(s);
    if (threadIdx.x == 0) out[b * CC + c] = s + bf[c];
}

extern "C" void kernel_launch(void* const* d_in, const int* in_sizes, int n_in,
                              void* d_out, int out_size) {
    const void*  ids = d_in[0];
    const float* emb = (const float*)d_in[1];
    const float* pe  = (const float*)d_in[2];
    const float* wq  = (const float*)d_in[3];
    const float* bq  = (const float*)d_in[4];
    const float* wk  = (const float*)d_in[5];
    const float* bk  = (const float*)d_in[6];
    const float* wv  = (const float*)d_in[7];
    const float* bv  = (const float*)d_in[8];
    const float* wo  = (const float*)d_in[9];
    const float* bo  = (const float*)d_in[10];
    const float* w1  = (const float*)d_in[11];
    const float* b1  = (const float*)d_in[12];
    const float* w2  = (const float*)d_in[13];
    const float* b2  = (const float*)d_in[14];
    const float* g1  = (const float*)d_in[15];
    const float* be1 = (const float*)d_in[16];
    const float* g2  = (const float*)d_in[17];
    const float* be2 = (const float*)d_in[18];
    const float* wf  = (const float*)d_in[19];
    const float* bf  = (const float*)d_in[20];
    float* out = (float*)d_out;

    const int SM128 = (128 + 128) * PITCH * 5;   // 5 stages
    const int SM64  = (64 + 128) * PITCH * 3;    // 3 stages
    cudaFuncSetAttribute(gemm_tc<128>, cudaFuncAttributeMaxDynamicSharedMemorySize, SM128);
    cudaFuncSetAttribute(gemm_tc<64>, cudaFuncAttributeMaxDynamicSharedMemorySize, SM64);

    float *bff, *bqkv;
    f16 *xhi, *xlo, *tmph, *qkvh, *ohi, *src2h, *wqkvT, *woT, *WffT, *w1h, *w2T;
    cudaGetSymbolAddress((void**)&bff, g_bff);
    cudaGetSymbolAddress((void**)&bqkv, g_bqkv);
    cudaGetSymbolAddress((void**)&xhi, g_xhi);
    cudaGetSymbolAddress((void**)&xlo, g_xlo);
    cudaGetSymbolAddress((void**)&tmph, g_tmph);
    cudaGetSymbolAddress((void**)&qkvh, g_qkvh);
    cudaGetSymbolAddress((void**)&ohi, g_ohi);
    cudaGetSymbolAddress((void**)&src2h, g_src2h);
    cudaGetSymbolAddress((void**)&wqkvT, g_wqkvT);
    cudaGetSymbolAddress((void**)&woT, g_woT);
    cudaGetSymbolAddress((void**)&WffT, g_WffT);
    cudaGetSymbolAddress((void**)&w1h, g_w1h);
    cudaGetSymbolAddress((void**)&w2T, g_w2T);

    detect_kernel<<<1, 1>>>(ids);
    embed_kernel<<<BB * LL, 256>>>(ids, emb, pe);

    dim3 tb(32, 8);
    tconv4<<<dim3(32, 32, 4), tb>>>(wq, wk, wv, wo);
    tconv<<<dim3(32, 128), tb>>>(w2, w2T, FF, DD);
    conv_h<<<(DD * FF) / 1024, 256>>>(w1, w1h);
    concat_bias<<<3, 1024>>>(bq, bk, bv);
    bff_part<<<32, 256>>>(b1, w2);
    bff_reduce<<<4, 256>>>(b2);
    gemm_tc<64><<<dim3(DD / 128, DD / 64, 1), 128, SM64>>>(w2T, w1h, nullptr,
                                                           nullptr, WffT, FF, FF, DD, 0);

    for (int layer = 0; layer < NLAYER; layer++) {
        gemm_tc<64><<<dim3(3 * DD / 128, LL / 64, 1), 128, SM64>>>(xhi, wqkvT, bqkv,
                                                                   nullptr, qkvh, DD, DD, 3 * DD, 0);
        flash_mma<<<dim3(16, HH), 64>>>(qkvh);
        gemm_tc<64><<<dim3(DD / 128, LL / 64, 2), 128, SM64>>>(ohi, woT, nullptr,
                                                               nullptr, src2h, DD / 2, DD, DD, LL * DD);
        add_ln<<<BB * LL / 8, 256>>>(xhi, xlo, src2h, src2h + (size_t)LL * DD, bo,
                                     LL - 1, g1, be1);
        gemm_tc<128><<<dim3(DD / 128, (BB * LL) / 128, 1), 256, SM128>>>(xhi, WffT, bff,
                                                                         nullptr, tmph, DD, DD, DD, 0);
        add_ln<<<BB * LL / 8, 256>>>(xhi, xlo, tmph, nullptr, nullptr,
                                     BB * LL - 1, g2, be2);
    }

    pool_mean<<<dim3(DD / 256, BB), 256>>>();
    logits_kernel<<<BB * CC, 256>>>(wf, bf, out);
}